// round 3
// baseline (speedup 1.0000x reference)
#include <cuda_runtime.h>
#include <math.h>

#define BATCH 8
#define CIN 256
#define HH 100
#define WW 152
#define HW 15200
#define NC 81
#define NKEEP 100
#define NOUT1 (BATCH*CIN*NKEEP)   /* 204800 */

typedef unsigned long long ull;

// Scratch (device globals: allocation-free per harness rules)
__device__ float g_hid[(size_t)BATCH*CIN*HW];     // conv1 output (relu'd)
__device__ float g_w1t[CIN*9*CIN];                // w1 transposed to [ci][k][co]
__device__ int   g_cls[BATCH*HW];
__device__ float g_pv[BATCH*HW];
__device__ ull   g_keys[BATCH*HW];
__device__ int   g_topk[BATCH*NKEEP];

// Packed f32x2 helpers (SASS FFMA2 — 2x fp32 FMA throughput, exact IEEE fp32)
#define FMA2(d,a,b,c) asm("fma.rn.f32x2 %0, %1, %2, %3;" : "=l"(d) : "l"(a), "l"(b), "l"(c))
#define PACK2(d,lo,hi) asm("mov.b64 %0, {%1, %2};" : "=l"(d) : "f"(lo), "f"(hi))
#define UNPACK2(lo,hi,s) asm("mov.b64 {%0, %1}, %2;" : "=f"(lo), "=f"(hi) : "l"(s))

// ---------------------------------------------------------------------------
// w1 (co,ci,kh,kw) -> g_w1t[ci][k][co] for coalesced smem staging in conv3x3
// ---------------------------------------------------------------------------
__global__ void k_transpose_w1(const float* __restrict__ w1){
  int i = blockIdx.x*256 + threadIdx.x;
  if (i < CIN*CIN*9){
    int k = i % 9; int ci = (i/9) % CIN; int co = i/(9*CIN);
    g_w1t[ci*9*CIN + k*CIN + co] = w1[i];
  }
}

// ---------------------------------------------------------------------------
// 3x3 SAME conv, 256->256, + bias + relu, packed f32x2 FMA.
// Block tile: 16 rows x 16 cols x 64 co, ci chunks of 4.
// Thread: 4 co x 8 cols x 2 rows (row pair = f32x2 lanes).
// Lane map: og=tid&15 (co), rg/cg from high bits -> inner data LDS.64 is a
// 16-way broadcast of 2 addresses per warp (conflict-free). Weights are
// stored pre-duplicated (w,w) in smem: no per-FMA packing.
// ---------------------------------------------------------------------------
__global__ __launch_bounds__(256,2) void k_conv3x3(const float* __restrict__ x,
                                                   const float* __restrict__ b1){
  __shared__ ull s_v[4][17][19];   // [ci][pair-row p=(y0-1+p, y0+p)][col]
  __shared__ ull s_wd[4][9][64];   // [ci][k][co], each entry = (w,w)
  int tid = threadIdx.x;
  int x0 = blockIdx.x*16, y0 = blockIdx.y*16;
  int bz = blockIdx.z;
  int b   = bz >> 2;
  int co0 = (bz & 3) * 64;
  int og = tid & 15;          // co group (4 co each)
  int rg = (tid >> 4) & 7;    // row group: rows rg*2, rg*2+1
  int cg = tid >> 7;          // col group: cols cg*8 .. cg*8+7
  int co = co0 + og*4;
  int c0 = cg*8;

  ull acc[4][8];
  #pragma unroll
  for (int i=0;i<4;i++){
    float bv = b1[co+i];
    ull bp; PACK2(bp, bv, bv);
    #pragma unroll
    for (int j=0;j<8;j++) acc[i][j] = bp;
  }

  const float* xb = x + (size_t)b*CIN*HW;

  for (int ci0=0; ci0<CIN; ci0+=4){
    __syncthreads();
    // stage input 4ci x 18x18 halo into vertical-pair layout
    #pragma unroll 1
    for (int i=tid; i<4*18*18; i+=256){
      int xx = i % 18; int t = i/18; int yy = t % 18; int ci = t/18;
      int gx = x0 - 1 + xx, gy = y0 - 1 + yy;
      float v = 0.f;
      if ((unsigned)gx < WW && (unsigned)gy < HH)
        v = xb[(size_t)(ci0+ci)*HW + gy*WW + gx];
      if (yy <= 16) ((float*)&s_v[ci][yy][xx])[0]   = v;  // lo of pair yy
      if (yy >= 1)  ((float*)&s_v[ci][yy-1][xx])[1] = v;  // hi of pair yy-1
    }
    // stage weights 4ci x 9 x 64co, duplicated (co fastest in g_w1t: coalesced)
    #pragma unroll 1
    for (int i=tid; i<4*9*64; i+=256){
      int lco = i & 63; int t = i >> 6; int k = t % 9; int ci = t/9;
      float w = g_w1t[(ci0+ci)*9*CIN + k*CIN + co0 + lco];
      ull d; PACK2(d, w, w);
      s_wd[ci][k][lco] = d;
    }
    __syncthreads();

    #pragma unroll
    for (int ci=0; ci<4; ci++){
      #pragma unroll
      for (int ky=0; ky<3; ky++){
        int p = rg*2 + ky;
        ull v[10];
        #pragma unroll
        for (int u=0;u<10;u++) v[u] = s_v[ci][p][c0+u];
        #pragma unroll
        for (int kx=0;kx<3;kx++){
          const ulonglong2* wp = (const ulonglong2*)&s_wd[ci][ky*3+kx][og*4];
          ulonglong2 wa = wp[0], wb = wp[1];
          #pragma unroll
          for (int j=0;j<8;j++){
            FMA2(acc[0][j], v[kx+j], wa.x, acc[0][j]);
            FMA2(acc[1][j], v[kx+j], wa.y, acc[1][j]);
            FMA2(acc[2][j], v[kx+j], wb.x, acc[2][j]);
            FMA2(acc[3][j], v[kx+j], wb.y, acc[3][j]);
          }
        }
      }
    }
  }

  // epilogue: unpack, relu, store two rows of 8 per co
  int gy = y0 + rg*2;
  int gx = x0 + c0;
  if (gx + 7 < WW){
    #pragma unroll
    for (int i=0;i<4;i++){
      float lo[8], hi[8];
      #pragma unroll
      for (int j=0;j<8;j++){
        UNPACK2(lo[j], hi[j], acc[i][j]);
        lo[j] = fmaxf(lo[j], 0.f); hi[j] = fmaxf(hi[j], 0.f);
      }
      float* base = g_hid + ((size_t)b*CIN + (co+i))*HW;
      if (gy < HH){
        float* hp = base + (size_t)gy*WW + gx;
        *(float4*)hp     = make_float4(lo[0],lo[1],lo[2],lo[3]);
        *(float4*)(hp+4) = make_float4(lo[4],lo[5],lo[6],lo[7]);
      }
      if (gy+1 < HH){
        float* hp = base + (size_t)(gy+1)*WW + gx;
        *(float4*)hp     = make_float4(hi[0],hi[1],hi[2],hi[3]);
        *(float4*)(hp+4) = make_float4(hi[4],hi[5],hi[6],hi[7]);
      }
    }
  }
}

// ---------------------------------------------------------------------------
// 1x1 conv 256->81 + bias, f32x2 (co pairs). One px per thread, co in 3
// chunks of 27 (28 padded -> 14 pairs). Weight pairs pre-packed in smem,
// broadcast LDS.64 in the inner loop.
// ---------------------------------------------------------------------------
__global__ __launch_bounds__(256) void k_conv1x1(const float* __restrict__ w2,
                                                 const float* __restrict__ b2,
                                                 float* __restrict__ logits){
  __shared__ ull s_w[256*14];    // [ci][pair j] = (w[2j], w[2j+1]), 28KB
  int tid = threadIdx.x;
  int b  = blockIdx.y;
  int px = blockIdx.x*256 + tid;
  const float* hb = g_hid + (size_t)b*CIN*HW;
  float* ob = logits + (size_t)b*NC*HW;

  for (int cc=0; cc<3; cc++){
    __syncthreads();
    for (int i=tid; i<256*14; i+=256){
      int j = i % 14; int ci = i/14;
      float wa = (2*j   < 27) ? w2[(cc*27+2*j  )*CIN + ci] : 0.f;
      float wb = (2*j+1 < 27) ? w2[(cc*27+2*j+1)*CIN + ci] : 0.f;
      ull d; PACK2(d, wa, wb);
      s_w[i] = d;
    }
    __syncthreads();
    if (px < HW){
      ull acc[14];
      #pragma unroll
      for (int j=0;j<14;j++){
        float ba = (2*j   < 27) ? b2[cc*27+2*j  ] : 0.f;
        float bb = (2*j+1 < 27) ? b2[cc*27+2*j+1] : 0.f;
        PACK2(acc[j], ba, bb);
      }
      #pragma unroll 4
      for (int ci=0; ci<CIN; ci++){
        float v = hb[(size_t)ci*HW + px];
        ull vd; PACK2(vd, v, v);
        const ull* wp = s_w + ci*14;
        #pragma unroll
        for (int j=0;j<14;j++) FMA2(acc[j], vd, wp[j], acc[j]);
      }
      #pragma unroll
      for (int j=0;j<14;j++){
        float a, c; UNPACK2(a, c, acc[j]);
        if (2*j   < 27) ob[(size_t)(cc*27+2*j  )*HW + px] = a;
        if (2*j+1 < 27) ob[(size_t)(cc*27+2*j+1)*HW + px] = c;
      }
    }
  }
}

// ---------------------------------------------------------------------------
// Per-pixel: softmax over 81 channels, argmax over first 80 (first-max wins),
// p = prob at argmax channel. (After masking only that channel is nonzero.)
// ---------------------------------------------------------------------------
__global__ void k_softmax(const float* __restrict__ logits){
  int i = blockIdx.x*256 + threadIdx.x;
  if (i >= BATCH*HW) return;
  int b = i / HW, px = i - b*HW;
  const float* lp = logits + (size_t)b*NC*HW + px;
  float M = -1e30f, best = -1e30f; int bi = 0;
  #pragma unroll 1
  for (int c=0;c<NC;c++){
    float v = lp[(size_t)c*HW];
    if (c < 80 && v > best){ best = v; bi = c; }
    M = fmaxf(M, v);
  }
  float s = 0.f;
  #pragma unroll 1
  for (int c=0;c<NC;c++) s += expf(lp[(size_t)c*HW] - M);
  g_pv[i] = expf(best - M) / s;
  g_cls[i] = bi;
}

// ---------------------------------------------------------------------------
// score = p + 1 if (p>=eps and no in-bounds 8-neighbor with same class and
// strictly larger p). Emits sortable key: (score_bits<<32) | (~px) so ties
// prefer the smaller index (lax.top_k semantics). score >= 0 always.
// ---------------------------------------------------------------------------
__global__ void k_score(){
  int i = blockIdx.x*256 + threadIdx.x;
  if (i >= BATCH*HW) return;
  int b = i / HW, px = i - b*HW;
  int y = px / WW, xx = px - y*WW;
  float p = g_pv[i]; int cls = g_cls[i];
  bool flag = (p >= 1e-6f);
  if (flag){
    #pragma unroll
    for (int dy=-1; dy<=1; dy++){
      #pragma unroll
      for (int dx=-1; dx<=1; dx++){
        if (dy==0 && dx==0) continue;
        int ny = y+dy, nx = xx+dx;
        if ((unsigned)ny < HH && (unsigned)nx < WW){
          int j = b*HW + ny*WW + nx;
          if (g_cls[j]==cls && g_pv[j] > p) flag = false;
        }
      }
    }
  }
  float score = p + (flag ? 1.f : 0.f);
  g_keys[i] = (((ull)__float_as_uint(score))<<32)
              | (ull)(0xFFFFFFFFu - (unsigned)px);
}

// ---------------------------------------------------------------------------
// Top-100 per batch: 100 iterations of block-wide argmax over 15200 keys
// (L2-resident), zero the winner each round. Exact lax.top_k ordering.
// ---------------------------------------------------------------------------
__global__ void k_topk(){
  __shared__ ull s_red[256];
  int b = blockIdx.x, tid = threadIdx.x;
  ull* kb = g_keys + (size_t)b*HW;
  for (int it=0; it<NKEEP; it++){
    ull best = 0ull;
    for (int i=tid; i<HW; i+=256){
      ull k = kb[i];
      if (k > best) best = k;
    }
    s_red[tid] = best;
    __syncthreads();
    #pragma unroll
    for (int s=128; s>0; s>>=1){
      if (tid < s && s_red[tid+s] > s_red[tid]) s_red[tid] = s_red[tid+s];
      __syncthreads();
    }
    ull win = s_red[0];
    int wpx = (int)(0xFFFFFFFFu - (unsigned)(win & 0xFFFFFFFFull));
    if (tid==0){
      g_topk[b*NKEEP+it] = wpx;
      kb[wpx] = 0ull;      // exclude winner; __syncthreads gives block visibility
    }
    __syncthreads();
  }
}

// ---------------------------------------------------------------------------
// Gather x and pos at top-k indices. out layout: [proposals | pos | logits]
// ---------------------------------------------------------------------------
__global__ void k_gather(const float* __restrict__ x, const float* __restrict__ pos,
                         float* __restrict__ out){
  int i = blockIdx.x*256 + threadIdx.x;
  if (i >= NOUT1) return;
  int k = i % NKEEP; int t = i / NKEEP; int c = t % CIN; int b = t / CIN;
  int px = g_topk[b*NKEEP + k];
  out[i]         = x[((size_t)b*CIN + c)*HW + px];
  out[NOUT1 + i] = pos[(size_t)c*HW + px];
}

// ---------------------------------------------------------------------------
extern "C" void kernel_launch(void* const* d_in, const int* in_sizes, int n_in,
                              void* d_out, int out_size){
  (void)in_sizes; (void)n_in; (void)out_size;
  const float* x   = (const float*)d_in[0];
  const float* pos = (const float*)d_in[1];
  const float* w1  = (const float*)d_in[2];
  const float* b1  = (const float*)d_in[3];
  const float* w2  = (const float*)d_in[4];
  const float* b2  = (const float*)d_in[5];
  float* out = (float*)d_out;
  float* logits = out + 2*NOUT1;

  k_transpose_w1<<<(CIN*CIN*9+255)/256, 256>>>(w1);
  k_conv3x3<<<dim3(10,7,BATCH*4), 256>>>(x, b1);
  k_conv1x1<<<dim3((HW+255)/256, BATCH), 256>>>(w2, b2, logits);
  k_softmax<<<(BATCH*HW+255)/256, 256>>>(logits);
  k_score<<<(BATCH*HW+255)/256, 256>>>();
  k_topk<<<BATCH, 256>>>();
  k_gather<<<(NOUT1+255)/256, 256>>>(x, pos, out);
}

// round 4
// speedup vs baseline: 1.2419x; 1.2419x over previous
#include <cuda_runtime.h>
#include <math.h>

#define BATCH 8
#define CIN 256
#define HH 100
#define WW 152
#define HW 15200
#define NC 81
#define NKEEP 100
#define NOUT1 (BATCH*CIN*NKEEP)   /* 204800 */

typedef unsigned long long ull;

// Scratch (device globals: allocation-free per harness rules)
__device__ float g_hid[(size_t)BATCH*CIN*HW];     // conv1 output (relu'd)
__device__ float g_w1t[CIN*9*CIN];                // w1 transposed to [ci][k][co]
__device__ int   g_cls[BATCH*HW];
__device__ float g_pv[BATCH*HW];
__device__ ull   g_keys[BATCH*HW];
__device__ int   g_topk[BATCH*NKEEP];

// Packed f32x2 helpers (SASS FFMA2 — exact IEEE fp32, rt limited by RF banks)
#define FMA2(d,a,b,c) asm("fma.rn.f32x2 %0, %1, %2, %3;" : "=l"(d) : "l"(a), "l"(b), "l"(c))
#define PACK2(d,lo,hi) asm("mov.b64 %0, {%1, %2};" : "=l"(d) : "f"(lo), "f"(hi))
#define UNPACK2(lo,hi,s) asm("mov.b64 {%0, %1}, %2;" : "=f"(lo), "=f"(hi) : "l"(s))

// ---------------------------------------------------------------------------
// w1 (co,ci,kh,kw) -> g_w1t[ci][k][co] for coalesced smem staging in conv3x3
// ---------------------------------------------------------------------------
__global__ void k_transpose_w1(const float* __restrict__ w1){
  int i = blockIdx.x*256 + threadIdx.x;
  if (i < CIN*CIN*9){
    int k = i % 9; int ci = (i/9) % CIN; int co = i/(9*CIN);
    g_w1t[ci*9*CIN + k*CIN + co] = w1[i];
  }
}

// ---------------------------------------------------------------------------
// 3x3 SAME conv, 256->256, + bias + relu, packed f32x2 FMA.
// Block tile: 16 rows x 16 cols x 64 co. ci chunks of 4, DOUBLE-BUFFERED:
// chunk c+1 is prefetched into registers while computing chunk c; one
// __syncthreads per chunk. Thread computes 4 co x 8 cols x 2 rows (row pair
// = f32x2 lanes). Lane map puts co-group in low tid bits so inner data
// LDS.64 is a 16-way broadcast (conflict-free).
// ---------------------------------------------------------------------------
__global__ __launch_bounds__(256,2) void k_conv3x3(const float* __restrict__ x,
                                                   const float* __restrict__ b1,
                                                   int b){
  __shared__ ull   s_v[2][4][17][19];   // [buf][ci][pair-row][col]
  __shared__ float s_w[2][4][9][64];    // [buf][ci][k][co]
  int tid = threadIdx.x;
  int x0 = blockIdx.x*16, y0 = blockIdx.y*16;
  int co0 = blockIdx.z * 64;
  int og = tid & 15;          // co group (4 co each)
  int rg = (tid >> 4) & 7;    // row group: rows rg*2, rg*2+1
  int cg = tid >> 7;          // col group: cols cg*8 .. cg*8+7
  int co = co0 + og*4;
  int c0 = cg*8;

  ull acc[4][8];
  #pragma unroll
  for (int i=0;i<4;i++){
    float bv = b1[co+i];
    ull bp; PACK2(bp, bv, bv);
    #pragma unroll
    for (int j=0;j<8;j++) acc[i][j] = bp;
  }

  const float* xb = x + (size_t)b*CIN*HW;

  // precomputed indices for this thread's staging slots
  // input: i = tid + t*256, t<6 (1296 total); weights: i = tid + t*256, t<9 (2304)
  float rin[6], rw[9];

  // ---- prefetch chunk 0 ----
  #pragma unroll
  for (int t=0;t<6;t++){
    int i = tid + t*256; rin[t]=0.f;
    if (i < 4*18*18){
      int xx=i%18; int q=i/18; int yy=q%18; int ci=q/18;
      int gx=x0-1+xx, gy=y0-1+yy;
      if ((unsigned)gx < WW && (unsigned)gy < HH)
        rin[t] = xb[(size_t)ci*HW + gy*WW + gx];
    }
  }
  #pragma unroll
  for (int t=0;t<9;t++){
    int i = tid + t*256;
    int lco=i&63; int q=i>>6; int k=q%9; int ci=q/9;
    rw[t] = g_w1t[(size_t)ci*9*CIN + k*CIN + co0 + lco];
  }
  // store chunk 0 into buf 0
  #pragma unroll
  for (int t=0;t<6;t++){
    int i = tid + t*256;
    if (i < 4*18*18){
      int xx=i%18; int q=i/18; int yy=q%18; int ci=q/18;
      if (yy <= 16) ((float*)&s_v[0][ci][yy][xx])[0]   = rin[t];
      if (yy >= 1)  ((float*)&s_v[0][ci][yy-1][xx])[1] = rin[t];
    }
  }
  #pragma unroll
  for (int t=0;t<9;t++){
    int i = tid + t*256;
    int lco=i&63; int q=i>>6; int k=q%9; int ci=q/9;
    s_w[0][ci][k][lco] = rw[t];
  }
  __syncthreads();

  #pragma unroll 1
  for (int c=0; c<64; c++){
    int buf = c & 1;
    // ---- issue prefetch LDGs for chunk c+1 ----
    int ci0n = (c+1)*4;
    if (c+1 < 64){
      #pragma unroll
      for (int t=0;t<6;t++){
        int i = tid + t*256; rin[t]=0.f;
        if (i < 4*18*18){
          int xx=i%18; int q=i/18; int yy=q%18; int ci=q/18;
          int gx=x0-1+xx, gy=y0-1+yy;
          if ((unsigned)gx < WW && (unsigned)gy < HH)
            rin[t] = xb[(size_t)(ci0n+ci)*HW + gy*WW + gx];
        }
      }
      #pragma unroll
      for (int t=0;t<9;t++){
        int i = tid + t*256;
        int lco=i&63; int q=i>>6; int k=q%9; int ci=q/9;
        rw[t] = g_w1t[(size_t)(ci0n+ci)*9*CIN + k*CIN + co0 + lco];
      }
    }

    // ---- compute chunk c from buf ----
    #pragma unroll 2
    for (int ci=0; ci<4; ci++){
      #pragma unroll
      for (int ky=0; ky<3; ky++){
        int p = rg*2 + ky;
        ull v[10];
        #pragma unroll
        for (int u=0;u<10;u++) v[u] = s_v[buf][ci][p][c0+u];
        #pragma unroll
        for (int kx=0;kx<3;kx++){
          float4 w4 = *(const float4*)&s_w[buf][ci][ky*3+kx][og*4];
          ull wd0, wd1, wd2, wd3;
          PACK2(wd0, w4.x, w4.x); PACK2(wd1, w4.y, w4.y);
          PACK2(wd2, w4.z, w4.z); PACK2(wd3, w4.w, w4.w);
          #pragma unroll
          for (int j=0;j<8;j++){
            FMA2(acc[0][j], v[kx+j], wd0, acc[0][j]);
            FMA2(acc[1][j], v[kx+j], wd1, acc[1][j]);
            FMA2(acc[2][j], v[kx+j], wd2, acc[2][j]);
            FMA2(acc[3][j], v[kx+j], wd3, acc[3][j]);
          }
        }
      }
    }

    // ---- store prefetched chunk into other buffer ----
    if (c+1 < 64){
      int nb = buf ^ 1;
      #pragma unroll
      for (int t=0;t<6;t++){
        int i = tid + t*256;
        if (i < 4*18*18){
          int xx=i%18; int q=i/18; int yy=q%18; int ci=q/18;
          if (yy <= 16) ((float*)&s_v[nb][ci][yy][xx])[0]   = rin[t];
          if (yy >= 1)  ((float*)&s_v[nb][ci][yy-1][xx])[1] = rin[t];
        }
      }
      #pragma unroll
      for (int t=0;t<9;t++){
        int i = tid + t*256;
        int lco=i&63; int q=i>>6; int k=q%9; int ci=q/9;
        s_w[nb][ci][k][lco] = rw[t];
      }
    }
    __syncthreads();
  }

  // epilogue: unpack, relu, store two rows of 8 per co
  int gy = y0 + rg*2;
  int gx = x0 + c0;
  if (gx + 7 < WW){
    #pragma unroll
    for (int i=0;i<4;i++){
      float lo[8], hi[8];
      #pragma unroll
      for (int j=0;j<8;j++){
        UNPACK2(lo[j], hi[j], acc[i][j]);
        lo[j] = fmaxf(lo[j], 0.f); hi[j] = fmaxf(hi[j], 0.f);
      }
      float* base = g_hid + ((size_t)b*CIN + (co+i))*HW;
      if (gy < HH){
        float* hp = base + (size_t)gy*WW + gx;
        *(float4*)hp     = make_float4(lo[0],lo[1],lo[2],lo[3]);
        *(float4*)(hp+4) = make_float4(lo[4],lo[5],lo[6],lo[7]);
      }
      if (gy+1 < HH){
        float* hp = base + (size_t)(gy+1)*WW + gx;
        *(float4*)hp     = make_float4(hi[0],hi[1],hi[2],hi[3]);
        *(float4*)(hp+4) = make_float4(hi[4],hi[5],hi[6],hi[7]);
      }
    }
  }
}

// ---------------------------------------------------------------------------
// 1x1 conv 256->81 + bias, f32x2 (co pairs). One px per thread, co in 3
// chunks of 27 (28 padded -> 14 pairs). Weight pairs pre-packed in smem,
// broadcast LDS.64 in the inner loop.
// ---------------------------------------------------------------------------
__global__ __launch_bounds__(256) void k_conv1x1(const float* __restrict__ w2,
                                                 const float* __restrict__ b2,
                                                 float* __restrict__ logits){
  __shared__ ull s_w[256*14];    // [ci][pair j] = (w[2j], w[2j+1]), 28KB
  int tid = threadIdx.x;
  int b  = blockIdx.y;
  int px = blockIdx.x*256 + tid;
  const float* hb = g_hid + (size_t)b*CIN*HW;
  float* ob = logits + (size_t)b*NC*HW;

  for (int cc=0; cc<3; cc++){
    __syncthreads();
    for (int i=tid; i<256*14; i+=256){
      int j = i % 14; int ci = i/14;
      float wa = (2*j   < 27) ? w2[(cc*27+2*j  )*CIN + ci] : 0.f;
      float wb = (2*j+1 < 27) ? w2[(cc*27+2*j+1)*CIN + ci] : 0.f;
      ull d; PACK2(d, wa, wb);
      s_w[i] = d;
    }
    __syncthreads();
    if (px < HW){
      ull acc[14];
      #pragma unroll
      for (int j=0;j<14;j++){
        float ba = (2*j   < 27) ? b2[cc*27+2*j  ] : 0.f;
        float bb = (2*j+1 < 27) ? b2[cc*27+2*j+1] : 0.f;
        PACK2(acc[j], ba, bb);
      }
      #pragma unroll 4
      for (int ci=0; ci<CIN; ci++){
        float v = hb[(size_t)ci*HW + px];
        ull vd; PACK2(vd, v, v);
        const ull* wp = s_w + ci*14;
        #pragma unroll
        for (int j=0;j<14;j++) FMA2(acc[j], vd, wp[j], acc[j]);
      }
      #pragma unroll
      for (int j=0;j<14;j++){
        float a, c; UNPACK2(a, c, acc[j]);
        if (2*j   < 27) ob[(size_t)(cc*27+2*j  )*HW + px] = a;
        if (2*j+1 < 27) ob[(size_t)(cc*27+2*j+1)*HW + px] = c;
      }
    }
  }
}

// ---------------------------------------------------------------------------
// Per-pixel: softmax over 81 channels, argmax over first 80 (first-max wins),
// p = prob at argmax channel. (After masking only that channel is nonzero.)
// ---------------------------------------------------------------------------
__global__ void k_softmax(const float* __restrict__ logits){
  int i = blockIdx.x*256 + threadIdx.x;
  if (i >= BATCH*HW) return;
  int b = i / HW, px = i - b*HW;
  const float* lp = logits + (size_t)b*NC*HW + px;
  float M = -1e30f, best = -1e30f; int bi = 0;
  #pragma unroll 1
  for (int c=0;c<NC;c++){
    float v = lp[(size_t)c*HW];
    if (c < 80 && v > best){ best = v; bi = c; }
    M = fmaxf(M, v);
  }
  float s = 0.f;
  #pragma unroll 1
  for (int c=0;c<NC;c++) s += expf(lp[(size_t)c*HW] - M);
  g_pv[i] = expf(best - M) / s;
  g_cls[i] = bi;
}

// ---------------------------------------------------------------------------
// score = p + 1 if (p>=eps and no in-bounds 8-neighbor with same class and
// strictly larger p). Emits sortable key: (score_bits<<32) | (~px) so ties
// prefer the smaller index (lax.top_k semantics). score >= 0 always.
// ---------------------------------------------------------------------------
__global__ void k_score(){
  int i = blockIdx.x*256 + threadIdx.x;
  if (i >= BATCH*HW) return;
  int b = i / HW, px = i - b*HW;
  int y = px / WW, xx = px - y*WW;
  float p = g_pv[i]; int cls = g_cls[i];
  bool flag = (p >= 1e-6f);
  if (flag){
    #pragma unroll
    for (int dy=-1; dy<=1; dy++){
      #pragma unroll
      for (int dx=-1; dx<=1; dx++){
        if (dy==0 && dx==0) continue;
        int ny = y+dy, nx = xx+dx;
        if ((unsigned)ny < HH && (unsigned)nx < WW){
          int j = b*HW + ny*WW + nx;
          if (g_cls[j]==cls && g_pv[j] > p) flag = false;
        }
      }
    }
  }
  float score = p + (flag ? 1.f : 0.f);
  g_keys[i] = (((ull)__float_as_uint(score))<<32)
              | (ull)(0xFFFFFFFFu - (unsigned)px);
}

// ---------------------------------------------------------------------------
// Top-100 per batch: 100 iterations of block-wide argmax over 15200 keys
// (L2-resident), zero the winner each round. Exact lax.top_k ordering.
// ---------------------------------------------------------------------------
__global__ void k_topk(){
  __shared__ ull s_red[256];
  int b = blockIdx.x, tid = threadIdx.x;
  ull* kb = g_keys + (size_t)b*HW;
  for (int it=0; it<NKEEP; it++){
    ull best = 0ull;
    for (int i=tid; i<HW; i+=256){
      ull k = kb[i];
      if (k > best) best = k;
    }
    s_red[tid] = best;
    __syncthreads();
    #pragma unroll
    for (int s=128; s>0; s>>=1){
      if (tid < s && s_red[tid+s] > s_red[tid]) s_red[tid] = s_red[tid+s];
      __syncthreads();
    }
    ull win = s_red[0];
    int wpx = (int)(0xFFFFFFFFu - (unsigned)(win & 0xFFFFFFFFull));
    if (tid==0){
      g_topk[b*NKEEP+it] = wpx;
      kb[wpx] = 0ull;      // exclude winner; __syncthreads gives block visibility
    }
    __syncthreads();
  }
}

// ---------------------------------------------------------------------------
// Gather x and pos at top-k indices. out layout: [proposals | pos | logits]
// ---------------------------------------------------------------------------
__global__ void k_gather(const float* __restrict__ x, const float* __restrict__ pos,
                         float* __restrict__ out){
  int i = blockIdx.x*256 + threadIdx.x;
  if (i >= NOUT1) return;
  int k = i % NKEEP; int t = i / NKEEP; int c = t % CIN; int b = t / CIN;
  int px = g_topk[b*NKEEP + k];
  out[i]         = x[((size_t)b*CIN + c)*HW + px];
  out[NOUT1 + i] = pos[(size_t)c*HW + px];
}

// ---------------------------------------------------------------------------
extern "C" void kernel_launch(void* const* d_in, const int* in_sizes, int n_in,
                              void* d_out, int out_size){
  (void)in_sizes; (void)n_in; (void)out_size;
  const float* x   = (const float*)d_in[0];
  const float* pos = (const float*)d_in[1];
  const float* w1  = (const float*)d_in[2];
  const float* b1  = (const float*)d_in[3];
  const float* w2  = (const float*)d_in[4];
  const float* b2  = (const float*)d_in[5];
  float* out = (float*)d_out;
  float* logits = out + 2*NOUT1;

  k_transpose_w1<<<(CIN*CIN*9+255)/256, 256>>>(w1);
  // conv3x3 split per batch (8 launches) so the ncu -s 5 -c 1 window lands
  // on a conv3x3 instance — the dominant kernel we need visibility into.
  for (int b=0; b<BATCH; b++)
    k_conv3x3<<<dim3(10,7,4), 256>>>(x, b1, b);
  k_conv1x1<<<dim3((HW+255)/256, BATCH), 256>>>(w2, b2, logits);
  k_softmax<<<(BATCH*HW+255)/256, 256>>>(logits);
  k_score<<<(BATCH*HW+255)/256, 256>>>();
  k_topk<<<BATCH, 256>>>();
  k_gather<<<(NOUT1+255)/256, 256>>>(x, pos, out);
}

// round 5
// speedup vs baseline: 1.2788x; 1.0297x over previous
#include <cuda_runtime.h>
#include <math.h>

#define BATCH 8
#define CIN 256
#define HH 100
#define WW 152
#define HW 15200
#define NC 81
#define NKEEP 100
#define NOUT1 (BATCH*CIN*NKEEP)   /* 204800 */

typedef unsigned long long ull;

// Scratch (device globals: allocation-free per harness rules)
__device__ float g_hid[(size_t)BATCH*CIN*HW];     // conv1 output (relu'd)
__device__ float g_w1t[CIN*9*CIN];                // w1 transposed to [ci][k][co]
__device__ int   g_cls[BATCH*HW];
__device__ float g_pv[BATCH*HW];
__device__ ull   g_keys[BATCH*HW];
__device__ int   g_topk[BATCH*NKEEP];

// Packed f32x2 helpers (SASS FFMA2 — exact IEEE fp32)
#define FMA2(d,a,b,c) asm("fma.rn.f32x2 %0, %1, %2, %3;" : "=l"(d) : "l"(a), "l"(b), "l"(c))
#define PACK2(d,lo,hi) asm("mov.b64 %0, {%1, %2};" : "=l"(d) : "f"(lo), "f"(hi))
#define UNPACK2(lo,hi,s) asm("mov.b64 {%0, %1}, %2;" : "=f"(lo), "=f"(hi) : "l"(s))

// ---------------------------------------------------------------------------
// w1 (co,ci,kh,kw) -> g_w1t[ci][k][co] for coalesced smem staging in conv3x3
// ---------------------------------------------------------------------------
__global__ void k_transpose_w1(const float* __restrict__ w1){
  int i = blockIdx.x*256 + threadIdx.x;
  if (i < CIN*CIN*9){
    int k = i % 9; int ci = (i/9) % CIN; int co = i/(9*CIN);
    g_w1t[ci*9*CIN + k*CIN + co] = w1[i];
  }
}

// ---------------------------------------------------------------------------
// 3x3 SAME conv, 256->256, + bias + relu, packed f32x2 FMA paired over CO.
// Block tile: 16 rows x 16 cols x 64 co. ci chunks of 4, register-double-
// buffered (prefetch chunk c+1 while computing c, one sync per chunk).
// Thread computes 8 co (4 f32x2 pairs) x 8 cols x 1 row.
// Data stored DUPLICATED (v,v) in smem at staging time; weight pairs are
// naturally adjacent co values -> inner loop has ZERO pack/mov instructions:
// 30 broadcast LDS.64 + 18 LDS.128 + 96 FFMA2 per ci.
// ---------------------------------------------------------------------------
__global__ __launch_bounds__(256,2) void k_conv3x3(const float* __restrict__ x,
                                                   const float* __restrict__ b1){
  __shared__ ull   s_vd[2][4][18][18];  // [buf][ci][y][x] = (v,v)
  __shared__ float s_w[2][4][9][64];    // [buf][ci][k][co]
  int tid = threadIdx.x;
  int x0 = blockIdx.x*16, y0 = blockIdx.y*16;
  int bz = blockIdx.z;
  int b   = bz >> 2;
  int co0 = (bz & 3) * 64;
  int og = tid & 7;           // co octet: co = co0 + og*8 .. +7
  int rg = (tid >> 3) & 15;   // row 0..15
  int cg = tid >> 7;          // col group: cols cg*8..cg*8+7
  int c0 = cg*8;
  int cob = co0 + og*8;

  ull acc[4][8];
  #pragma unroll
  for (int p=0;p<4;p++){
    float ba = b1[cob+2*p], bb = b1[cob+2*p+1];
    ull bp; PACK2(bp, ba, bb);
    #pragma unroll
    for (int j=0;j<8;j++) acc[p][j] = bp;
  }

  const float* xb = x + (size_t)b*CIN*HW;

  float rin[6], rw[9];

  // ---- prefetch + store chunk 0 ----
  #pragma unroll
  for (int t=0;t<6;t++){
    int i = tid + t*256; rin[t]=0.f;
    if (i < 4*18*18){
      int xx=i%18; int q=i/18; int yy=q%18; int ci=q/18;
      int gx=x0-1+xx, gy=y0-1+yy;
      if ((unsigned)gx < WW && (unsigned)gy < HH)
        rin[t] = xb[(size_t)ci*HW + gy*WW + gx];
    }
  }
  #pragma unroll
  for (int t=0;t<9;t++){
    int i = tid + t*256;
    int lco=i&63; int q=i>>6; int k=q%9; int ci=q/9;
    rw[t] = g_w1t[(size_t)ci*9*CIN + k*CIN + co0 + lco];
  }
  #pragma unroll
  for (int t=0;t<6;t++){
    int i = tid + t*256;
    if (i < 4*18*18){
      int xx=i%18; int q=i/18; int yy=q%18; int ci=q/18;
      ull d; PACK2(d, rin[t], rin[t]);
      s_vd[0][ci][yy][xx] = d;
    }
  }
  #pragma unroll
  for (int t=0;t<9;t++){
    int i = tid + t*256;
    int lco=i&63; int q=i>>6; int k=q%9; int ci=q/9;
    s_w[0][ci][k][lco] = rw[t];
  }
  __syncthreads();

  #pragma unroll 1
  for (int c=0; c<64; c++){
    int buf = c & 1;
    int ci0n = (c+1)*4;
    if (c+1 < 64){
      #pragma unroll
      for (int t=0;t<6;t++){
        int i = tid + t*256; rin[t]=0.f;
        if (i < 4*18*18){
          int xx=i%18; int q=i/18; int yy=q%18; int ci=q/18;
          int gx=x0-1+xx, gy=y0-1+yy;
          if ((unsigned)gx < WW && (unsigned)gy < HH)
            rin[t] = xb[(size_t)(ci0n+ci)*HW + gy*WW + gx];
        }
      }
      #pragma unroll
      for (int t=0;t<9;t++){
        int i = tid + t*256;
        int lco=i&63; int q=i>>6; int k=q%9; int ci=q/9;
        rw[t] = g_w1t[(size_t)(ci0n+ci)*9*CIN + k*CIN + co0 + lco];
      }
    }

    // ---- compute chunk c ----
    #pragma unroll 2
    for (int ci=0; ci<4; ci++){
      #pragma unroll
      for (int ky=0; ky<3; ky++){
        int y = rg + ky;                 // s_vd row (y0-1 offset built in)
        ull v[10];
        #pragma unroll
        for (int u=0;u<10;u++) v[u] = s_vd[buf][ci][y][c0+u];
        #pragma unroll
        for (int kx=0;kx<3;kx++){
          const ulonglong2* wp = (const ulonglong2*)&s_w[buf][ci][ky*3+kx][og*8];
          ulonglong2 wa = wp[0], wb = wp[1];
          #pragma unroll
          for (int j=0;j<8;j++){
            FMA2(acc[0][j], v[kx+j], wa.x, acc[0][j]);
            FMA2(acc[1][j], v[kx+j], wa.y, acc[1][j]);
            FMA2(acc[2][j], v[kx+j], wb.x, acc[2][j]);
            FMA2(acc[3][j], v[kx+j], wb.y, acc[3][j]);
          }
        }
      }
    }

    // ---- store prefetched chunk ----
    if (c+1 < 64){
      int nb = buf ^ 1;
      #pragma unroll
      for (int t=0;t<6;t++){
        int i = tid + t*256;
        if (i < 4*18*18){
          int xx=i%18; int q=i/18; int yy=q%18; int ci=q/18;
          ull d; PACK2(d, rin[t], rin[t]);
          s_vd[nb][ci][yy][xx] = d;
        }
      }
      #pragma unroll
      for (int t=0;t<9;t++){
        int i = tid + t*256;
        int lco=i&63; int q=i>>6; int k=q%9; int ci=q/9;
        s_w[nb][ci][k][lco] = rw[t];
      }
    }
    __syncthreads();
  }

  // epilogue: unpack co-pairs, relu, store one row of 8 px per co (8 co)
  int gy = y0 + rg;
  int gx = x0 + c0;
  if (gy < HH && gx + 7 < WW){
    #pragma unroll
    for (int p=0;p<4;p++){
      float lo[8], hi[8];
      #pragma unroll
      for (int j=0;j<8;j++){
        UNPACK2(lo[j], hi[j], acc[p][j]);
        lo[j] = fmaxf(lo[j], 0.f); hi[j] = fmaxf(hi[j], 0.f);
      }
      float* h0 = g_hid + ((size_t)b*CIN + (cob+2*p  ))*HW + (size_t)gy*WW + gx;
      float* h1 = g_hid + ((size_t)b*CIN + (cob+2*p+1))*HW + (size_t)gy*WW + gx;
      *(float4*)h0     = make_float4(lo[0],lo[1],lo[2],lo[3]);
      *(float4*)(h0+4) = make_float4(lo[4],lo[5],lo[6],lo[7]);
      *(float4*)h1     = make_float4(hi[0],hi[1],hi[2],hi[3]);
      *(float4*)(h1+4) = make_float4(hi[4],hi[5],hi[6],hi[7]);
    }
  }
}

// ---------------------------------------------------------------------------
// 1x1 conv 256->81 + bias, f32x2 (co pairs). One px per thread, co in 3
// chunks of 27 (28 padded -> 14 pairs). Weight pairs pre-packed in smem,
// broadcast LDS.64 in the inner loop.
// ---------------------------------------------------------------------------
__global__ __launch_bounds__(256) void k_conv1x1(const float* __restrict__ w2,
                                                 const float* __restrict__ b2,
                                                 float* __restrict__ logits){
  __shared__ ull s_w[256*14];    // [ci][pair j] = (w[2j], w[2j+1]), 28KB
  int tid = threadIdx.x;
  int b  = blockIdx.y;
  int px = blockIdx.x*256 + tid;
  const float* hb = g_hid + (size_t)b*CIN*HW;
  float* ob = logits + (size_t)b*NC*HW;

  for (int cc=0; cc<3; cc++){
    __syncthreads();
    for (int i=tid; i<256*14; i+=256){
      int j = i % 14; int ci = i/14;
      float wa = (2*j   < 27) ? w2[(cc*27+2*j  )*CIN + ci] : 0.f;
      float wb = (2*j+1 < 27) ? w2[(cc*27+2*j+1)*CIN + ci] : 0.f;
      ull d; PACK2(d, wa, wb);
      s_w[i] = d;
    }
    __syncthreads();
    if (px < HW){
      ull acc[14];
      #pragma unroll
      for (int j=0;j<14;j++){
        float ba = (2*j   < 27) ? b2[cc*27+2*j  ] : 0.f;
        float bb = (2*j+1 < 27) ? b2[cc*27+2*j+1] : 0.f;
        PACK2(acc[j], ba, bb);
      }
      #pragma unroll 4
      for (int ci=0; ci<CIN; ci++){
        float v = hb[(size_t)ci*HW + px];
        ull vd; PACK2(vd, v, v);
        const ull* wp = s_w + ci*14;
        #pragma unroll
        for (int j=0;j<14;j++) FMA2(acc[j], vd, wp[j], acc[j]);
      }
      #pragma unroll
      for (int j=0;j<14;j++){
        float a, c; UNPACK2(a, c, acc[j]);
        if (2*j   < 27) ob[(size_t)(cc*27+2*j  )*HW + px] = a;
        if (2*j+1 < 27) ob[(size_t)(cc*27+2*j+1)*HW + px] = c;
      }
    }
  }
}

// ---------------------------------------------------------------------------
// Per-pixel: softmax over 81 channels, argmax over first 80 (first-max wins),
// p = prob at argmax channel. (After masking only that channel is nonzero.)
// ---------------------------------------------------------------------------
__global__ void k_softmax(const float* __restrict__ logits){
  int i = blockIdx.x*256 + threadIdx.x;
  if (i >= BATCH*HW) return;
  int b = i / HW, px = i - b*HW;
  const float* lp = logits + (size_t)b*NC*HW + px;
  float M = -1e30f, best = -1e30f; int bi = 0;
  #pragma unroll 1
  for (int c=0;c<NC;c++){
    float v = lp[(size_t)c*HW];
    if (c < 80 && v > best){ best = v; bi = c; }
    M = fmaxf(M, v);
  }
  float s = 0.f;
  #pragma unroll 1
  for (int c=0;c<NC;c++) s += expf(lp[(size_t)c*HW] - M);
  g_pv[i] = expf(best - M) / s;
  g_cls[i] = bi;
}

// ---------------------------------------------------------------------------
// score = p + 1 if (p>=eps and no in-bounds 8-neighbor with same class and
// strictly larger p). Emits sortable key: (score_bits<<32) | (~px) so ties
// prefer the smaller index (lax.top_k semantics). score >= 0 always.
// ---------------------------------------------------------------------------
__global__ void k_score(){
  int i = blockIdx.x*256 + threadIdx.x;
  if (i >= BATCH*HW) return;
  int b = i / HW, px = i - b*HW;
  int y = px / WW, xx = px - y*WW;
  float p = g_pv[i]; int cls = g_cls[i];
  bool flag = (p >= 1e-6f);
  if (flag){
    #pragma unroll
    for (int dy=-1; dy<=1; dy++){
      #pragma unroll
      for (int dx=-1; dx<=1; dx++){
        if (dy==0 && dx==0) continue;
        int ny = y+dy, nx = xx+dx;
        if ((unsigned)ny < HH && (unsigned)nx < WW){
          int j = b*HW + ny*WW + nx;
          if (g_cls[j]==cls && g_pv[j] > p) flag = false;
        }
      }
    }
  }
  float score = p + (flag ? 1.f : 0.f);
  g_keys[i] = (((ull)__float_as_uint(score))<<32)
              | (ull)(0xFFFFFFFFu - (unsigned)px);
}

// ---------------------------------------------------------------------------
// Top-100 per batch: 100 iterations of block-wide argmax over 15200 keys
// (L2-resident), zero the winner each round. Exact lax.top_k ordering.
// ---------------------------------------------------------------------------
__global__ void k_topk(){
  __shared__ ull s_red[256];
  int b = blockIdx.x, tid = threadIdx.x;
  ull* kb = g_keys + (size_t)b*HW;
  for (int it=0; it<NKEEP; it++){
    ull best = 0ull;
    for (int i=tid; i<HW; i+=256){
      ull k = kb[i];
      if (k > best) best = k;
    }
    s_red[tid] = best;
    __syncthreads();
    #pragma unroll
    for (int s=128; s>0; s>>=1){
      if (tid < s && s_red[tid+s] > s_red[tid]) s_red[tid] = s_red[tid+s];
      __syncthreads();
    }
    ull win = s_red[0];
    int wpx = (int)(0xFFFFFFFFu - (unsigned)(win & 0xFFFFFFFFull));
    if (tid==0){
      g_topk[b*NKEEP+it] = wpx;
      kb[wpx] = 0ull;      // exclude winner; __syncthreads gives block visibility
    }
    __syncthreads();
  }
}

// ---------------------------------------------------------------------------
// Gather x and pos at top-k indices. out layout: [proposals | pos | logits]
// ---------------------------------------------------------------------------
__global__ void k_gather(const float* __restrict__ x, const float* __restrict__ pos,
                         float* __restrict__ out){
  int i = blockIdx.x*256 + threadIdx.x;
  if (i >= NOUT1) return;
  int k = i % NKEEP; int t = i / NKEEP; int c = t % CIN; int b = t / CIN;
  int px = g_topk[b*NKEEP + k];
  out[i]         = x[((size_t)b*CIN + c)*HW + px];
  out[NOUT1 + i] = pos[(size_t)c*HW + px];
}

// ---------------------------------------------------------------------------
extern "C" void kernel_launch(void* const* d_in, const int* in_sizes, int n_in,
                              void* d_out, int out_size){
  (void)in_sizes; (void)n_in; (void)out_size;
  const float* x   = (const float*)d_in[0];
  const float* pos = (const float*)d_in[1];
  const float* w1  = (const float*)d_in[2];
  const float* b1  = (const float*)d_in[3];
  const float* w2  = (const float*)d_in[4];
  const float* b2  = (const float*)d_in[5];
  float* out = (float*)d_out;
  float* logits = out + 2*NOUT1;

  k_transpose_w1<<<(CIN*CIN*9+255)/256, 256>>>(w1);
  k_conv3x3<<<dim3(10,7,BATCH*4), 256>>>(x, b1);
  k_conv1x1<<<dim3((HW+255)/256, BATCH), 256>>>(w2, b2, logits);
  k_softmax<<<(BATCH*HW+255)/256, 256>>>(logits);
  k_score<<<(BATCH*HW+255)/256, 256>>>();
  k_topk<<<BATCH, 256>>>();
  k_gather<<<(NOUT1+255)/256, 256>>>(x, pos, out);
}

// round 6
// speedup vs baseline: 1.2788x; 1.0000x over previous
#include <cuda_runtime.h>
#include <math.h>

#define BATCH 8
#define CIN 256
#define HH 100
#define WW 152
#define HW 15200
#define NC 81
#define NKEEP 100
#define NOUT1 (BATCH*CIN*NKEEP)   /* 204800 */

typedef unsigned long long ull;

// Scratch (device globals: allocation-free per harness rules)
__device__ float g_hid[(size_t)BATCH*CIN*HW];     // conv1 output (relu'd)
__device__ float g_w1t[CIN*9*CIN];                // w1 transposed to [ci][k][co]
__device__ int   g_cls[BATCH*HW];
__device__ float g_pv[BATCH*HW];
__device__ ull   g_keys[BATCH*HW];
__device__ int   g_topk[BATCH*NKEEP];

// Packed f32x2 helpers (SASS FFMA2 — exact IEEE fp32)
#define FMA2(d,a,b,c) asm("fma.rn.f32x2 %0, %1, %2, %3;" : "=l"(d) : "l"(a), "l"(b), "l"(c))
#define PACK2(d,lo,hi) asm("mov.b64 %0, {%1, %2};" : "=l"(d) : "f"(lo), "f"(hi))
#define UNPACK2(lo,hi,s) asm("mov.b64 {%0, %1}, %2;" : "=f"(lo), "=f"(hi) : "l"(s))

// ---------------------------------------------------------------------------
// w1 (co,ci,kh,kw) -> g_w1t[ci][k][co] for coalesced smem staging in conv3x3
// ---------------------------------------------------------------------------
__global__ void k_transpose_w1(const float* __restrict__ w1){
  int i = blockIdx.x*256 + threadIdx.x;
  if (i < CIN*CIN*9){
    int k = i % 9; int ci = (i/9) % CIN; int co = i/(9*CIN);
    g_w1t[ci*9*CIN + k*CIN + co] = w1[i];
  }
}

// ---------------------------------------------------------------------------
// 3x3 SAME conv, 256->256, + bias + relu, packed f32x2 FMA paired over CO.
// Block tile: 16 rows x 16 cols x 64 co. ci chunks of 4, register-double-
// buffered (prefetch chunk c+1 while computing c, one sync per chunk).
// Thread computes 8 co (4 f32x2 pairs) x 8 cols x 1 row.
// Data stored DUPLICATED (v,v) in smem at staging time; weight pairs are
// naturally adjacent co values -> inner loop has ZERO pack/mov instructions:
// 30 broadcast LDS.64 + 18 LDS.128 + 96 FFMA2 per ci.
// ---------------------------------------------------------------------------
__global__ __launch_bounds__(256,2) void k_conv3x3(const float* __restrict__ x,
                                                   const float* __restrict__ b1){
  __shared__ ull   s_vd[2][4][18][18];  // [buf][ci][y][x] = (v,v)
  __shared__ float s_w[2][4][9][64];    // [buf][ci][k][co]
  int tid = threadIdx.x;
  int x0 = blockIdx.x*16, y0 = blockIdx.y*16;
  int bz = blockIdx.z;
  int b   = bz >> 2;
  int co0 = (bz & 3) * 64;
  int og = tid & 7;           // co octet: co = co0 + og*8 .. +7
  int rg = (tid >> 3) & 15;   // row 0..15
  int cg = tid >> 7;          // col group: cols cg*8..cg*8+7
  int c0 = cg*8;
  int cob = co0 + og*8;

  ull acc[4][8];
  #pragma unroll
  for (int p=0;p<4;p++){
    float ba = b1[cob+2*p], bb = b1[cob+2*p+1];
    ull bp; PACK2(bp, ba, bb);
    #pragma unroll
    for (int j=0;j<8;j++) acc[p][j] = bp;
  }

  const float* xb = x + (size_t)b*CIN*HW;

  float rin[6], rw[9];

  // ---- prefetch + store chunk 0 ----
  #pragma unroll
  for (int t=0;t<6;t++){
    int i = tid + t*256; rin[t]=0.f;
    if (i < 4*18*18){
      int xx=i%18; int q=i/18; int yy=q%18; int ci=q/18;
      int gx=x0-1+xx, gy=y0-1+yy;
      if ((unsigned)gx < WW && (unsigned)gy < HH)
        rin[t] = xb[(size_t)ci*HW + gy*WW + gx];
    }
  }
  #pragma unroll
  for (int t=0;t<9;t++){
    int i = tid + t*256;
    int lco=i&63; int q=i>>6; int k=q%9; int ci=q/9;
    rw[t] = g_w1t[(size_t)ci*9*CIN + k*CIN + co0 + lco];
  }
  #pragma unroll
  for (int t=0;t<6;t++){
    int i = tid + t*256;
    if (i < 4*18*18){
      int xx=i%18; int q=i/18; int yy=q%18; int ci=q/18;
      ull d; PACK2(d, rin[t], rin[t]);
      s_vd[0][ci][yy][xx] = d;
    }
  }
  #pragma unroll
  for (int t=0;t<9;t++){
    int i = tid + t*256;
    int lco=i&63; int q=i>>6; int k=q%9; int ci=q/9;
    s_w[0][ci][k][lco] = rw[t];
  }
  __syncthreads();

  #pragma unroll 1
  for (int c=0; c<64; c++){
    int buf = c & 1;
    int ci0n = (c+1)*4;
    if (c+1 < 64){
      #pragma unroll
      for (int t=0;t<6;t++){
        int i = tid + t*256; rin[t]=0.f;
        if (i < 4*18*18){
          int xx=i%18; int q=i/18; int yy=q%18; int ci=q/18;
          int gx=x0-1+xx, gy=y0-1+yy;
          if ((unsigned)gx < WW && (unsigned)gy < HH)
            rin[t] = xb[(size_t)(ci0n+ci)*HW + gy*WW + gx];
        }
      }
      #pragma unroll
      for (int t=0;t<9;t++){
        int i = tid + t*256;
        int lco=i&63; int q=i>>6; int k=q%9; int ci=q/9;
        rw[t] = g_w1t[(size_t)(ci0n+ci)*9*CIN + k*CIN + co0 + lco];
      }
    }

    // ---- compute chunk c ----
    #pragma unroll 2
    for (int ci=0; ci<4; ci++){
      #pragma unroll
      for (int ky=0; ky<3; ky++){
        int y = rg + ky;                 // s_vd row (y0-1 offset built in)
        ull v[10];
        #pragma unroll
        for (int u=0;u<10;u++) v[u] = s_vd[buf][ci][y][c0+u];
        #pragma unroll
        for (int kx=0;kx<3;kx++){
          const ulonglong2* wp = (const ulonglong2*)&s_w[buf][ci][ky*3+kx][og*8];
          ulonglong2 wa = wp[0], wb = wp[1];
          #pragma unroll
          for (int j=0;j<8;j++){
            FMA2(acc[0][j], v[kx+j], wa.x, acc[0][j]);
            FMA2(acc[1][j], v[kx+j], wa.y, acc[1][j]);
            FMA2(acc[2][j], v[kx+j], wb.x, acc[2][j]);
            FMA2(acc[3][j], v[kx+j], wb.y, acc[3][j]);
          }
        }
      }
    }

    // ---- store prefetched chunk ----
    if (c+1 < 64){
      int nb = buf ^ 1;
      #pragma unroll
      for (int t=0;t<6;t++){
        int i = tid + t*256;
        if (i < 4*18*18){
          int xx=i%18; int q=i/18; int yy=q%18; int ci=q/18;
          ull d; PACK2(d, rin[t], rin[t]);
          s_vd[nb][ci][yy][xx] = d;
        }
      }
      #pragma unroll
      for (int t=0;t<9;t++){
        int i = tid + t*256;
        int lco=i&63; int q=i>>6; int k=q%9; int ci=q/9;
        s_w[nb][ci][k][lco] = rw[t];
      }
    }
    __syncthreads();
  }

  // epilogue: unpack co-pairs, relu, store one row of 8 px per co (8 co)
  int gy = y0 + rg;
  int gx = x0 + c0;
  if (gy < HH && gx + 7 < WW){
    #pragma unroll
    for (int p=0;p<4;p++){
      float lo[8], hi[8];
      #pragma unroll
      for (int j=0;j<8;j++){
        UNPACK2(lo[j], hi[j], acc[p][j]);
        lo[j] = fmaxf(lo[j], 0.f); hi[j] = fmaxf(hi[j], 0.f);
      }
      float* h0 = g_hid + ((size_t)b*CIN + (cob+2*p  ))*HW + (size_t)gy*WW + gx;
      float* h1 = g_hid + ((size_t)b*CIN + (cob+2*p+1))*HW + (size_t)gy*WW + gx;
      *(float4*)h0     = make_float4(lo[0],lo[1],lo[2],lo[3]);
      *(float4*)(h0+4) = make_float4(lo[4],lo[5],lo[6],lo[7]);
      *(float4*)h1     = make_float4(hi[0],hi[1],hi[2],hi[3]);
      *(float4*)(h1+4) = make_float4(hi[4],hi[5],hi[6],hi[7]);
    }
  }
}

// ---------------------------------------------------------------------------
// 1x1 conv 256->81 + bias, f32x2 (co pairs). One px per thread, co in 3
// chunks of 27 (28 padded -> 14 pairs). Weight pairs pre-packed in smem,
// broadcast LDS.64 in the inner loop.
// ---------------------------------------------------------------------------
__global__ __launch_bounds__(256) void k_conv1x1(const float* __restrict__ w2,
                                                 const float* __restrict__ b2,
                                                 float* __restrict__ logits){
  __shared__ ull s_w[256*14];    // [ci][pair j] = (w[2j], w[2j+1]), 28KB
  int tid = threadIdx.x;
  int b  = blockIdx.y;
  int px = blockIdx.x*256 + tid;
  const float* hb = g_hid + (size_t)b*CIN*HW;
  float* ob = logits + (size_t)b*NC*HW;

  for (int cc=0; cc<3; cc++){
    __syncthreads();
    for (int i=tid; i<256*14; i+=256){
      int j = i % 14; int ci = i/14;
      float wa = (2*j   < 27) ? w2[(cc*27+2*j  )*CIN + ci] : 0.f;
      float wb = (2*j+1 < 27) ? w2[(cc*27+2*j+1)*CIN + ci] : 0.f;
      ull d; PACK2(d, wa, wb);
      s_w[i] = d;
    }
    __syncthreads();
    if (px < HW){
      ull acc[14];
      #pragma unroll
      for (int j=0;j<14;j++){
        float ba = (2*j   < 27) ? b2[cc*27+2*j  ] : 0.f;
        float bb = (2*j+1 < 27) ? b2[cc*27+2*j+1] : 0.f;
        PACK2(acc[j], ba, bb);
      }
      #pragma unroll 4
      for (int ci=0; ci<CIN; ci++){
        float v = hb[(size_t)ci*HW + px];
        ull vd; PACK2(vd, v, v);
        const ull* wp = s_w + ci*14;
        #pragma unroll
        for (int j=0;j<14;j++) FMA2(acc[j], vd, wp[j], acc[j]);
      }
      #pragma unroll
      for (int j=0;j<14;j++){
        float a, c; UNPACK2(a, c, acc[j]);
        if (2*j   < 27) ob[(size_t)(cc*27+2*j  )*HW + px] = a;
        if (2*j+1 < 27) ob[(size_t)(cc*27+2*j+1)*HW + px] = c;
      }
    }
  }
}

// ---------------------------------------------------------------------------
// Per-pixel: softmax over 81 channels, argmax over first 80 (first-max wins),
// p = prob at argmax channel. (After masking only that channel is nonzero.)
// ---------------------------------------------------------------------------
__global__ void k_softmax(const float* __restrict__ logits){
  int i = blockIdx.x*256 + threadIdx.x;
  if (i >= BATCH*HW) return;
  int b = i / HW, px = i - b*HW;
  const float* lp = logits + (size_t)b*NC*HW + px;
  float M = -1e30f, best = -1e30f; int bi = 0;
  #pragma unroll 1
  for (int c=0;c<NC;c++){
    float v = lp[(size_t)c*HW];
    if (c < 80 && v > best){ best = v; bi = c; }
    M = fmaxf(M, v);
  }
  float s = 0.f;
  #pragma unroll 1
  for (int c=0;c<NC;c++) s += expf(lp[(size_t)c*HW] - M);
  g_pv[i] = expf(best - M) / s;
  g_cls[i] = bi;
}

// ---------------------------------------------------------------------------
// score = p + 1 if (p>=eps and no in-bounds 8-neighbor with same class and
// strictly larger p). Emits sortable key: (score_bits<<32) | (~px) so ties
// prefer the smaller index (lax.top_k semantics). score >= 0 always.
// ---------------------------------------------------------------------------
__global__ void k_score(){
  int i = blockIdx.x*256 + threadIdx.x;
  if (i >= BATCH*HW) return;
  int b = i / HW, px = i - b*HW;
  int y = px / WW, xx = px - y*WW;
  float p = g_pv[i]; int cls = g_cls[i];
  bool flag = (p >= 1e-6f);
  if (flag){
    #pragma unroll
    for (int dy=-1; dy<=1; dy++){
      #pragma unroll
      for (int dx=-1; dx<=1; dx++){
        if (dy==0 && dx==0) continue;
        int ny = y+dy, nx = xx+dx;
        if ((unsigned)ny < HH && (unsigned)nx < WW){
          int j = b*HW + ny*WW + nx;
          if (g_cls[j]==cls && g_pv[j] > p) flag = false;
        }
      }
    }
  }
  float score = p + (flag ? 1.f : 0.f);
  g_keys[i] = (((ull)__float_as_uint(score))<<32)
              | (ull)(0xFFFFFFFFu - (unsigned)px);
}

// ---------------------------------------------------------------------------
// Top-100 per batch: 100 iterations of block-wide argmax over 15200 keys
// (L2-resident), zero the winner each round. Exact lax.top_k ordering.
// ---------------------------------------------------------------------------
__global__ void k_topk(){
  __shared__ ull s_red[256];
  int b = blockIdx.x, tid = threadIdx.x;
  ull* kb = g_keys + (size_t)b*HW;
  for (int it=0; it<NKEEP; it++){
    ull best = 0ull;
    for (int i=tid; i<HW; i+=256){
      ull k = kb[i];
      if (k > best) best = k;
    }
    s_red[tid] = best;
    __syncthreads();
    #pragma unroll
    for (int s=128; s>0; s>>=1){
      if (tid < s && s_red[tid+s] > s_red[tid]) s_red[tid] = s_red[tid+s];
      __syncthreads();
    }
    ull win = s_red[0];
    int wpx = (int)(0xFFFFFFFFu - (unsigned)(win & 0xFFFFFFFFull));
    if (tid==0){
      g_topk[b*NKEEP+it] = wpx;
      kb[wpx] = 0ull;      // exclude winner; __syncthreads gives block visibility
    }
    __syncthreads();
  }
}

// ---------------------------------------------------------------------------
// Gather x and pos at top-k indices. out layout: [proposals | pos | logits]
// ---------------------------------------------------------------------------
__global__ void k_gather(const float* __restrict__ x, const float* __restrict__ pos,
                         float* __restrict__ out){
  int i = blockIdx.x*256 + threadIdx.x;
  if (i >= NOUT1) return;
  int k = i % NKEEP; int t = i / NKEEP; int c = t % CIN; int b = t / CIN;
  int px = g_topk[b*NKEEP + k];
  out[i]         = x[((size_t)b*CIN + c)*HW + px];
  out[NOUT1 + i] = pos[(size_t)c*HW + px];
}

// ---------------------------------------------------------------------------
extern "C" void kernel_launch(void* const* d_in, const int* in_sizes, int n_in,
                              void* d_out, int out_size){
  (void)in_sizes; (void)n_in; (void)out_size;
  const float* x   = (const float*)d_in[0];
  const float* pos = (const float*)d_in[1];
  const float* w1  = (const float*)d_in[2];
  const float* b1  = (const float*)d_in[3];
  const float* w2  = (const float*)d_in[4];
  const float* b2  = (const float*)d_in[5];
  float* out = (float*)d_out;
  float* logits = out + 2*NOUT1;

  k_transpose_w1<<<(CIN*CIN*9+255)/256, 256>>>(w1);
  k_conv3x3<<<dim3(10,7,BATCH*4), 256>>>(x, b1);
  k_conv1x1<<<dim3((HW+255)/256, BATCH), 256>>>(w2, b2, logits);
  k_softmax<<<(BATCH*HW+255)/256, 256>>>(logits);
  k_score<<<(BATCH*HW+255)/256, 256>>>();
  k_topk<<<BATCH, 256>>>();
  k_gather<<<(NOUT1+255)/256, 256>>>(x, pos, out);
}

// round 8
// speedup vs baseline: 2.4499x; 1.9157x over previous
#include <cuda_runtime.h>
#include <math.h>

#define BATCH 8
#define CIN 256
#define HH 100
#define WW 152
#define HW 15200
#define NC 81
#define NKEEP 100
#define NOUT1 (BATCH*CIN*NKEEP)   /* 204800 */

#define NTILES 7600       /* 8 * 25 * 38 */
#define TPB    950        /* tiles per batch image */
#define TPAD   7680       /* padded tile count (60 * 128) */

typedef unsigned long long ull;

// ---------------------------------------------------------------------------
// Device scratch (allocation-free per harness rules)
// ---------------------------------------------------------------------------
__device__ float g_hid[(size_t)BATCH*CIN*HW];     // conv1 output (relu'd)
__device__ int   g_cls[BATCH*HW];
__device__ float g_pv[BATCH*HW];
__device__ ull   g_keys[BATCH*HW];
__device__ int   g_topk[BATCH*NKEEP];
// Winograd buffers
__device__ float g_U[(size_t)36*CIN*CIN];         // weight transform [k][ci][co]
__device__ float g_V[(size_t)36*CIN*TPAD];        // input transform  [k][ci][t]
__device__ float g_M[(size_t)36*CIN*TPAD];        // GEMM output      [k][co][t]

// Packed f32x2 helpers (SASS FFMA2 — exact IEEE fp32)
#define FMA2(d,a,b,c) asm("fma.rn.f32x2 %0, %1, %2, %3;" : "=l"(d) : "l"(a), "l"(b), "l"(c))
#define PACK2(d,lo,hi) asm("mov.b64 %0, {%1, %2};" : "=l"(d) : "f"(lo), "f"(hi))
#define UNPACK2(lo,hi,s) asm("mov.b64 {%0, %1}, %2;" : "=f"(lo), "=f"(hi) : "l"(s))

// ---------------------------------------------------------------------------
// Winograd F(4x4,3x3) weight transform: U = G g G^T, stored [k=36][ci][co]
// (co contiguous for GEMM weight staging).
// ---------------------------------------------------------------------------
__global__ void k_wino_w(const float* __restrict__ w1){
  int i = blockIdx.x*256 + threadIdx.x;
  if (i >= CIN*CIN) return;
  int co = i & 255, ci = i >> 8;
  float g[3][3];
  #pragma unroll
  for (int m=0;m<3;m++)
    #pragma unroll
    for (int j=0;j<3;j++)
      g[m][j] = w1[((size_t)(co*CIN+ci)*3+m)*3+j];
  float T1[6][3];
  #pragma unroll
  for (int j=0;j<3;j++){
    float g0=g[0][j], g1=g[1][j], g2=g[2][j];
    T1[0][j] = 0.25f*g0;
    T1[1][j] = (-g0-g1-g2)*(1.f/6.f);
    T1[2][j] = (-g0+g1-g2)*(1.f/6.f);
    T1[3][j] = g0*(1.f/24.f)+g1*(1.f/12.f)+g2*(1.f/6.f);
    T1[4][j] = g0*(1.f/24.f)-g1*(1.f/12.f)+g2*(1.f/6.f);
    T1[5][j] = g2;
  }
  #pragma unroll
  for (int r=0;r<6;r++){
    float t0=T1[r][0], t1=T1[r][1], t2=T1[r][2];
    float u[6];
    u[0] = 0.25f*t0;
    u[1] = (-t0-t1-t2)*(1.f/6.f);
    u[2] = (-t0+t1-t2)*(1.f/6.f);
    u[3] = t0*(1.f/24.f)+t1*(1.f/12.f)+t2*(1.f/6.f);
    u[4] = t0*(1.f/24.f)-t1*(1.f/12.f)+t2*(1.f/6.f);
    u[5] = t2;
    #pragma unroll
    for (int c=0;c<6;c++)
      g_U[((size_t)(r*6+c)*CIN + ci)*CIN + co] = u[c];
  }
}

// ---------------------------------------------------------------------------
// Input transform: V = B^T d B per (tile, ci). Tile (b,ty,tx): 6x6 patch at
// (4ty-1, 4tx-1), zero-padded. Stored [k][ci][t] (t contiguous -> coalesced).
// ---------------------------------------------------------------------------
__global__ void k_wino_in(const float* __restrict__ x){
  int t = blockIdx.x*256 + threadIdx.x;
  int ci = blockIdx.y;
  if (t >= NTILES) return;
  int b = t / TPB, rr = t - b*TPB;
  int ty = rr / 38, tx = rr - ty*38;
  int y0 = ty*4 - 1, xg0 = tx*4 - 1;
  const float* xp = x + ((size_t)b*CIN + ci)*HW;
  float d[6][6];
  #pragma unroll
  for (int m=0;m<6;m++){
    int gy = y0 + m;
    bool ry = ((unsigned)gy < HH);
    #pragma unroll
    for (int j=0;j<6;j++){
      int gx = xg0 + j;
      d[m][j] = (ry && (unsigned)gx < WW) ? xp[gy*WW + gx] : 0.f;
    }
  }
  float tmp[6][6];
  #pragma unroll
  for (int j=0;j<6;j++){
    float d0=d[0][j],d1=d[1][j],d2=d[2][j],d3=d[3][j],d4=d[4][j],d5=d[5][j];
    tmp[0][j] = 4.f*d0 - 5.f*d2 + d4;
    tmp[1][j] = -4.f*d1 - 4.f*d2 + d3 + d4;
    tmp[2][j] =  4.f*d1 - 4.f*d2 - d3 + d4;
    tmp[3][j] = -2.f*d1 - d2 + 2.f*d3 + d4;
    tmp[4][j] =  2.f*d1 - d2 - 2.f*d3 + d4;
    tmp[5][j] =  4.f*d1 - 5.f*d3 + d5;
  }
  #pragma unroll
  for (int i=0;i<6;i++){
    float r0=tmp[i][0],r1=tmp[i][1],r2=tmp[i][2],r3=tmp[i][3],r4=tmp[i][4],r5=tmp[i][5];
    float v[6];
    v[0] = 4.f*r0 - 5.f*r2 + r4;
    v[1] = -4.f*r1 - 4.f*r2 + r3 + r4;
    v[2] =  4.f*r1 - 4.f*r2 - r3 + r4;
    v[3] = -2.f*r1 - r2 + 2.f*r3 + r4;
    v[4] =  2.f*r1 - r2 - 2.f*r3 + r4;
    v[5] =  4.f*r1 - 5.f*r3 + r5;
    #pragma unroll
    for (int c=0;c<6;c++)
      g_V[((size_t)(i*6+c)*CIN + ci)*TPAD + t] = v[c];
  }
}

// ---------------------------------------------------------------------------
// 36 GEMMs: M[k][co][t] = sum_ci U[k][ci][co] * V[k][ci][t].
// Block: 64co x 128t, ci chunks of 16, register-double-buffered.
// Thread: 8co (4 f32x2 pairs over co, weights naturally adjacent) x 4t.
// Data duplicated (v,v) in smem at staging; inner loop: 4 broadcast LDS.64
// + 2 LDS.128 + 16 FFMA2 per ci — the structure measured at ~97% of the
// FFMA2 RF-bank roofline in the direct conv.
// ---------------------------------------------------------------------------
__global__ __launch_bounds__(256,2) void k_gemm(){
  __shared__ __align__(16) ull   s_v[2][16][128];  // (v,v) pairs, 32KB
  __shared__ __align__(16) float s_w[2][16][64];   // 8KB
  int tid = threadIdx.x;
  int t0  = blockIdx.x*128;
  int co0 = blockIdx.y*64;
  int kk  = blockIdx.z;
  int og = tid & 7;        // co group: 8 co
  int tg = tid >> 3;       // t group: 4 t
  const float* Vk = g_V + (size_t)kk*CIN*TPAD;
  const float* Uk = g_U + (size_t)kk*CIN*CIN;

  ull acc[4][4];
  #pragma unroll
  for (int p=0;p<4;p++)
    #pragma unroll
    for (int j=0;j<4;j++) PACK2(acc[p][j], 0.f, 0.f);

  float4 rv[2], rw;
  int vci[2], vtq[2], wci, wcq;
  {
    int u0 = tid, u1 = tid + 256;
    vci[0]=u0>>5; vtq[0]=u0&31; vci[1]=u1>>5; vtq[1]=u1&31;
    wci = tid>>4; wcq = tid&15;
  }

  // prefetch chunk 0
  #pragma unroll
  for (int j=0;j<2;j++)
    rv[j] = *(const float4*)&Vk[(size_t)vci[j]*TPAD + t0 + vtq[j]*4];
  rw = *(const float4*)&Uk[(size_t)wci*CIN + co0 + wcq*4];
  #pragma unroll
  for (int j=0;j<2;j++){
    ull d0,d1,d2,d3;
    PACK2(d0,rv[j].x,rv[j].x); PACK2(d1,rv[j].y,rv[j].y);
    PACK2(d2,rv[j].z,rv[j].z); PACK2(d3,rv[j].w,rv[j].w);
    ull* dst = &s_v[0][vci[j]][vtq[j]*4];
    dst[0]=d0; dst[1]=d1; dst[2]=d2; dst[3]=d3;
  }
  *(float4*)&s_w[0][wci][wcq*4] = rw;
  __syncthreads();

  #pragma unroll 1
  for (int c=0; c<16; c++){
    int buf = c & 1;
    if (c+1 < 16){
      int ci0n = (c+1)*16;
      #pragma unroll
      for (int j=0;j<2;j++)
        rv[j] = *(const float4*)&Vk[(size_t)(ci0n+vci[j])*TPAD + t0 + vtq[j]*4];
      rw = *(const float4*)&Uk[(size_t)(ci0n+wci)*CIN + co0 + wcq*4];
    }

    #pragma unroll 4
    for (int ci=0; ci<16; ci++){
      ull v0 = s_v[buf][ci][tg*4+0];
      ull v1 = s_v[buf][ci][tg*4+1];
      ull v2 = s_v[buf][ci][tg*4+2];
      ull v3 = s_v[buf][ci][tg*4+3];
      ulonglong2 wa = *(const ulonglong2*)&s_w[buf][ci][og*8];
      ulonglong2 wb = *(const ulonglong2*)&s_w[buf][ci][og*8+4];
      FMA2(acc[0][0], v0, wa.x, acc[0][0]);
      FMA2(acc[0][1], v1, wa.x, acc[0][1]);
      FMA2(acc[0][2], v2, wa.x, acc[0][2]);
      FMA2(acc[0][3], v3, wa.x, acc[0][3]);
      FMA2(acc[1][0], v0, wa.y, acc[1][0]);
      FMA2(acc[1][1], v1, wa.y, acc[1][1]);
      FMA2(acc[1][2], v2, wa.y, acc[1][2]);
      FMA2(acc[1][3], v3, wa.y, acc[1][3]);
      FMA2(acc[2][0], v0, wb.x, acc[2][0]);
      FMA2(acc[2][1], v1, wb.x, acc[2][1]);
      FMA2(acc[2][2], v2, wb.x, acc[2][2]);
      FMA2(acc[2][3], v3, wb.x, acc[2][3]);
      FMA2(acc[3][0], v0, wb.y, acc[3][0]);
      FMA2(acc[3][1], v1, wb.y, acc[3][1]);
      FMA2(acc[3][2], v2, wb.y, acc[3][2]);
      FMA2(acc[3][3], v3, wb.y, acc[3][3]);
    }

    if (c+1 < 16){
      int nb = buf ^ 1;
      #pragma unroll
      for (int j=0;j<2;j++){
        ull d0,d1,d2,d3;
        PACK2(d0,rv[j].x,rv[j].x); PACK2(d1,rv[j].y,rv[j].y);
        PACK2(d2,rv[j].z,rv[j].z); PACK2(d3,rv[j].w,rv[j].w);
        ull* dst = &s_v[nb][vci[j]][vtq[j]*4];
        dst[0]=d0; dst[1]=d1; dst[2]=d2; dst[3]=d3;
      }
      *(float4*)&s_w[nb][wci][wcq*4] = rw;
    }
    __syncthreads();
  }

  // epilogue: unpack co-pairs, store 2 rows of 4 t per pair
  float* Mk = g_M + (size_t)kk*CIN*TPAD;
  #pragma unroll
  for (int p=0;p<4;p++){
    float lo[4], hi[4];
    #pragma unroll
    for (int j=0;j<4;j++) UNPACK2(lo[j], hi[j], acc[p][j]);
    int co = co0 + og*8 + 2*p;
    *(float4*)&Mk[(size_t)co*TPAD + t0 + tg*4] =
        make_float4(lo[0],lo[1],lo[2],lo[3]);
    *(float4*)&Mk[(size_t)(co+1)*TPAD + t0 + tg*4] =
        make_float4(hi[0],hi[1],hi[2],hi[3]);
  }
}

// ---------------------------------------------------------------------------
// Output transform: Y = A^T M A (6x6 -> 4x4), + bias + relu -> g_hid.
// ---------------------------------------------------------------------------
__global__ void k_wino_out(const float* __restrict__ b1){
  int t = blockIdx.x*256 + threadIdx.x;
  int co = blockIdx.y;
  if (t >= NTILES) return;
  float m6[6][6];
  #pragma unroll
  for (int k=0;k<36;k++)
    m6[k/6][k%6] = g_M[((size_t)k*CIN + co)*TPAD + t];
  float tmp[4][6];
  #pragma unroll
  for (int j=0;j<6;j++){
    float m0=m6[0][j],m1=m6[1][j],m2=m6[2][j],m3=m6[3][j],m4=m6[4][j],m5=m6[5][j];
    tmp[0][j] = m0+m1+m2+m3+m4;
    tmp[1][j] = m1-m2+2.f*m3-2.f*m4;
    tmp[2][j] = m1+m2+4.f*m3+4.f*m4;
    tmp[3][j] = m1-m2+8.f*m3-8.f*m4+m5;
  }
  int b = t / TPB, rr = t - b*TPB;
  int ty = rr / 38, tx = rr - ty*38;
  float bv = b1[co];
  float* hp = g_hid + ((size_t)b*CIN + co)*HW + (size_t)(ty*4)*WW + tx*4;
  #pragma unroll
  for (int i=0;i<4;i++){
    float r0=tmp[i][0],r1=tmp[i][1],r2=tmp[i][2],r3=tmp[i][3],r4=tmp[i][4],r5=tmp[i][5];
    float y0 = r0+r1+r2+r3+r4;
    float y1 = r1-r2+2.f*r3-2.f*r4;
    float y2 = r1+r2+4.f*r3+4.f*r4;
    float y3 = r1-r2+8.f*r3-8.f*r4+r5;
    float4 v;
    v.x = fmaxf(y0+bv, 0.f); v.y = fmaxf(y1+bv, 0.f);
    v.z = fmaxf(y2+bv, 0.f); v.w = fmaxf(y3+bv, 0.f);
    *(float4*)(hp + (size_t)i*WW) = v;
  }
}

// ---------------------------------------------------------------------------
// 1x1 conv 256->81 + bias, f32x2 (co pairs) — unchanged
// ---------------------------------------------------------------------------
__global__ __launch_bounds__(256) void k_conv1x1(const float* __restrict__ w2,
                                                 const float* __restrict__ b2,
                                                 float* __restrict__ logits){
  __shared__ ull s_w[256*14];
  int tid = threadIdx.x;
  int b  = blockIdx.y;
  int px = blockIdx.x*256 + tid;
  const float* hb = g_hid + (size_t)b*CIN*HW;
  float* ob = logits + (size_t)b*NC*HW;

  for (int cc=0; cc<3; cc++){
    __syncthreads();
    for (int i=tid; i<256*14; i+=256){
      int j = i % 14; int ci = i/14;
      float wa = (2*j   < 27) ? w2[(cc*27+2*j  )*CIN + ci] : 0.f;
      float wb = (2*j+1 < 27) ? w2[(cc*27+2*j+1)*CIN + ci] : 0.f;
      ull d; PACK2(d, wa, wb);
      s_w[i] = d;
    }
    __syncthreads();
    if (px < HW){
      ull acc[14];
      #pragma unroll
      for (int j=0;j<14;j++){
        float ba = (2*j   < 27) ? b2[cc*27+2*j  ] : 0.f;
        float bb = (2*j+1 < 27) ? b2[cc*27+2*j+1] : 0.f;
        PACK2(acc[j], ba, bb);
      }
      #pragma unroll 4
      for (int ci=0; ci<CIN; ci++){
        float v = hb[(size_t)ci*HW + px];
        ull vd; PACK2(vd, v, v);
        const ull* wp = s_w + ci*14;
        #pragma unroll
        for (int j=0;j<14;j++) FMA2(acc[j], vd, wp[j], acc[j]);
      }
      #pragma unroll
      for (int j=0;j<14;j++){
        float a, c; UNPACK2(a, c, acc[j]);
        if (2*j   < 27) ob[(size_t)(cc*27+2*j  )*HW + px] = a;
        if (2*j+1 < 27) ob[(size_t)(cc*27+2*j+1)*HW + px] = c;
      }
    }
  }
}

// ---------------------------------------------------------------------------
__global__ void k_softmax(const float* __restrict__ logits){
  int i = blockIdx.x*256 + threadIdx.x;
  if (i >= BATCH*HW) return;
  int b = i / HW, px = i - b*HW;
  const float* lp = logits + (size_t)b*NC*HW + px;
  float M = -1e30f, best = -1e30f; int bi = 0;
  #pragma unroll 1
  for (int c=0;c<NC;c++){
    float v = lp[(size_t)c*HW];
    if (c < 80 && v > best){ best = v; bi = c; }
    M = fmaxf(M, v);
  }
  float s = 0.f;
  #pragma unroll 1
  for (int c=0;c<NC;c++) s += expf(lp[(size_t)c*HW] - M);
  g_pv[i] = expf(best - M) / s;
  g_cls[i] = bi;
}

__global__ void k_score(){
  int i = blockIdx.x*256 + threadIdx.x;
  if (i >= BATCH*HW) return;
  int b = i / HW, px = i - b*HW;
  int y = px / WW, xx = px - y*WW;
  float p = g_pv[i]; int cls = g_cls[i];
  bool flag = (p >= 1e-6f);
  if (flag){
    #pragma unroll
    for (int dy=-1; dy<=1; dy++){
      #pragma unroll
      for (int dx=-1; dx<=1; dx++){
        if (dy==0 && dx==0) continue;
        int ny = y+dy, nx = xx+dx;
        if ((unsigned)ny < HH && (unsigned)nx < WW){
          int j = b*HW + ny*WW + nx;
          if (g_cls[j]==cls && g_pv[j] > p) flag = false;
        }
      }
    }
  }
  float score = p + (flag ? 1.f : 0.f);
  g_keys[i] = (((ull)__float_as_uint(score))<<32)
              | (ull)(0xFFFFFFFFu - (unsigned)px);
}

__global__ void k_topk(){
  __shared__ ull s_red[256];
  int b = blockIdx.x, tid = threadIdx.x;
  ull* kb = g_keys + (size_t)b*HW;
  for (int it=0; it<NKEEP; it++){
    ull best = 0ull;
    for (int i=tid; i<HW; i+=256){
      ull k = kb[i];
      if (k > best) best = k;
    }
    s_red[tid] = best;
    __syncthreads();
    #pragma unroll
    for (int s=128; s>0; s>>=1){
      if (tid < s && s_red[tid+s] > s_red[tid]) s_red[tid] = s_red[tid+s];
      __syncthreads();
    }
    ull win = s_red[0];
    int wpx = (int)(0xFFFFFFFFu - (unsigned)(win & 0xFFFFFFFFull));
    if (tid==0){
      g_topk[b*NKEEP+it] = wpx;
      kb[wpx] = 0ull;
    }
    __syncthreads();
  }
}

__global__ void k_gather(const float* __restrict__ x, const float* __restrict__ pos,
                         float* __restrict__ out){
  int i = blockIdx.x*256 + threadIdx.x;
  if (i >= NOUT1) return;
  int k = i % NKEEP; int t = i / NKEEP; int c = t % CIN; int b = t / CIN;
  int px = g_topk[b*NKEEP + k];
  out[i]         = x[((size_t)b*CIN + c)*HW + px];
  out[NOUT1 + i] = pos[(size_t)c*HW + px];
}

// ---------------------------------------------------------------------------
extern "C" void kernel_launch(void* const* d_in, const int* in_sizes, int n_in,
                              void* d_out, int out_size){
  (void)in_sizes; (void)n_in; (void)out_size;
  const float* x   = (const float*)d_in[0];
  const float* pos = (const float*)d_in[1];
  const float* w1  = (const float*)d_in[2];
  const float* b1  = (const float*)d_in[3];
  const float* w2  = (const float*)d_in[4];
  const float* b2  = (const float*)d_in[5];
  float* out = (float*)d_out;
  float* logits = out + 2*NOUT1;

  k_wino_w  <<<(CIN*CIN+255)/256, 256>>>(w1);
  k_wino_in <<<dim3((NTILES+255)/256, CIN), 256>>>(x);
  k_gemm    <<<dim3(TPAD/128, CIN/64, 36), 256>>>();
  k_wino_out<<<dim3((NTILES+255)/256, CIN), 256>>>(b1);
  k_conv1x1 <<<dim3((HW+255)/256, BATCH), 256>>>(w2, b2, logits);
  k_softmax <<<(BATCH*HW+255)/256, 256>>>(logits);
  k_score   <<<(BATCH*HW+255)/256, 256>>>();
  k_topk    <<<BATCH, 256>>>();
  k_gather  <<<(NOUT1+255)/256, 256>>>(x, pos, out);
}

// round 9
// speedup vs baseline: 2.8583x; 1.1667x over previous
#include <cuda_runtime.h>
#include <math.h>

#define BATCH 8
#define CIN 256
#define HH 100
#define WW 152
#define HW 15200
#define NC 81
#define NKEEP 100
#define NOUT1 (BATCH*CIN*NKEEP)   /* 204800 */

#define NTILES 7600       /* 8 * 25 * 38 */
#define TPB    950        /* tiles per batch image */
#define TPAD   7680       /* padded tile count (60 * 128) */

typedef unsigned long long ull;

// ---------------------------------------------------------------------------
// Device scratch (allocation-free per harness rules)
// ---------------------------------------------------------------------------
__device__ float g_hid[(size_t)BATCH*CIN*HW];     // conv1 output (relu'd)
__device__ int   g_cls[BATCH*HW];
__device__ float g_pv[BATCH*HW];
__device__ ull   g_keys[BATCH*HW];
__device__ int   g_topk[BATCH*NKEEP];
// Winograd buffers
__device__ float g_U[(size_t)36*CIN*CIN];         // weight transform [k][ci][co]
__device__ float g_V[(size_t)36*CIN*TPAD];        // input transform  [k][ci][t]
__device__ float g_M[(size_t)36*CIN*TPAD];        // GEMM output      [k][co][t]

// Packed f32x2 helpers (SASS FFMA2 — exact IEEE fp32)
#define FMA2(d,a,b,c) asm("fma.rn.f32x2 %0, %1, %2, %3;" : "=l"(d) : "l"(a), "l"(b), "l"(c))
#define PACK2(d,lo,hi) asm("mov.b64 %0, {%1, %2};" : "=l"(d) : "f"(lo), "f"(hi))
#define UNPACK2(lo,hi,s) asm("mov.b64 {%0, %1}, %2;" : "=f"(lo), "=f"(hi) : "l"(s))

// ---------------------------------------------------------------------------
// Winograd F(4x4,3x3) weight transform: U = G g G^T, stored [k=36][ci][co]
// ---------------------------------------------------------------------------
__global__ void k_wino_w(const float* __restrict__ w1){
  int i = blockIdx.x*256 + threadIdx.x;
  if (i >= CIN*CIN) return;
  int co = i & 255, ci = i >> 8;
  float g[3][3];
  #pragma unroll
  for (int m=0;m<3;m++)
    #pragma unroll
    for (int j=0;j<3;j++)
      g[m][j] = w1[((size_t)(co*CIN+ci)*3+m)*3+j];
  float T1[6][3];
  #pragma unroll
  for (int j=0;j<3;j++){
    float g0=g[0][j], g1=g[1][j], g2=g[2][j];
    T1[0][j] = 0.25f*g0;
    T1[1][j] = (-g0-g1-g2)*(1.f/6.f);
    T1[2][j] = (-g0+g1-g2)*(1.f/6.f);
    T1[3][j] = g0*(1.f/24.f)+g1*(1.f/12.f)+g2*(1.f/6.f);
    T1[4][j] = g0*(1.f/24.f)-g1*(1.f/12.f)+g2*(1.f/6.f);
    T1[5][j] = g2;
  }
  #pragma unroll
  for (int r=0;r<6;r++){
    float t0=T1[r][0], t1=T1[r][1], t2=T1[r][2];
    float u[6];
    u[0] = 0.25f*t0;
    u[1] = (-t0-t1-t2)*(1.f/6.f);
    u[2] = (-t0+t1-t2)*(1.f/6.f);
    u[3] = t0*(1.f/24.f)+t1*(1.f/12.f)+t2*(1.f/6.f);
    u[4] = t0*(1.f/24.f)-t1*(1.f/12.f)+t2*(1.f/6.f);
    u[5] = t2;
    #pragma unroll
    for (int c=0;c<6;c++)
      g_U[((size_t)(r*6+c)*CIN + ci)*CIN + co] = u[c];
  }
}

// ---------------------------------------------------------------------------
// Input transform: V = B^T d B per (tile, ci). Stored [k][ci][t].
// ---------------------------------------------------------------------------
__global__ void k_wino_in(const float* __restrict__ x){
  int t = blockIdx.x*256 + threadIdx.x;
  int ci = blockIdx.y;
  if (t >= NTILES) return;
  int b = t / TPB, rr = t - b*TPB;
  int ty = rr / 38, tx = rr - ty*38;
  int y0 = ty*4 - 1, xg0 = tx*4 - 1;
  const float* xp = x + ((size_t)b*CIN + ci)*HW;
  float d[6][6];
  #pragma unroll
  for (int m=0;m<6;m++){
    int gy = y0 + m;
    bool ry = ((unsigned)gy < HH);
    #pragma unroll
    for (int j=0;j<6;j++){
      int gx = xg0 + j;
      d[m][j] = (ry && (unsigned)gx < WW) ? xp[gy*WW + gx] : 0.f;
    }
  }
  float tmp[6][6];
  #pragma unroll
  for (int j=0;j<6;j++){
    float d0=d[0][j],d1=d[1][j],d2=d[2][j],d3=d[3][j],d4=d[4][j],d5=d[5][j];
    tmp[0][j] = 4.f*d0 - 5.f*d2 + d4;
    tmp[1][j] = -4.f*d1 - 4.f*d2 + d3 + d4;
    tmp[2][j] =  4.f*d1 - 4.f*d2 - d3 + d4;
    tmp[3][j] = -2.f*d1 - d2 + 2.f*d3 + d4;
    tmp[4][j] =  2.f*d1 - d2 - 2.f*d3 + d4;
    tmp[5][j] =  4.f*d1 - 5.f*d3 + d5;
  }
  #pragma unroll
  for (int i=0;i<6;i++){
    float r0=tmp[i][0],r1=tmp[i][1],r2=tmp[i][2],r3=tmp[i][3],r4=tmp[i][4],r5=tmp[i][5];
    float v[6];
    v[0] = 4.f*r0 - 5.f*r2 + r4;
    v[1] = -4.f*r1 - 4.f*r2 + r3 + r4;
    v[2] =  4.f*r1 - 4.f*r2 - r3 + r4;
    v[3] = -2.f*r1 - r2 + 2.f*r3 + r4;
    v[4] =  2.f*r1 - r2 - 2.f*r3 + r4;
    v[5] =  4.f*r1 - 5.f*r3 + r5;
    #pragma unroll
    for (int c=0;c<6;c++)
      g_V[((size_t)(i*6+c)*CIN + ci)*TPAD + t] = v[c];
  }
}

// ---------------------------------------------------------------------------
// GEMM v2: M[k][co][t] = sum_ci U[k][ci][co] * V[k][ci][t].
// Block: 128co x 128t, ci chunks of 8, register-double-buffered.
// Thread: 8co (4 f32x2 pairs) x 8t -> 32 FFMA2 per ci, acc = 32 ull.
// og in low lane bits -> data LDS.64 is broadcast; weight pairs pre-packed.
// ---------------------------------------------------------------------------
__global__ __launch_bounds__(256,2) void k_gemm(int kbase){
  __shared__ __align__(16) ull s_v[2][8][128];   // (v,v) pairs, 16KB
  __shared__ __align__(16) ull s_w[2][8][64];    // (w0,w1) pairs, 8KB
  int tid = threadIdx.x;
  int t0  = blockIdx.x*128;
  int co0 = blockIdx.y*128;
  int kk  = kbase + blockIdx.z;
  int og = tid & 15;       // co group: 8 co (4 pairs)
  int tg = tid >> 4;       // t group: 8 t
  const float* Vk = g_V + (size_t)kk*CIN*TPAD;
  const float* Uk = g_U + (size_t)kk*CIN*CIN;

  ull acc[4][8];
  #pragma unroll
  for (int p=0;p<4;p++)
    #pragma unroll
    for (int j=0;j<8;j++) PACK2(acc[p][j], 0.f, 0.f);

  int sci  = tid >> 5;       // staging row 0..7
  int scol = tid & 31;       // staging col group

  // prefetch + store chunk 0
  float4 rv = *(const float4*)&Vk[(size_t)sci*TPAD + t0 + scol*4];
  float4 rw = *(const float4*)&Uk[(size_t)sci*CIN + co0 + scol*4];
  {
    ull d0,d1,d2,d3;
    PACK2(d0,rv.x,rv.x); PACK2(d1,rv.y,rv.y);
    PACK2(d2,rv.z,rv.z); PACK2(d3,rv.w,rv.w);
    ull* dst = &s_v[0][sci][scol*4];
    dst[0]=d0; dst[1]=d1; dst[2]=d2; dst[3]=d3;
    ull w0,w1;
    PACK2(w0,rw.x,rw.y); PACK2(w1,rw.z,rw.w);
    s_w[0][sci][scol*2]   = w0;
    s_w[0][sci][scol*2+1] = w1;
  }
  __syncthreads();

  #pragma unroll 1
  for (int c=0; c<32; c++){
    int buf = c & 1;
    if (c+1 < 32){
      int cin = (c+1)*8;
      rv = *(const float4*)&Vk[(size_t)(cin+sci)*TPAD + t0 + scol*4];
      rw = *(const float4*)&Uk[(size_t)(cin+sci)*CIN + co0 + scol*4];
    }

    #pragma unroll
    for (int ci=0; ci<8; ci++){
      ull v[8];
      #pragma unroll
      for (int j=0;j<8;j++) v[j] = s_v[buf][ci][tg*8+j];
      ulonglong2 wa = *(const ulonglong2*)&s_w[buf][ci][og*4];
      ulonglong2 wb = *(const ulonglong2*)&s_w[buf][ci][og*4+2];
      #pragma unroll
      for (int j=0;j<8;j++){
        FMA2(acc[0][j], v[j], wa.x, acc[0][j]);
        FMA2(acc[1][j], v[j], wa.y, acc[1][j]);
        FMA2(acc[2][j], v[j], wb.x, acc[2][j]);
        FMA2(acc[3][j], v[j], wb.y, acc[3][j]);
      }
    }

    if (c+1 < 32){
      int nb = buf ^ 1;
      ull d0,d1,d2,d3;
      PACK2(d0,rv.x,rv.x); PACK2(d1,rv.y,rv.y);
      PACK2(d2,rv.z,rv.z); PACK2(d3,rv.w,rv.w);
      ull* dst = &s_v[nb][sci][scol*4];
      dst[0]=d0; dst[1]=d1; dst[2]=d2; dst[3]=d3;
      ull w0,w1;
      PACK2(w0,rw.x,rw.y); PACK2(w1,rw.z,rw.w);
      s_w[nb][sci][scol*2]   = w0;
      s_w[nb][sci][scol*2+1] = w1;
    }
    __syncthreads();
  }

  // epilogue: unpack co-pairs, store 2 co rows x 8 t per pair
  float* Mk = g_M + (size_t)kk*CIN*TPAD;
  #pragma unroll
  for (int p=0;p<4;p++){
    float lo[8], hi[8];
    #pragma unroll
    for (int j=0;j<8;j++) UNPACK2(lo[j], hi[j], acc[p][j]);
    int co = co0 + og*8 + 2*p;
    float* r0 = &Mk[(size_t)co*TPAD + t0 + tg*8];
    float* r1 = &Mk[(size_t)(co+1)*TPAD + t0 + tg*8];
    *(float4*)r0     = make_float4(lo[0],lo[1],lo[2],lo[3]);
    *(float4*)(r0+4) = make_float4(lo[4],lo[5],lo[6],lo[7]);
    *(float4*)r1     = make_float4(hi[0],hi[1],hi[2],hi[3]);
    *(float4*)(r1+4) = make_float4(hi[4],hi[5],hi[6],hi[7]);
  }
}

// ---------------------------------------------------------------------------
// Output transform: Y = A^T M A (6x6 -> 4x4), + bias + relu -> g_hid.
// ---------------------------------------------------------------------------
__global__ void k_wino_out(const float* __restrict__ b1){
  int t = blockIdx.x*256 + threadIdx.x;
  int co = blockIdx.y;
  if (t >= NTILES) return;
  float m6[6][6];
  #pragma unroll
  for (int k=0;k<36;k++)
    m6[k/6][k%6] = g_M[((size_t)k*CIN + co)*TPAD + t];
  float tmp[4][6];
  #pragma unroll
  for (int j=0;j<6;j++){
    float m0=m6[0][j],m1=m6[1][j],m2=m6[2][j],m3=m6[3][j],m4=m6[4][j],m5=m6[5][j];
    tmp[0][j] = m0+m1+m2+m3+m4;
    tmp[1][j] = m1-m2+2.f*m3-2.f*m4;
    tmp[2][j] = m1+m2+4.f*m3+4.f*m4;
    tmp[3][j] = m1-m2+8.f*m3-8.f*m4+m5;
  }
  int b = t / TPB, rr = t - b*TPB;
  int ty = rr / 38, tx = rr - ty*38;
  float bv = b1[co];
  float* hp = g_hid + ((size_t)b*CIN + co)*HW + (size_t)(ty*4)*WW + tx*4;
  #pragma unroll
  for (int i=0;i<4;i++){
    float r0=tmp[i][0],r1=tmp[i][1],r2=tmp[i][2],r3=tmp[i][3],r4=tmp[i][4],r5=tmp[i][5];
    float y0 = r0+r1+r2+r3+r4;
    float y1 = r1-r2+2.f*r3-2.f*r4;
    float y2 = r1+r2+4.f*r3+4.f*r4;
    float y3 = r1-r2+8.f*r3-8.f*r4+r5;
    float4 v;
    v.x = fmaxf(y0+bv, 0.f); v.y = fmaxf(y1+bv, 0.f);
    v.z = fmaxf(y2+bv, 0.f); v.w = fmaxf(y3+bv, 0.f);
    *(float4*)(hp + (size_t)i*WW) = v;
  }
}

// ---------------------------------------------------------------------------
// 1x1 conv 256->81 + bias, single pass over g_hid (read once).
// All 81 co accumulated at once (41 f32x2 pairs); weights staged per
// ci-chunk of 128 (42KB smem).
// ---------------------------------------------------------------------------
__global__ __launch_bounds__(256) void k_conv1x1(const float* __restrict__ w2,
                                                 const float* __restrict__ b2,
                                                 float* __restrict__ logits){
  __shared__ ull s_w[128][41];    // 41984 B
  int tid = threadIdx.x;
  int b  = blockIdx.y;
  int px = blockIdx.x*256 + tid;
  const float* hb = g_hid + (size_t)b*CIN*HW;
  float* ob = logits + (size_t)b*NC*HW;

  ull acc[41];
  #pragma unroll
  for (int j=0;j<41;j++){
    float ba = b2[2*j];
    float bb = (2*j+1 < 81) ? b2[2*j+1] : 0.f;
    PACK2(acc[j], ba, bb);
  }

  #pragma unroll 1
  for (int ch=0; ch<2; ch++){
    __syncthreads();
    #pragma unroll 1
    for (int i=tid; i<128*41; i+=256){
      int j = i % 41; int ci = i/41;
      int cia = ch*128 + ci;
      float wa = w2[(2*j)*CIN + cia];
      float wb = (2*j+1 < 81) ? w2[(2*j+1)*CIN + cia] : 0.f;
      ull d; PACK2(d, wa, wb);
      s_w[ci][j] = d;
    }
    __syncthreads();
    if (px < HW){
      #pragma unroll 2
      for (int ci=0; ci<128; ci++){
        float v = hb[(size_t)(ch*128+ci)*HW + px];
        ull vd; PACK2(vd, v, v);
        const ull* wp = s_w[ci];
        #pragma unroll
        for (int j=0;j<41;j++) FMA2(acc[j], vd, wp[j], acc[j]);
      }
    }
  }

  if (px < HW){
    #pragma unroll
    for (int j=0;j<41;j++){
      float a, c; UNPACK2(a, c, acc[j]);
      ob[(size_t)(2*j)*HW + px] = a;
      if (2*j+1 < 81) ob[(size_t)(2*j+1)*HW + px] = c;
    }
  }
}

// ---------------------------------------------------------------------------
__global__ void k_softmax(const float* __restrict__ logits){
  int i = blockIdx.x*256 + threadIdx.x;
  if (i >= BATCH*HW) return;
  int b = i / HW, px = i - b*HW;
  const float* lp = logits + (size_t)b*NC*HW + px;
  float M = -1e30f, best = -1e30f; int bi = 0;
  #pragma unroll 1
  for (int c=0;c<NC;c++){
    float v = lp[(size_t)c*HW];
    if (c < 80 && v > best){ best = v; bi = c; }
    M = fmaxf(M, v);
  }
  float s = 0.f;
  #pragma unroll 1
  for (int c=0;c<NC;c++) s += expf(lp[(size_t)c*HW] - M);
  g_pv[i] = expf(best - M) / s;
  g_cls[i] = bi;
}

__global__ void k_score(){
  int i = blockIdx.x*256 + threadIdx.x;
  if (i >= BATCH*HW) return;
  int b = i / HW, px = i - b*HW;
  int y = px / WW, xx = px - y*WW;
  float p = g_pv[i]; int cls = g_cls[i];
  bool flag = (p >= 1e-6f);
  if (flag){
    #pragma unroll
    for (int dy=-1; dy<=1; dy++){
      #pragma unroll
      for (int dx=-1; dx<=1; dx++){
        if (dy==0 && dx==0) continue;
        int ny = y+dy, nx = xx+dx;
        if ((unsigned)ny < HH && (unsigned)nx < WW){
          int j = b*HW + ny*WW + nx;
          if (g_cls[j]==cls && g_pv[j] > p) flag = false;
        }
      }
    }
  }
  float score = p + (flag ? 1.f : 0.f);
  g_keys[i] = (((ull)__float_as_uint(score))<<32)
              | (ull)(0xFFFFFFFFu - (unsigned)px);
}

__global__ void k_topk(){
  __shared__ ull s_red[256];
  int b = blockIdx.x, tid = threadIdx.x;
  ull* kb = g_keys + (size_t)b*HW;
  for (int it=0; it<NKEEP; it++){
    ull best = 0ull;
    for (int i=tid; i<HW; i+=256){
      ull k = kb[i];
      if (k > best) best = k;
    }
    s_red[tid] = best;
    __syncthreads();
    #pragma unroll
    for (int s=128; s>0; s>>=1){
      if (tid < s && s_red[tid+s] > s_red[tid]) s_red[tid] = s_red[tid+s];
      __syncthreads();
    }
    ull win = s_red[0];
    int wpx = (int)(0xFFFFFFFFu - (unsigned)(win & 0xFFFFFFFFull));
    if (tid==0){
      g_topk[b*NKEEP+it] = wpx;
      kb[wpx] = 0ull;
    }
    __syncthreads();
  }
}

__global__ void k_gather(const float* __restrict__ x, const float* __restrict__ pos,
                         float* __restrict__ out){
  int i = blockIdx.x*256 + threadIdx.x;
  if (i >= NOUT1) return;
  int k = i % NKEEP; int t = i / NKEEP; int c = t % CIN; int b = t / CIN;
  int px = g_topk[b*NKEEP + k];
  out[i]         = x[((size_t)b*CIN + c)*HW + px];
  out[NOUT1 + i] = pos[(size_t)c*HW + px];
}

// ---------------------------------------------------------------------------
extern "C" void kernel_launch(void* const* d_in, const int* in_sizes, int n_in,
                              void* d_out, int out_size){
  (void)in_sizes; (void)n_in; (void)out_size;
  const float* x   = (const float*)d_in[0];
  const float* pos = (const float*)d_in[1];
  const float* w1  = (const float*)d_in[2];
  const float* b1  = (const float*)d_in[3];
  const float* w2  = (const float*)d_in[4];
  const float* b2  = (const float*)d_in[5];
  float* out = (float*)d_out;
  float* logits = out + 2*NOUT1;

  k_wino_w  <<<(CIN*CIN+255)/256, 256>>>(w1);
  k_wino_in <<<dim3((NTILES+255)/256, CIN), 256>>>(x);
  k_gemm    <<<dim3(TPAD/128, CIN/128, 12), 256>>>(0);
  k_gemm    <<<dim3(TPAD/128, CIN/128, 12), 256>>>(12);
  k_gemm    <<<dim3(TPAD/128, CIN/128, 12), 256>>>(24);
  k_wino_out<<<dim3((NTILES+255)/256, CIN), 256>>>(b1);
  k_conv1x1 <<<dim3((HW+255)/256, BATCH), 256>>>(w2, b2, logits);
  k_softmax <<<(BATCH*HW+255)/256, 256>>>(logits);
  k_score   <<<(BATCH*HW+255)/256, 256>>>();
  k_topk    <<<BATCH, 256>>>();
  k_gather  <<<(NOUT1+255)/256, 256>>>(x, pos, out);
}

// round 10
// speedup vs baseline: 2.9411x; 1.0290x over previous
#include <cuda_runtime.h>
#include <math.h>

#define BATCH 8
#define CIN 256
#define HH 100
#define WW 152
#define HW 15200
#define NC 81
#define NKEEP 100
#define NOUT1 (BATCH*CIN*NKEEP)   /* 204800 */

#define NTILES 7600       /* 8 * 25 * 38 */
#define TPB    950        /* tiles per batch image */
#define TPAD   7680       /* padded tile count (60 * 128) */

typedef unsigned long long ull;

// ---------------------------------------------------------------------------
// Device scratch (allocation-free per harness rules)
// ---------------------------------------------------------------------------
__device__ float g_hid[(size_t)BATCH*CIN*HW];     // conv1 output (relu'd)
__device__ int   g_cls[BATCH*HW];
__device__ float g_pv[BATCH*HW];
__device__ ull   g_keys[BATCH*HW];
__device__ int   g_topk[BATCH*NKEEP];
// Winograd buffers
__device__ float g_U[(size_t)36*CIN*CIN];         // weight transform [k][ci][co]
__device__ float g_V[(size_t)36*CIN*TPAD];        // input transform  [k][ci][t]
__device__ float g_M[(size_t)36*CIN*TPAD];        // GEMM output      [k][co][t]

// Packed f32x2 helpers (SASS FFMA2 — exact IEEE fp32)
#define FMA2(d,a,b,c) asm("fma.rn.f32x2 %0, %1, %2, %3;" : "=l"(d) : "l"(a), "l"(b), "l"(c))
#define PACK2(d,lo,hi) asm("mov.b64 %0, {%1, %2};" : "=l"(d) : "f"(lo), "f"(hi))
#define UNPACK2(lo,hi,s) asm("mov.b64 {%0, %1}, %2;" : "=f"(lo), "=f"(hi) : "l"(s))

// ---------------------------------------------------------------------------
// Winograd F(4x4,3x3) weight transform: U = G g G^T, stored [k=36][ci][co]
// ---------------------------------------------------------------------------
__global__ void k_wino_w(const float* __restrict__ w1){
  int i = blockIdx.x*256 + threadIdx.x;
  if (i >= CIN*CIN) return;
  int co = i & 255, ci = i >> 8;
  float g[3][3];
  #pragma unroll
  for (int m=0;m<3;m++)
    #pragma unroll
    for (int j=0;j<3;j++)
      g[m][j] = w1[((size_t)(co*CIN+ci)*3+m)*3+j];
  float T1[6][3];
  #pragma unroll
  for (int j=0;j<3;j++){
    float g0=g[0][j], g1=g[1][j], g2=g[2][j];
    T1[0][j] = 0.25f*g0;
    T1[1][j] = (-g0-g1-g2)*(1.f/6.f);
    T1[2][j] = (-g0+g1-g2)*(1.f/6.f);
    T1[3][j] = g0*(1.f/24.f)+g1*(1.f/12.f)+g2*(1.f/6.f);
    T1[4][j] = g0*(1.f/24.f)-g1*(1.f/12.f)+g2*(1.f/6.f);
    T1[5][j] = g2;
  }
  #pragma unroll
  for (int r=0;r<6;r++){
    float t0=T1[r][0], t1=T1[r][1], t2=T1[r][2];
    float u[6];
    u[0] = 0.25f*t0;
    u[1] = (-t0-t1-t2)*(1.f/6.f);
    u[2] = (-t0+t1-t2)*(1.f/6.f);
    u[3] = t0*(1.f/24.f)+t1*(1.f/12.f)+t2*(1.f/6.f);
    u[4] = t0*(1.f/24.f)-t1*(1.f/12.f)+t2*(1.f/6.f);
    u[5] = t2;
    #pragma unroll
    for (int c=0;c<6;c++)
      g_U[((size_t)(r*6+c)*CIN + ci)*CIN + co] = u[c];
  }
}

// ---------------------------------------------------------------------------
// Input transform: V = B^T d B per (tile, ci). Stored [k][ci][t].
// ---------------------------------------------------------------------------
__global__ void k_wino_in(const float* __restrict__ x){
  int t = blockIdx.x*256 + threadIdx.x;
  int ci = blockIdx.y;
  if (t >= NTILES) return;
  int b = t / TPB, rr = t - b*TPB;
  int ty = rr / 38, tx = rr - ty*38;
  int y0 = ty*4 - 1, xg0 = tx*4 - 1;
  const float* xp = x + ((size_t)b*CIN + ci)*HW;
  float d[6][6];
  #pragma unroll
  for (int m=0;m<6;m++){
    int gy = y0 + m;
    bool ry = ((unsigned)gy < HH);
    #pragma unroll
    for (int j=0;j<6;j++){
      int gx = xg0 + j;
      d[m][j] = (ry && (unsigned)gx < WW) ? xp[gy*WW + gx] : 0.f;
    }
  }
  float tmp[6][6];
  #pragma unroll
  for (int j=0;j<6;j++){
    float d0=d[0][j],d1=d[1][j],d2=d[2][j],d3=d[3][j],d4=d[4][j],d5=d[5][j];
    tmp[0][j] = 4.f*d0 - 5.f*d2 + d4;
    tmp[1][j] = -4.f*d1 - 4.f*d2 + d3 + d4;
    tmp[2][j] =  4.f*d1 - 4.f*d2 - d3 + d4;
    tmp[3][j] = -2.f*d1 - d2 + 2.f*d3 + d4;
    tmp[4][j] =  2.f*d1 - d2 - 2.f*d3 + d4;
    tmp[5][j] =  4.f*d1 - 5.f*d3 + d5;
  }
  #pragma unroll
  for (int i=0;i<6;i++){
    float r0=tmp[i][0],r1=tmp[i][1],r2=tmp[i][2],r3=tmp[i][3],r4=tmp[i][4],r5=tmp[i][5];
    float v[6];
    v[0] = 4.f*r0 - 5.f*r2 + r4;
    v[1] = -4.f*r1 - 4.f*r2 + r3 + r4;
    v[2] =  4.f*r1 - 4.f*r2 - r3 + r4;
    v[3] = -2.f*r1 - r2 + 2.f*r3 + r4;
    v[4] =  2.f*r1 - r2 - 2.f*r3 + r4;
    v[5] =  4.f*r1 - 5.f*r3 + r5;
    #pragma unroll
    for (int c=0;c<6;c++)
      g_V[((size_t)(i*6+c)*CIN + ci)*TPAD + t] = v[c];
  }
}

// ---------------------------------------------------------------------------
// GEMM v3: M[k][co][t] = sum_ci U[k][ci][co] * V[k][ci][t].
// Block: 128co x 128t, ci chunks of 16, register-double-buffered (16 syncs).
// Thread: 8co (4 f32x2 pairs) x 8t -> 32 FFMA2 per ci.
// Data LDS via LDS.128 (adjacent t-pairs); weights via 2 LDS.128.
// og in low lane bits -> all inner LDS are broadcast-class.
// smem exactly 48KB static -> 2 blocks/SM.
// ---------------------------------------------------------------------------
__global__ __launch_bounds__(256,2) void k_gemm(){
  __shared__ __align__(16) ull s_v[2][16][128];   // (v,v) pairs, 32KB
  __shared__ __align__(16) ull s_w[2][16][64];    // (w0,w1) pairs, 16KB
  int tid = threadIdx.x;
  int t0  = blockIdx.x*128;
  int co0 = blockIdx.y*128;
  int kk  = blockIdx.z;
  int og = tid & 15;       // co group: 8 co (4 pairs)
  int tg = tid >> 4;       // t group: 8 t
  const float* Vk = g_V + (size_t)kk*CIN*TPAD;
  const float* Uk = g_U + (size_t)kk*CIN*CIN;

  ull acc[4][8];
  #pragma unroll
  for (int p=0;p<4;p++)
    #pragma unroll
    for (int j=0;j<8;j++) PACK2(acc[p][j], 0.f, 0.f);

  int sci  = tid >> 5;       // staging row 0..7 (two rows per thread: +8)
  int scol = tid & 31;       // staging col group

  // prefetch + store chunk 0 (16 ci rows: each thread stages rows sci, sci+8)
  float4 rv0 = *(const float4*)&Vk[(size_t)sci*TPAD + t0 + scol*4];
  float4 rv1 = *(const float4*)&Vk[(size_t)(sci+8)*TPAD + t0 + scol*4];
  float4 rw0 = *(const float4*)&Uk[(size_t)sci*CIN + co0 + scol*4];
  float4 rw1 = *(const float4*)&Uk[(size_t)(sci+8)*CIN + co0 + scol*4];
  {
    ull d0,d1,d2,d3;
    PACK2(d0,rv0.x,rv0.x); PACK2(d1,rv0.y,rv0.y);
    PACK2(d2,rv0.z,rv0.z); PACK2(d3,rv0.w,rv0.w);
    ull* dst = &s_v[0][sci][scol*4];
    dst[0]=d0; dst[1]=d1; dst[2]=d2; dst[3]=d3;
    PACK2(d0,rv1.x,rv1.x); PACK2(d1,rv1.y,rv1.y);
    PACK2(d2,rv1.z,rv1.z); PACK2(d3,rv1.w,rv1.w);
    dst = &s_v[0][sci+8][scol*4];
    dst[0]=d0; dst[1]=d1; dst[2]=d2; dst[3]=d3;
    ull w0,w1;
    PACK2(w0,rw0.x,rw0.y); PACK2(w1,rw0.z,rw0.w);
    s_w[0][sci][scol*2]   = w0;
    s_w[0][sci][scol*2+1] = w1;
    PACK2(w0,rw1.x,rw1.y); PACK2(w1,rw1.z,rw1.w);
    s_w[0][sci+8][scol*2]   = w0;
    s_w[0][sci+8][scol*2+1] = w1;
  }
  __syncthreads();

  #pragma unroll 1
  for (int c=0; c<16; c++){
    int buf = c & 1;
    if (c+1 < 16){
      int cin = (c+1)*16;
      rv0 = *(const float4*)&Vk[(size_t)(cin+sci)*TPAD + t0 + scol*4];
      rv1 = *(const float4*)&Vk[(size_t)(cin+sci+8)*TPAD + t0 + scol*4];
      rw0 = *(const float4*)&Uk[(size_t)(cin+sci)*CIN + co0 + scol*4];
      rw1 = *(const float4*)&Uk[(size_t)(cin+sci+8)*CIN + co0 + scol*4];
    }

    #pragma unroll 8
    for (int ci=0; ci<16; ci++){
      // data: 4 LDS.128 (adjacent t-pairs), broadcast-class
      ulonglong2 v01 = *(const ulonglong2*)&s_v[buf][ci][tg*8];
      ulonglong2 v23 = *(const ulonglong2*)&s_v[buf][ci][tg*8+2];
      ulonglong2 v45 = *(const ulonglong2*)&s_v[buf][ci][tg*8+4];
      ulonglong2 v67 = *(const ulonglong2*)&s_v[buf][ci][tg*8+6];
      ulonglong2 wa = *(const ulonglong2*)&s_w[buf][ci][og*4];
      ulonglong2 wb = *(const ulonglong2*)&s_w[buf][ci][og*4+2];
      ull v[8] = {v01.x, v01.y, v23.x, v23.y, v45.x, v45.y, v67.x, v67.y};
      #pragma unroll
      for (int j=0;j<8;j++){
        FMA2(acc[0][j], v[j], wa.x, acc[0][j]);
        FMA2(acc[1][j], v[j], wa.y, acc[1][j]);
        FMA2(acc[2][j], v[j], wb.x, acc[2][j]);
        FMA2(acc[3][j], v[j], wb.y, acc[3][j]);
      }
    }

    if (c+1 < 16){
      int nb = buf ^ 1;
      ull d0,d1,d2,d3;
      PACK2(d0,rv0.x,rv0.x); PACK2(d1,rv0.y,rv0.y);
      PACK2(d2,rv0.z,rv0.z); PACK2(d3,rv0.w,rv0.w);
      ull* dst = &s_v[nb][sci][scol*4];
      dst[0]=d0; dst[1]=d1; dst[2]=d2; dst[3]=d3;
      PACK2(d0,rv1.x,rv1.x); PACK2(d1,rv1.y,rv1.y);
      PACK2(d2,rv1.z,rv1.z); PACK2(d3,rv1.w,rv1.w);
      dst = &s_v[nb][sci+8][scol*4];
      dst[0]=d0; dst[1]=d1; dst[2]=d2; dst[3]=d3;
      ull w0,w1;
      PACK2(w0,rw0.x,rw0.y); PACK2(w1,rw0.z,rw0.w);
      s_w[nb][sci][scol*2]   = w0;
      s_w[nb][sci][scol*2+1] = w1;
      PACK2(w0,rw1.x,rw1.y); PACK2(w1,rw1.z,rw1.w);
      s_w[nb][sci+8][scol*2]   = w0;
      s_w[nb][sci+8][scol*2+1] = w1;
    }
    __syncthreads();
  }

  // epilogue: unpack co-pairs, store 2 co rows x 8 t per pair
  float* Mk = g_M + (size_t)kk*CIN*TPAD;
  #pragma unroll
  for (int p=0;p<4;p++){
    float lo[8], hi[8];
    #pragma unroll
    for (int j=0;j<8;j++) UNPACK2(lo[j], hi[j], acc[p][j]);
    int co = co0 + og*8 + 2*p;
    float* r0 = &Mk[(size_t)co*TPAD + t0 + tg*8];
    float* r1 = &Mk[(size_t)(co+1)*TPAD + t0 + tg*8];
    *(float4*)r0     = make_float4(lo[0],lo[1],lo[2],lo[3]);
    *(float4*)(r0+4) = make_float4(lo[4],lo[5],lo[6],lo[7]);
    *(float4*)r1     = make_float4(hi[0],hi[1],hi[2],hi[3]);
    *(float4*)(r1+4) = make_float4(hi[4],hi[5],hi[6],hi[7]);
  }
}

// ---------------------------------------------------------------------------
// Output transform: Y = A^T M A (6x6 -> 4x4), + bias + relu -> g_hid.
// ---------------------------------------------------------------------------
__global__ void k_wino_out(const float* __restrict__ b1){
  int t = blockIdx.x*256 + threadIdx.x;
  int co = blockIdx.y;
  if (t >= NTILES) return;
  float m6[6][6];
  #pragma unroll
  for (int k=0;k<36;k++)
    m6[k/6][k%6] = g_M[((size_t)k*CIN + co)*TPAD + t];
  float tmp[4][6];
  #pragma unroll
  for (int j=0;j<6;j++){
    float m0=m6[0][j],m1=m6[1][j],m2=m6[2][j],m3=m6[3][j],m4=m6[4][j],m5=m6[5][j];
    tmp[0][j] = m0+m1+m2+m3+m4;
    tmp[1][j] = m1-m2+2.f*m3-2.f*m4;
    tmp[2][j] = m1+m2+4.f*m3+4.f*m4;
    tmp[3][j] = m1-m2+8.f*m3-8.f*m4+m5;
  }
  int b = t / TPB, rr = t - b*TPB;
  int ty = rr / 38, tx = rr - ty*38;
  float bv = b1[co];
  float* hp = g_hid + ((size_t)b*CIN + co)*HW + (size_t)(ty*4)*WW + tx*4;
  #pragma unroll
  for (int i=0;i<4;i++){
    float r0=tmp[i][0],r1=tmp[i][1],r2=tmp[i][2],r3=tmp[i][3],r4=tmp[i][4],r5=tmp[i][5];
    float y0 = r0+r1+r2+r3+r4;
    float y1 = r1-r2+2.f*r3-2.f*r4;
    float y2 = r1+r2+4.f*r3+4.f*r4;
    float y3 = r1-r2+8.f*r3-8.f*r4+r5;
    float4 v;
    v.x = fmaxf(y0+bv, 0.f); v.y = fmaxf(y1+bv, 0.f);
    v.z = fmaxf(y2+bv, 0.f); v.w = fmaxf(y3+bv, 0.f);
    *(float4*)(hp + (size_t)i*WW) = v;
  }
}

// ---------------------------------------------------------------------------
// 1x1 conv 256->81 + bias, single pass over g_hid (read once).
// ---------------------------------------------------------------------------
__global__ __launch_bounds__(256) void k_conv1x1(const float* __restrict__ w2,
                                                 const float* __restrict__ b2,
                                                 float* __restrict__ logits){
  __shared__ ull s_w[128][41];    // 41984 B
  int tid = threadIdx.x;
  int b  = blockIdx.y;
  int px = blockIdx.x*256 + tid;
  const float* hb = g_hid + (size_t)b*CIN*HW;
  float* ob = logits + (size_t)b*NC*HW;

  ull acc[41];
  #pragma unroll
  for (int j=0;j<41;j++){
    float ba = b2[2*j];
    float bb = (2*j+1 < 81) ? b2[2*j+1] : 0.f;
    PACK2(acc[j], ba, bb);
  }

  #pragma unroll 1
  for (int ch=0; ch<2; ch++){
    __syncthreads();
    #pragma unroll 1
    for (int i=tid; i<128*41; i+=256){
      int j = i % 41; int ci = i/41;
      int cia = ch*128 + ci;
      float wa = w2[(2*j)*CIN + cia];
      float wb = (2*j+1 < 81) ? w2[(2*j+1)*CIN + cia] : 0.f;
      ull d; PACK2(d, wa, wb);
      s_w[ci][j] = d;
    }
    __syncthreads();
    if (px < HW){
      #pragma unroll 2
      for (int ci=0; ci<128; ci++){
        float v = hb[(size_t)(ch*128+ci)*HW + px];
        ull vd; PACK2(vd, v, v);
        const ull* wp = s_w[ci];
        #pragma unroll
        for (int j=0;j<41;j++) FMA2(acc[j], vd, wp[j], acc[j]);
      }
    }
  }

  if (px < HW){
    #pragma unroll
    for (int j=0;j<41;j++){
      float a, c; UNPACK2(a, c, acc[j]);
      ob[(size_t)(2*j)*HW + px] = a;
      if (2*j+1 < 81) ob[(size_t)(2*j+1)*HW + px] = c;
    }
  }
}

// ---------------------------------------------------------------------------
__global__ void k_softmax(const float* __restrict__ logits){
  int i = blockIdx.x*256 + threadIdx.x;
  if (i >= BATCH*HW) return;
  int b = i / HW, px = i - b*HW;
  const float* lp = logits + (size_t)b*NC*HW + px;
  float M = -1e30f, best = -1e30f; int bi = 0;
  #pragma unroll 1
  for (int c=0;c<NC;c++){
    float v = lp[(size_t)c*HW];
    if (c < 80 && v > best){ best = v; bi = c; }
    M = fmaxf(M, v);
  }
  float s = 0.f;
  #pragma unroll 1
  for (int c=0;c<NC;c++) s += expf(lp[(size_t)c*HW] - M);
  g_pv[i] = expf(best - M) / s;
  g_cls[i] = bi;
}

__global__ void k_score(){
  int i = blockIdx.x*256 + threadIdx.x;
  if (i >= BATCH*HW) return;
  int b = i / HW, px = i - b*HW;
  int y = px / WW, xx = px - y*WW;
  float p = g_pv[i]; int cls = g_cls[i];
  bool flag = (p >= 1e-6f);
  if (flag){
    #pragma unroll
    for (int dy=-1; dy<=1; dy++){
      #pragma unroll
      for (int dx=-1; dx<=1; dx++){
        if (dy==0 && dx==0) continue;
        int ny = y+dy, nx = xx+dx;
        if ((unsigned)ny < HH && (unsigned)nx < WW){
          int j = b*HW + ny*WW + nx;
          if (g_cls[j]==cls && g_pv[j] > p) flag = false;
        }
      }
    }
  }
  float score = p + (flag ? 1.f : 0.f);
  g_keys[i] = (((ull)__float_as_uint(score))<<32)
              | (ull)(0xFFFFFFFFu - (unsigned)px);
}

__global__ void k_topk(){
  __shared__ ull s_red[256];
  int b = blockIdx.x, tid = threadIdx.x;
  ull* kb = g_keys + (size_t)b*HW;
  for (int it=0; it<NKEEP; it++){
    ull best = 0ull;
    for (int i=tid; i<HW; i+=256){
      ull k = kb[i];
      if (k > best) best = k;
    }
    s_red[tid] = best;
    __syncthreads();
    #pragma unroll
    for (int s=128; s>0; s>>=1){
      if (tid < s && s_red[tid+s] > s_red[tid]) s_red[tid] = s_red[tid+s];
      __syncthreads();
    }
    ull win = s_red[0];
    int wpx = (int)(0xFFFFFFFFu - (unsigned)(win & 0xFFFFFFFFull));
    if (tid==0){
      g_topk[b*NKEEP+it] = wpx;
      kb[wpx] = 0ull;
    }
    __syncthreads();
  }
}

__global__ void k_gather(const float* __restrict__ x, const float* __restrict__ pos,
                         float* __restrict__ out){
  int i = blockIdx.x*256 + threadIdx.x;
  if (i >= NOUT1) return;
  int k = i % NKEEP; int t = i / NKEEP; int c = t % CIN; int b = t / CIN;
  int px = g_topk[b*NKEEP + k];
  out[i]         = x[((size_t)b*CIN + c)*HW + px];
  out[NOUT1 + i] = pos[(size_t)c*HW + px];
}

// ---------------------------------------------------------------------------
extern "C" void kernel_launch(void* const* d_in, const int* in_sizes, int n_in,
                              void* d_out, int out_size){
  (void)in_sizes; (void)n_in; (void)out_size;
  const float* x   = (const float*)d_in[0];
  const float* pos = (const float*)d_in[1];
  const float* w1  = (const float*)d_in[2];
  const float* b1  = (const float*)d_in[3];
  const float* w2  = (const float*)d_in[4];
  const float* b2  = (const float*)d_in[5];
  float* out = (float*)d_out;
  float* logits = out + 2*NOUT1;

  k_wino_w  <<<(CIN*CIN+255)/256, 256>>>(w1);
  k_wino_in <<<dim3((NTILES+255)/256, CIN), 256>>>(x);
  k_gemm    <<<dim3(TPAD/128, CIN/128, 36), 256>>>();
  k_wino_out<<<dim3((NTILES+255)/256, CIN), 256>>>(b1);
  k_conv1x1 <<<dim3((HW+255)/256, BATCH), 256>>>(w2, b2, logits);
  k_softmax <<<(BATCH*HW+255)/256, 256>>>(logits);
  k_score   <<<(BATCH*HW+255)/256, 256>>>();
  k_topk    <<<BATCH, 256>>>();
  k_gather  <<<(NOUT1+255)/256, 256>>>(x, pos, out);
}

// round 11
// speedup vs baseline: 3.1703x; 1.0779x over previous
#include <cuda_runtime.h>
#include <math.h>

#define BATCH 8
#define CIN 256
#define HH 100
#define WW 152
#define HW 15200
#define NC 81
#define NKEEP 100
#define NOUT1 (BATCH*CIN*NKEEP)   /* 204800 */

#define NTILES 7600       /* 8 * 25 * 38 */
#define TPB    950        /* tiles per batch image */
#define TPAD   7680       /* padded tile count (60 * 128) */

typedef unsigned long long ull;

// ---------------------------------------------------------------------------
// Device scratch (allocation-free per harness rules)
// ---------------------------------------------------------------------------
__device__ float g_hid[(size_t)BATCH*CIN*HW];     // conv1 output (relu'd)
__device__ int   g_cls[BATCH*HW];
__device__ float g_pv[BATCH*HW];
__device__ ull   g_keys[BATCH*HW];
__device__ int   g_topk[BATCH*NKEEP];
// Winograd buffers
__device__ float g_U[(size_t)36*CIN*CIN];         // weight transform [k][ci][co]
__device__ float g_V[(size_t)36*CIN*TPAD];        // input transform  [k][ci][t]
__device__ float g_M[(size_t)36*CIN*TPAD];        // GEMM output      [k][co][t]

// Packed f32x2 helpers (SASS FFMA2 — exact IEEE fp32)
#define FMA2(d,a,b,c) asm("fma.rn.f32x2 %0, %1, %2, %3;" : "=l"(d) : "l"(a), "l"(b), "l"(c))
#define PACK2(d,lo,hi) asm("mov.b64 %0, {%1, %2};" : "=l"(d) : "f"(lo), "f"(hi))
#define UNPACK2(lo,hi,s) asm("mov.b64 {%0, %1}, %2;" : "=f"(lo), "=f"(hi) : "l"(s))

// ---------------------------------------------------------------------------
// Winograd F(4x4,3x3) weight transform: U = G g G^T, stored [k=36][ci][co]
// ---------------------------------------------------------------------------
__global__ void k_wino_w(const float* __restrict__ w1){
  int i = blockIdx.x*256 + threadIdx.x;
  if (i >= CIN*CIN) return;
  int co = i & 255, ci = i >> 8;
  float g[3][3];
  #pragma unroll
  for (int m=0;m<3;m++)
    #pragma unroll
    for (int j=0;j<3;j++)
      g[m][j] = w1[((size_t)(co*CIN+ci)*3+m)*3+j];
  float T1[6][3];
  #pragma unroll
  for (int j=0;j<3;j++){
    float g0=g[0][j], g1=g[1][j], g2=g[2][j];
    T1[0][j] = 0.25f*g0;
    T1[1][j] = (-g0-g1-g2)*(1.f/6.f);
    T1[2][j] = (-g0+g1-g2)*(1.f/6.f);
    T1[3][j] = g0*(1.f/24.f)+g1*(1.f/12.f)+g2*(1.f/6.f);
    T1[4][j] = g0*(1.f/24.f)-g1*(1.f/12.f)+g2*(1.f/6.f);
    T1[5][j] = g2;
  }
  #pragma unroll
  for (int r=0;r<6;r++){
    float t0=T1[r][0], t1=T1[r][1], t2=T1[r][2];
    float u[6];
    u[0] = 0.25f*t0;
    u[1] = (-t0-t1-t2)*(1.f/6.f);
    u[2] = (-t0+t1-t2)*(1.f/6.f);
    u[3] = t0*(1.f/24.f)+t1*(1.f/12.f)+t2*(1.f/6.f);
    u[4] = t0*(1.f/24.f)-t1*(1.f/12.f)+t2*(1.f/6.f);
    u[5] = t2;
    #pragma unroll
    for (int c=0;c<6;c++)
      g_U[((size_t)(r*6+c)*CIN + ci)*CIN + co] = u[c];
  }
}

// ---------------------------------------------------------------------------
// Input transform: V = B^T d B per (tile, ci). Stored [k][ci][t].
// ---------------------------------------------------------------------------
__global__ void k_wino_in(const float* __restrict__ x){
  int t = blockIdx.x*256 + threadIdx.x;
  int ci = blockIdx.y;
  if (t >= NTILES) return;
  int b = t / TPB, rr = t - b*TPB;
  int ty = rr / 38, tx = rr - ty*38;
  int y0 = ty*4 - 1, xg0 = tx*4 - 1;
  const float* xp = x + ((size_t)b*CIN + ci)*HW;
  float d[6][6];
  #pragma unroll
  for (int m=0;m<6;m++){
    int gy = y0 + m;
    bool ry = ((unsigned)gy < HH);
    #pragma unroll
    for (int j=0;j<6;j++){
      int gx = xg0 + j;
      d[m][j] = (ry && (unsigned)gx < WW) ? xp[gy*WW + gx] : 0.f;
    }
  }
  float tmp[6][6];
  #pragma unroll
  for (int j=0;j<6;j++){
    float d0=d[0][j],d1=d[1][j],d2=d[2][j],d3=d[3][j],d4=d[4][j],d5=d[5][j];
    tmp[0][j] = 4.f*d0 - 5.f*d2 + d4;
    tmp[1][j] = -4.f*d1 - 4.f*d2 + d3 + d4;
    tmp[2][j] =  4.f*d1 - 4.f*d2 - d3 + d4;
    tmp[3][j] = -2.f*d1 - d2 + 2.f*d3 + d4;
    tmp[4][j] =  2.f*d1 - d2 - 2.f*d3 + d4;
    tmp[5][j] =  4.f*d1 - 5.f*d3 + d5;
  }
  #pragma unroll
  for (int i=0;i<6;i++){
    float r0=tmp[i][0],r1=tmp[i][1],r2=tmp[i][2],r3=tmp[i][3],r4=tmp[i][4],r5=tmp[i][5];
    float v[6];
    v[0] = 4.f*r0 - 5.f*r2 + r4;
    v[1] = -4.f*r1 - 4.f*r2 + r3 + r4;
    v[2] =  4.f*r1 - 4.f*r2 - r3 + r4;
    v[3] = -2.f*r1 - r2 + 2.f*r3 + r4;
    v[4] =  2.f*r1 - r2 - 2.f*r3 + r4;
    v[5] =  4.f*r1 - 5.f*r3 + r5;
    #pragma unroll
    for (int c=0;c<6;c++)
      g_V[((size_t)(i*6+c)*CIN + ci)*TPAD + t] = v[c];
  }
}

// ---------------------------------------------------------------------------
// GEMM v3 (unchanged from R10 win): 128co x 128t, ci chunks of 16.
// ---------------------------------------------------------------------------
__global__ __launch_bounds__(256,2) void k_gemm(){
  __shared__ __align__(16) ull s_v[2][16][128];   // (v,v) pairs, 32KB
  __shared__ __align__(16) ull s_w[2][16][64];    // (w0,w1) pairs, 16KB
  int tid = threadIdx.x;
  int t0  = blockIdx.x*128;
  int co0 = blockIdx.y*128;
  int kk  = blockIdx.z;
  int og = tid & 15;       // co group: 8 co (4 pairs)
  int tg = tid >> 4;       // t group: 8 t
  const float* Vk = g_V + (size_t)kk*CIN*TPAD;
  const float* Uk = g_U + (size_t)kk*CIN*CIN;

  ull acc[4][8];
  #pragma unroll
  for (int p=0;p<4;p++)
    #pragma unroll
    for (int j=0;j<8;j++) PACK2(acc[p][j], 0.f, 0.f);

  int sci  = tid >> 5;
  int scol = tid & 31;

  float4 rv0 = *(const float4*)&Vk[(size_t)sci*TPAD + t0 + scol*4];
  float4 rv1 = *(const float4*)&Vk[(size_t)(sci+8)*TPAD + t0 + scol*4];
  float4 rw0 = *(const float4*)&Uk[(size_t)sci*CIN + co0 + scol*4];
  float4 rw1 = *(const float4*)&Uk[(size_t)(sci+8)*CIN + co0 + scol*4];
  {
    ull d0,d1,d2,d3;
    PACK2(d0,rv0.x,rv0.x); PACK2(d1,rv0.y,rv0.y);
    PACK2(d2,rv0.z,rv0.z); PACK2(d3,rv0.w,rv0.w);
    ull* dst = &s_v[0][sci][scol*4];
    dst[0]=d0; dst[1]=d1; dst[2]=d2; dst[3]=d3;
    PACK2(d0,rv1.x,rv1.x); PACK2(d1,rv1.y,rv1.y);
    PACK2(d2,rv1.z,rv1.z); PACK2(d3,rv1.w,rv1.w);
    dst = &s_v[0][sci+8][scol*4];
    dst[0]=d0; dst[1]=d1; dst[2]=d2; dst[3]=d3;
    ull w0,w1;
    PACK2(w0,rw0.x,rw0.y); PACK2(w1,rw0.z,rw0.w);
    s_w[0][sci][scol*2]   = w0;
    s_w[0][sci][scol*2+1] = w1;
    PACK2(w0,rw1.x,rw1.y); PACK2(w1,rw1.z,rw1.w);
    s_w[0][sci+8][scol*2]   = w0;
    s_w[0][sci+8][scol*2+1] = w1;
  }
  __syncthreads();

  #pragma unroll 1
  for (int c=0; c<16; c++){
    int buf = c & 1;
    if (c+1 < 16){
      int cin = (c+1)*16;
      rv0 = *(const float4*)&Vk[(size_t)(cin+sci)*TPAD + t0 + scol*4];
      rv1 = *(const float4*)&Vk[(size_t)(cin+sci+8)*TPAD + t0 + scol*4];
      rw0 = *(const float4*)&Uk[(size_t)(cin+sci)*CIN + co0 + scol*4];
      rw1 = *(const float4*)&Uk[(size_t)(cin+sci+8)*CIN + co0 + scol*4];
    }

    #pragma unroll 8
    for (int ci=0; ci<16; ci++){
      ulonglong2 v01 = *(const ulonglong2*)&s_v[buf][ci][tg*8];
      ulonglong2 v23 = *(const ulonglong2*)&s_v[buf][ci][tg*8+2];
      ulonglong2 v45 = *(const ulonglong2*)&s_v[buf][ci][tg*8+4];
      ulonglong2 v67 = *(const ulonglong2*)&s_v[buf][ci][tg*8+6];
      ulonglong2 wa = *(const ulonglong2*)&s_w[buf][ci][og*4];
      ulonglong2 wb = *(const ulonglong2*)&s_w[buf][ci][og*4+2];
      ull v[8] = {v01.x, v01.y, v23.x, v23.y, v45.x, v45.y, v67.x, v67.y};
      #pragma unroll
      for (int j=0;j<8;j++){
        FMA2(acc[0][j], v[j], wa.x, acc[0][j]);
        FMA2(acc[1][j], v[j], wa.y, acc[1][j]);
        FMA2(acc[2][j], v[j], wb.x, acc[2][j]);
        FMA2(acc[3][j], v[j], wb.y, acc[3][j]);
      }
    }

    if (c+1 < 16){
      int nb = buf ^ 1;
      ull d0,d1,d2,d3;
      PACK2(d0,rv0.x,rv0.x); PACK2(d1,rv0.y,rv0.y);
      PACK2(d2,rv0.z,rv0.z); PACK2(d3,rv0.w,rv0.w);
      ull* dst = &s_v[nb][sci][scol*4];
      dst[0]=d0; dst[1]=d1; dst[2]=d2; dst[3]=d3;
      PACK2(d0,rv1.x,rv1.x); PACK2(d1,rv1.y,rv1.y);
      PACK2(d2,rv1.z,rv1.z); PACK2(d3,rv1.w,rv1.w);
      dst = &s_v[nb][sci+8][scol*4];
      dst[0]=d0; dst[1]=d1; dst[2]=d2; dst[3]=d3;
      ull w0,w1;
      PACK2(w0,rw0.x,rw0.y); PACK2(w1,rw0.z,rw0.w);
      s_w[nb][sci][scol*2]   = w0;
      s_w[nb][sci][scol*2+1] = w1;
      PACK2(w0,rw1.x,rw1.y); PACK2(w1,rw1.z,rw1.w);
      s_w[nb][sci+8][scol*2]   = w0;
      s_w[nb][sci+8][scol*2+1] = w1;
    }
    __syncthreads();
  }

  float* Mk = g_M + (size_t)kk*CIN*TPAD;
  #pragma unroll
  for (int p=0;p<4;p++){
    float lo[8], hi[8];
    #pragma unroll
    for (int j=0;j<8;j++) UNPACK2(lo[j], hi[j], acc[p][j]);
    int co = co0 + og*8 + 2*p;
    float* r0 = &Mk[(size_t)co*TPAD + t0 + tg*8];
    float* r1 = &Mk[(size_t)(co+1)*TPAD + t0 + tg*8];
    *(float4*)r0     = make_float4(lo[0],lo[1],lo[2],lo[3]);
    *(float4*)(r0+4) = make_float4(lo[4],lo[5],lo[6],lo[7]);
    *(float4*)r1     = make_float4(hi[0],hi[1],hi[2],hi[3]);
    *(float4*)(r1+4) = make_float4(hi[4],hi[5],hi[6],hi[7]);
  }
}

// ---------------------------------------------------------------------------
// Output transform: Y = A^T M A (6x6 -> 4x4), + bias + relu -> g_hid.
// ---------------------------------------------------------------------------
__global__ void k_wino_out(const float* __restrict__ b1){
  int t = blockIdx.x*256 + threadIdx.x;
  int co = blockIdx.y;
  if (t >= NTILES) return;
  float m6[6][6];
  #pragma unroll
  for (int k=0;k<36;k++)
    m6[k/6][k%6] = g_M[((size_t)k*CIN + co)*TPAD + t];
  float tmp[4][6];
  #pragma unroll
  for (int j=0;j<6;j++){
    float m0=m6[0][j],m1=m6[1][j],m2=m6[2][j],m3=m6[3][j],m4=m6[4][j],m5=m6[5][j];
    tmp[0][j] = m0+m1+m2+m3+m4;
    tmp[1][j] = m1-m2+2.f*m3-2.f*m4;
    tmp[2][j] = m1+m2+4.f*m3+4.f*m4;
    tmp[3][j] = m1-m2+8.f*m3-8.f*m4+m5;
  }
  int b = t / TPB, rr = t - b*TPB;
  int ty = rr / 38, tx = rr - ty*38;
  float bv = b1[co];
  float* hp = g_hid + ((size_t)b*CIN + co)*HW + (size_t)(ty*4)*WW + tx*4;
  #pragma unroll
  for (int i=0;i<4;i++){
    float r0=tmp[i][0],r1=tmp[i][1],r2=tmp[i][2],r3=tmp[i][3],r4=tmp[i][4],r5=tmp[i][5];
    float y0 = r0+r1+r2+r3+r4;
    float y1 = r1-r2+2.f*r3-2.f*r4;
    float y2 = r1+r2+4.f*r3+4.f*r4;
    float y3 = r1-r2+8.f*r3-8.f*r4+r5;
    float4 v;
    v.x = fmaxf(y0+bv, 0.f); v.y = fmaxf(y1+bv, 0.f);
    v.z = fmaxf(y2+bv, 0.f); v.w = fmaxf(y3+bv, 0.f);
    *(float4*)(hp + (size_t)i*WW) = v;
  }
}

// ---------------------------------------------------------------------------
// FUSED 1x1 conv + bias + softmax/argmax. Writes logits AND g_pv/g_cls —
// logits never re-read from DRAM. Math identical to conv1x1 + k_softmax.
// ---------------------------------------------------------------------------
__global__ __launch_bounds__(256) void k_conv1x1s(const float* __restrict__ w2,
                                                  const float* __restrict__ b2,
                                                  float* __restrict__ logits){
  __shared__ ull s_w[128][41];    // 41984 B
  int tid = threadIdx.x;
  int b  = blockIdx.y;
  int px = blockIdx.x*256 + tid;
  const float* hb = g_hid + (size_t)b*CIN*HW;
  float* ob = logits + (size_t)b*NC*HW;

  ull acc[41];
  #pragma unroll
  for (int j=0;j<41;j++){
    float ba = b2[2*j];
    float bb = (2*j+1 < 81) ? b2[2*j+1] : 0.f;
    PACK2(acc[j], ba, bb);
  }

  #pragma unroll 1
  for (int ch=0; ch<2; ch++){
    __syncthreads();
    #pragma unroll 1
    for (int i=tid; i<128*41; i+=256){
      int j = i % 41; int ci = i/41;
      int cia = ch*128 + ci;
      float wa = w2[(2*j)*CIN + cia];
      float wb = (2*j+1 < 81) ? w2[(2*j+1)*CIN + cia] : 0.f;
      ull d; PACK2(d, wa, wb);
      s_w[ci][j] = d;
    }
    __syncthreads();
    if (px < HW){
      #pragma unroll 2
      for (int ci=0; ci<128; ci++){
        float v = hb[(size_t)(ch*128+ci)*HW + px];
        ull vd; PACK2(vd, v, v);
        const ull* wp = s_w[ci];
        #pragma unroll
        for (int j=0;j<41;j++) FMA2(acc[j], vd, wp[j], acc[j]);
      }
    }
  }

  if (px < HW){
    // write logits + find M (max over 81) and argmax over first 80 (first wins)
    float M = -1e30f, best = -1e30f; int bi = 0;
    #pragma unroll
    for (int j=0;j<41;j++){
      float a, c; UNPACK2(a, c, acc[j]);
      ob[(size_t)(2*j)*HW + px] = a;
      if (2*j < 80 && a > best){ best = a; bi = 2*j; }
      M = fmaxf(M, a);
      if (2*j+1 < 81){
        ob[(size_t)(2*j+1)*HW + px] = c;
        if (2*j+1 < 80 && c > best){ best = c; bi = 2*j+1; }
        M = fmaxf(M, c);
      }
    }
    // tie rule: argmax is first index attaining the max. Our loop is ascending
    // with strict '>' so first-wins holds. (index 80 excluded, as reference.)
    float s = 0.f;
    #pragma unroll
    for (int j=0;j<41;j++){
      float a, c; UNPACK2(a, c, acc[j]);
      s += expf(a - M);
      if (2*j+1 < 81) s += expf(c - M);
    }
    int gi = b*HW + px;
    g_pv[gi]  = expf(best - M) / s;
    g_cls[gi] = bi;
  }
}

// ---------------------------------------------------------------------------
// score = p + 1 if local max (same-class strict neighbors) — unchanged.
// ---------------------------------------------------------------------------
__global__ void k_score(){
  int i = blockIdx.x*256 + threadIdx.x;
  if (i >= BATCH*HW) return;
  int b = i / HW, px = i - b*HW;
  int y = px / WW, xx = px - y*WW;
  float p = g_pv[i]; int cls = g_cls[i];
  bool flag = (p >= 1e-6f);
  if (flag){
    #pragma unroll
    for (int dy=-1; dy<=1; dy++){
      #pragma unroll
      for (int dx=-1; dx<=1; dx++){
        if (dy==0 && dx==0) continue;
        int ny = y+dy, nx = xx+dx;
        if ((unsigned)ny < HH && (unsigned)nx < WW){
          int j = b*HW + ny*WW + nx;
          if (g_cls[j]==cls && g_pv[j] > p) flag = false;
        }
      }
    }
  }
  float score = p + (flag ? 1.f : 0.f);
  g_keys[i] = (((ull)__float_as_uint(score))<<32)
              | (ull)(0xFFFFFFFFu - (unsigned)px);
}

// ---------------------------------------------------------------------------
// Top-100 v2: per-thread stripe maxima cached in smem; per iteration a
// shfl argmax (3 syncs) + cooperative rebuild of only the winner's stripe.
// Exact lax.top_k ordering (same keys as before).
// ---------------------------------------------------------------------------
__global__ void k_topk(){
  __shared__ ull s_val[256];
  __shared__ ull s_wv[8];
  __shared__ int s_wi[8];
  __shared__ int s_twin;
  int b = blockIdx.x, tid = threadIdx.x;
  int lane = tid & 31, wid = tid >> 5;
  ull* kb = g_keys + (size_t)b*HW;

  // init stripe maxima: stripe(T) = { kb[T + 256*j] }
  {
    ull m = 0ull;
    for (int i=tid; i<HW; i+=256){
      ull k = kb[i];
      if (k > m) m = k;
    }
    s_val[tid] = m;
  }
  __syncthreads();

  for (int it=0; it<NKEEP; it++){
    // warp-level argmax over stripe maxima
    ull v = s_val[tid]; int idx = tid;
    #pragma unroll
    for (int off=16; off; off>>=1){
      ull ov  = __shfl_down_sync(0xFFFFFFFFu, v, off);
      int oi  = __shfl_down_sync(0xFFFFFFFFu, idx, off);
      if (ov > v){ v = ov; idx = oi; }
    }
    if (lane==0){ s_wv[wid] = v; s_wi[wid] = idx; }
    __syncthreads();
    if (tid==0){
      ull bv = s_wv[0]; int bidx = s_wi[0];
      #pragma unroll
      for (int w=1;w<8;w++)
        if (s_wv[w] > bv){ bv = s_wv[w]; bidx = s_wi[w]; }
      int wpx = (int)(0xFFFFFFFFu - (unsigned)(bv & 0xFFFFFFFFull));
      g_topk[b*NKEEP+it] = wpx;
      kb[wpx] = 0ull;
      s_twin = bidx;
    }
    __syncthreads();
    // warp 0 rebuilds only the winner's stripe
    int twin = s_twin;
    if (wid==0){
      ull m = 0ull;
      int i0 = twin + lane*256, i1 = twin + (lane+32)*256;
      if (i0 < HW){ ull k = kb[i0]; if (k > m) m = k; }
      if (i1 < HW){ ull k = kb[i1]; if (k > m) m = k; }
      #pragma unroll
      for (int off=16; off; off>>=1){
        ull ov = __shfl_down_sync(0xFFFFFFFFu, m, off);
        if (ov > m) m = ov;
      }
      if (lane==0) s_val[twin] = m;
    }
    __syncthreads();
  }
}

// ---------------------------------------------------------------------------
// Gather x and pos at top-k indices. out layout: [proposals | pos | logits]
// ---------------------------------------------------------------------------
__global__ void k_gather(const float* __restrict__ x, const float* __restrict__ pos,
                         float* __restrict__ out){
  int i = blockIdx.x*256 + threadIdx.x;
  if (i >= NOUT1) return;
  int k = i % NKEEP; int t = i / NKEEP; int c = t % CIN; int b = t / CIN;
  int px = g_topk[b*NKEEP + k];
  out[i]         = x[((size_t)b*CIN + c)*HW + px];
  out[NOUT1 + i] = pos[(size_t)c*HW + px];
}

// ---------------------------------------------------------------------------
extern "C" void kernel_launch(void* const* d_in, const int* in_sizes, int n_in,
                              void* d_out, int out_size){
  (void)in_sizes; (void)n_in; (void)out_size;
  const float* x   = (const float*)d_in[0];
  const float* pos = (const float*)d_in[1];
  const float* w1  = (const float*)d_in[2];
  const float* b1  = (const float*)d_in[3];
  const float* w2  = (const float*)d_in[4];
  const float* b2  = (const float*)d_in[5];
  float* out = (float*)d_out;
  float* logits = out + 2*NOUT1;

  k_wino_w  <<<(CIN*CIN+255)/256, 256>>>(w1);
  k_wino_in <<<dim3((NTILES+255)/256, CIN), 256>>>(x);
  k_gemm    <<<dim3(TPAD/128, CIN/128, 36), 256>>>();
  k_wino_out<<<dim3((NTILES+255)/256, CIN), 256>>>(b1);
  k_conv1x1s<<<dim3((HW+255)/256, BATCH), 256>>>(w2, b2, logits);
  k_score   <<<(BATCH*HW+255)/256, 256>>>();
  k_topk    <<<BATCH, 256>>>();
  k_gather  <<<(NOUT1+255)/256, 256>>>(x, pos, out);
}

// round 12
// speedup vs baseline: 3.4884x; 1.1003x over previous
#include <cuda_runtime.h>
#include <math.h>

#define BATCH 8
#define CIN 256
#define HH 100
#define WW 152
#define HW 15200
#define NC 81
#define NKEEP 100
#define NOUT1 (BATCH*CIN*NKEEP)   /* 204800 */

#define NTILES 7600       /* 8 * 25 * 38 */
#define TPB    950        /* tiles per batch image */
#define TPAD   7680       /* padded tile count (60 * 128) */

typedef unsigned long long ull;

// ---------------------------------------------------------------------------
// Device scratch (allocation-free per harness rules)
// ---------------------------------------------------------------------------
__device__ int   g_cls[BATCH*HW];
__device__ float g_pv[BATCH*HW];
__device__ ull   g_keys[BATCH*HW];
__device__ int   g_topk[BATCH*NKEEP];
// Winograd buffers
__device__ float g_U[(size_t)36*CIN*CIN];         // weight transform [k][ci][co]
__device__ float g_V[(size_t)36*CIN*TPAD];        // input transform  [k][ci][t]
__device__ float g_M[(size_t)36*CIN*TPAD];        // GEMM output      [k][co][t]

// Packed f32x2 helpers (SASS FFMA2 — exact IEEE fp32)
#define FMA2(d,a,b,c) asm("fma.rn.f32x2 %0, %1, %2, %3;" : "=l"(d) : "l"(a), "l"(b), "l"(c))
#define PACK2(d,lo,hi) asm("mov.b64 %0, {%1, %2};" : "=l"(d) : "f"(lo), "f"(hi))
#define UNPACK2(lo,hi,s) asm("mov.b64 {%0, %1}, %2;" : "=f"(lo), "=f"(hi) : "l"(s))

// ---------------------------------------------------------------------------
// Winograd F(4x4,3x3) weight transform: U = G g G^T, stored [k=36][ci][co]
// ---------------------------------------------------------------------------
__global__ void k_wino_w(const float* __restrict__ w1){
  int i = blockIdx.x*256 + threadIdx.x;
  if (i >= CIN*CIN) return;
  int co = i & 255, ci = i >> 8;
  float g[3][3];
  #pragma unroll
  for (int m=0;m<3;m++)
    #pragma unroll
    for (int j=0;j<3;j++)
      g[m][j] = w1[((size_t)(co*CIN+ci)*3+m)*3+j];
  float T1[6][3];
  #pragma unroll
  for (int j=0;j<3;j++){
    float g0=g[0][j], g1=g[1][j], g2=g[2][j];
    T1[0][j] = 0.25f*g0;
    T1[1][j] = (-g0-g1-g2)*(1.f/6.f);
    T1[2][j] = (-g0+g1-g2)*(1.f/6.f);
    T1[3][j] = g0*(1.f/24.f)+g1*(1.f/12.f)+g2*(1.f/6.f);
    T1[4][j] = g0*(1.f/24.f)-g1*(1.f/12.f)+g2*(1.f/6.f);
    T1[5][j] = g2;
  }
  #pragma unroll
  for (int r=0;r<6;r++){
    float t0=T1[r][0], t1=T1[r][1], t2=T1[r][2];
    float u[6];
    u[0] = 0.25f*t0;
    u[1] = (-t0-t1-t2)*(1.f/6.f);
    u[2] = (-t0+t1-t2)*(1.f/6.f);
    u[3] = t0*(1.f/24.f)+t1*(1.f/12.f)+t2*(1.f/6.f);
    u[4] = t0*(1.f/24.f)-t1*(1.f/12.f)+t2*(1.f/6.f);
    u[5] = t2;
    #pragma unroll
    for (int c=0;c<6;c++)
      g_U[((size_t)(r*6+c)*CIN + ci)*CIN + co] = u[c];
  }
}

// ---------------------------------------------------------------------------
// Input transform: V = B^T d B per (tile, ci). Stored [k][ci][t].
// ---------------------------------------------------------------------------
__global__ void k_wino_in(const float* __restrict__ x){
  int t = blockIdx.x*256 + threadIdx.x;
  int ci = blockIdx.y;
  if (t >= NTILES) return;
  int b = t / TPB, rr = t - b*TPB;
  int ty = rr / 38, tx = rr - ty*38;
  int y0 = ty*4 - 1, xg0 = tx*4 - 1;
  const float* xp = x + ((size_t)b*CIN + ci)*HW;
  float d[6][6];
  #pragma unroll
  for (int m=0;m<6;m++){
    int gy = y0 + m;
    bool ry = ((unsigned)gy < HH);
    #pragma unroll
    for (int j=0;j<6;j++){
      int gx = xg0 + j;
      d[m][j] = (ry && (unsigned)gx < WW) ? xp[gy*WW + gx] : 0.f;
    }
  }
  float tmp[6][6];
  #pragma unroll
  for (int j=0;j<6;j++){
    float d0=d[0][j],d1=d[1][j],d2=d[2][j],d3=d[3][j],d4=d[4][j],d5=d[5][j];
    tmp[0][j] = 4.f*d0 - 5.f*d2 + d4;
    tmp[1][j] = -4.f*d1 - 4.f*d2 + d3 + d4;
    tmp[2][j] =  4.f*d1 - 4.f*d2 - d3 + d4;
    tmp[3][j] = -2.f*d1 - d2 + 2.f*d3 + d4;
    tmp[4][j] =  2.f*d1 - d2 - 2.f*d3 + d4;
    tmp[5][j] =  4.f*d1 - 5.f*d3 + d5;
  }
  #pragma unroll
  for (int i=0;i<6;i++){
    float r0=tmp[i][0],r1=tmp[i][1],r2=tmp[i][2],r3=tmp[i][3],r4=tmp[i][4],r5=tmp[i][5];
    float v[6];
    v[0] = 4.f*r0 - 5.f*r2 + r4;
    v[1] = -4.f*r1 - 4.f*r2 + r3 + r4;
    v[2] =  4.f*r1 - 4.f*r2 - r3 + r4;
    v[3] = -2.f*r1 - r2 + 2.f*r3 + r4;
    v[4] =  2.f*r1 - r2 - 2.f*r3 + r4;
    v[5] =  4.f*r1 - 5.f*r3 + r5;
    #pragma unroll
    for (int c=0;c<6;c++)
      g_V[((size_t)(i*6+c)*CIN + ci)*TPAD + t] = v[c];
  }
}

// ---------------------------------------------------------------------------
// GEMM v3 (unchanged from R10/R11 win): 128co x 128t, ci chunks of 16.
// ---------------------------------------------------------------------------
__global__ __launch_bounds__(256,2) void k_gemm(){
  __shared__ __align__(16) ull s_v[2][16][128];   // (v,v) pairs, 32KB
  __shared__ __align__(16) ull s_w[2][16][64];    // (w0,w1) pairs, 16KB
  int tid = threadIdx.x;
  int t0  = blockIdx.x*128;
  int co0 = blockIdx.y*128;
  int kk  = blockIdx.z;
  int og = tid & 15;       // co group: 8 co (4 pairs)
  int tg = tid >> 4;       // t group: 8 t
  const float* Vk = g_V + (size_t)kk*CIN*TPAD;
  const float* Uk = g_U + (size_t)kk*CIN*CIN;

  ull acc[4][8];
  #pragma unroll
  for (int p=0;p<4;p++)
    #pragma unroll
    for (int j=0;j<8;j++) PACK2(acc[p][j], 0.f, 0.f);

  int sci  = tid >> 5;
  int scol = tid & 31;

  float4 rv0 = *(const float4*)&Vk[(size_t)sci*TPAD + t0 + scol*4];
  float4 rv1 = *(const float4*)&Vk[(size_t)(sci+8)*TPAD + t0 + scol*4];
  float4 rw0 = *(const float4*)&Uk[(size_t)sci*CIN + co0 + scol*4];
  float4 rw1 = *(const float4*)&Uk[(size_t)(sci+8)*CIN + co0 + scol*4];
  {
    ull d0,d1,d2,d3;
    PACK2(d0,rv0.x,rv0.x); PACK2(d1,rv0.y,rv0.y);
    PACK2(d2,rv0.z,rv0.z); PACK2(d3,rv0.w,rv0.w);
    ull* dst = &s_v[0][sci][scol*4];
    dst[0]=d0; dst[1]=d1; dst[2]=d2; dst[3]=d3;
    PACK2(d0,rv1.x,rv1.x); PACK2(d1,rv1.y,rv1.y);
    PACK2(d2,rv1.z,rv1.z); PACK2(d3,rv1.w,rv1.w);
    dst = &s_v[0][sci+8][scol*4];
    dst[0]=d0; dst[1]=d1; dst[2]=d2; dst[3]=d3;
    ull w0,w1;
    PACK2(w0,rw0.x,rw0.y); PACK2(w1,rw0.z,rw0.w);
    s_w[0][sci][scol*2]   = w0;
    s_w[0][sci][scol*2+1] = w1;
    PACK2(w0,rw1.x,rw1.y); PACK2(w1,rw1.z,rw1.w);
    s_w[0][sci+8][scol*2]   = w0;
    s_w[0][sci+8][scol*2+1] = w1;
  }
  __syncthreads();

  #pragma unroll 1
  for (int c=0; c<16; c++){
    int buf = c & 1;
    if (c+1 < 16){
      int cin = (c+1)*16;
      rv0 = *(const float4*)&Vk[(size_t)(cin+sci)*TPAD + t0 + scol*4];
      rv1 = *(const float4*)&Vk[(size_t)(cin+sci+8)*TPAD + t0 + scol*4];
      rw0 = *(const float4*)&Uk[(size_t)(cin+sci)*CIN + co0 + scol*4];
      rw1 = *(const float4*)&Uk[(size_t)(cin+sci+8)*CIN + co0 + scol*4];
    }

    #pragma unroll 8
    for (int ci=0; ci<16; ci++){
      ulonglong2 v01 = *(const ulonglong2*)&s_v[buf][ci][tg*8];
      ulonglong2 v23 = *(const ulonglong2*)&s_v[buf][ci][tg*8+2];
      ulonglong2 v45 = *(const ulonglong2*)&s_v[buf][ci][tg*8+4];
      ulonglong2 v67 = *(const ulonglong2*)&s_v[buf][ci][tg*8+6];
      ulonglong2 wa = *(const ulonglong2*)&s_w[buf][ci][og*4];
      ulonglong2 wb = *(const ulonglong2*)&s_w[buf][ci][og*4+2];
      ull v[8] = {v01.x, v01.y, v23.x, v23.y, v45.x, v45.y, v67.x, v67.y};
      #pragma unroll
      for (int j=0;j<8;j++){
        FMA2(acc[0][j], v[j], wa.x, acc[0][j]);
        FMA2(acc[1][j], v[j], wa.y, acc[1][j]);
        FMA2(acc[2][j], v[j], wb.x, acc[2][j]);
        FMA2(acc[3][j], v[j], wb.y, acc[3][j]);
      }
    }

    if (c+1 < 16){
      int nb = buf ^ 1;
      ull d0,d1,d2,d3;
      PACK2(d0,rv0.x,rv0.x); PACK2(d1,rv0.y,rv0.y);
      PACK2(d2,rv0.z,rv0.z); PACK2(d3,rv0.w,rv0.w);
      ull* dst = &s_v[nb][sci][scol*4];
      dst[0]=d0; dst[1]=d1; dst[2]=d2; dst[3]=d3;
      PACK2(d0,rv1.x,rv1.x); PACK2(d1,rv1.y,rv1.y);
      PACK2(d2,rv1.z,rv1.z); PACK2(d3,rv1.w,rv1.w);
      dst = &s_v[nb][sci+8][scol*4];
      dst[0]=d0; dst[1]=d1; dst[2]=d2; dst[3]=d3;
      ull w0,w1;
      PACK2(w0,rw0.x,rw0.y); PACK2(w1,rw0.z,rw0.w);
      s_w[nb][sci][scol*2]   = w0;
      s_w[nb][sci][scol*2+1] = w1;
      PACK2(w0,rw1.x,rw1.y); PACK2(w1,rw1.z,rw1.w);
      s_w[nb][sci+8][scol*2]   = w0;
      s_w[nb][sci+8][scol*2+1] = w1;
    }
    __syncthreads();
  }

  float* Mk = g_M + (size_t)kk*CIN*TPAD;
  #pragma unroll
  for (int p=0;p<4;p++){
    float lo[8], hi[8];
    #pragma unroll
    for (int j=0;j<8;j++) UNPACK2(lo[j], hi[j], acc[p][j]);
    int co = co0 + og*8 + 2*p;
    float* r0 = &Mk[(size_t)co*TPAD + t0 + tg*8];
    float* r1 = &Mk[(size_t)(co+1)*TPAD + t0 + tg*8];
    *(float4*)r0     = make_float4(lo[0],lo[1],lo[2],lo[3]);
    *(float4*)(r0+4) = make_float4(lo[4],lo[5],lo[6],lo[7]);
    *(float4*)r1     = make_float4(hi[0],hi[1],hi[2],hi[3]);
    *(float4*)(r1+4) = make_float4(hi[4],hi[5],hi[6],hi[7]);
  }
}

// ---------------------------------------------------------------------------
// FUSED: output transform (A^T M A + bias + relu) + 1x1 conv + softmax.
// Block = 16 tiles (256 px). 16 ci-chunks of 16: 256 threads transform
// their (co,tile) pair from g_M into smem hid, then each thread (1 px,
// 41 f32x2 logit accumulators) accumulates the chunk. ci order 0..255
// ascending -> bitwise identical to previous wino_out + conv1x1s.
// g_hid never materialized (saves 249 MB of DRAM traffic).
// ---------------------------------------------------------------------------
__global__ __launch_bounds__(256,1) void k_fused_out(const float* __restrict__ b1,
                                                     const float* __restrict__ w2,
                                                     const float* __restrict__ b2,
                                                     float* __restrict__ logits){
  __shared__ float s_hid[16][256];   // [ci16][tl*16 + pos], 16KB
  __shared__ ull   s_w2[16][41];     // (w[2j],w[2j+1]) per ci, 5.25KB
  int tid = threadIdx.x;
  int t0 = blockIdx.x*16;
  int co16 = tid >> 4;     // transform role: local co
  int tl   = tid & 15;     // transform role: local tile
  int t    = t0 + tl;

  ull acc[41];
  #pragma unroll
  for (int j=0;j<41;j++){
    float ba = b2[2*j];
    float bb = (2*j+1 < 81) ? b2[2*j+1] : 0.f;
    PACK2(acc[j], ba, bb);
  }

  #pragma unroll 1
  for (int ch=0; ch<16; ch++){
    __syncthreads();   // protect s_hid/s_w2 from previous chunk's readers
    // stage w2 chunk (16 ci x 41 pairs)
    #pragma unroll 1
    for (int i=tid; i<16*41; i+=256){
      int j = i % 41; int ci = i/41;
      int cia = ch*16 + ci;
      float wa = w2[(2*j)*CIN + cia];
      float wb = (2*j+1 < 81) ? w2[(2*j+1)*CIN + cia] : 0.f;
      ull d; PACK2(d, wa, wb);
      s_w2[ci][j] = d;
    }
    // transform: co = ch*16 + co16, tile t (column-incremental, low reg)
    {
      int co = ch*16 + co16;
      const float* Mp = g_M + (size_t)co*TPAD + t;
      float bv = b1[co];
      float tr0[6], tr1[6], tr2[6], tr3[6];
      #pragma unroll
      for (int j=0;j<6;j++){
        float m0 = Mp[(size_t)(0*6+j)*CIN*TPAD];
        float m1 = Mp[(size_t)(1*6+j)*CIN*TPAD];
        float m2 = Mp[(size_t)(2*6+j)*CIN*TPAD];
        float m3 = Mp[(size_t)(3*6+j)*CIN*TPAD];
        float m4 = Mp[(size_t)(4*6+j)*CIN*TPAD];
        float m5 = Mp[(size_t)(5*6+j)*CIN*TPAD];
        tr0[j] = m0+m1+m2+m3+m4;
        tr1[j] = m1-m2+2.f*m3-2.f*m4;
        tr2[j] = m1+m2+4.f*m3+4.f*m4;
        tr3[j] = m1-m2+8.f*m3-8.f*m4+m5;
      }
      float* hrow = &s_hid[co16][tl*16];
      #pragma unroll
      for (int r=0;r<4;r++){
        const float* tr = (r==0)?tr0:((r==1)?tr1:((r==2)?tr2:tr3));
        float r0=tr[0],r1=tr[1],r2=tr[2],r3=tr[3],r4=tr[4],r5=tr[5];
        float y0 = r0+r1+r2+r3+r4;
        float y1 = r1-r2+2.f*r3-2.f*r4;
        float y2 = r1+r2+4.f*r3+4.f*r4;
        float y3 = r1-r2+8.f*r3-8.f*r4+r5;
        hrow[r*4+0] = fmaxf(y0+bv, 0.f);
        hrow[r*4+1] = fmaxf(y1+bv, 0.f);
        hrow[r*4+2] = fmaxf(y2+bv, 0.f);
        hrow[r*4+3] = fmaxf(y3+bv, 0.f);
      }
    }
    __syncthreads();
    // conv: thread owns px index tid (tile = tid>>4, pos = tid&15)
    #pragma unroll 2
    for (int ci=0; ci<16; ci++){
      float v = s_hid[ci][tid];
      ull vd; PACK2(vd, v, v);
      const ull* wp = s_w2[ci];
      #pragma unroll
      for (int j=0;j<41;j++) FMA2(acc[j], vd, wp[j], acc[j]);
    }
  }

  // epilogue: logits write + softmax/argmax (identical math to conv1x1s)
  int tile = t0 + (tid >> 4);
  if (tile < NTILES){
    int pos = tid & 15;
    int b = tile / TPB, rr = tile - b*TPB;
    int ty = rr / 38, tx = rr - ty*38;
    int px = (ty*4 + (pos>>2))*WW + tx*4 + (pos&3);
    float* ob = logits + (size_t)b*NC*HW;

    float M = -1e30f, best = -1e30f; int bi = 0;
    #pragma unroll
    for (int j=0;j<41;j++){
      float a, c; UNPACK2(a, c, acc[j]);
      ob[(size_t)(2*j)*HW + px] = a;
      if (2*j < 80 && a > best){ best = a; bi = 2*j; }
      M = fmaxf(M, a);
      if (2*j+1 < 81){
        ob[(size_t)(2*j+1)*HW + px] = c;
        if (2*j+1 < 80 && c > best){ best = c; bi = 2*j+1; }
        M = fmaxf(M, c);
      }
    }
    float s = 0.f;
    #pragma unroll
    for (int j=0;j<41;j++){
      float a, c; UNPACK2(a, c, acc[j]);
      s += expf(a - M);
      if (2*j+1 < 81) s += expf(c - M);
    }
    int gi = b*HW + px;
    g_pv[gi]  = expf(best - M) / s;
    g_cls[gi] = bi;
  }
}

// ---------------------------------------------------------------------------
// score = p + 1 if local max (same-class strict neighbors) — unchanged.
// ---------------------------------------------------------------------------
__global__ void k_score(){
  int i = blockIdx.x*256 + threadIdx.x;
  if (i >= BATCH*HW) return;
  int b = i / HW, px = i - b*HW;
  int y = px / WW, xx = px - y*WW;
  float p = g_pv[i]; int cls = g_cls[i];
  bool flag = (p >= 1e-6f);
  if (flag){
    #pragma unroll
    for (int dy=-1; dy<=1; dy++){
      #pragma unroll
      for (int dx=-1; dx<=1; dx++){
        if (dy==0 && dx==0) continue;
        int ny = y+dy, nx = xx+dx;
        if ((unsigned)ny < HH && (unsigned)nx < WW){
          int j = b*HW + ny*WW + nx;
          if (g_cls[j]==cls && g_pv[j] > p) flag = false;
        }
      }
    }
  }
  float score = p + (flag ? 1.f : 0.f);
  g_keys[i] = (((ull)__float_as_uint(score))<<32)
              | (ull)(0xFFFFFFFFu - (unsigned)px);
}

// ---------------------------------------------------------------------------
// Top-100 v2 (unchanged from R11 win): stripe cache + shfl argmax.
// ---------------------------------------------------------------------------
__global__ void k_topk(){
  __shared__ ull s_val[256];
  __shared__ ull s_wv[8];
  __shared__ int s_wi[8];
  __shared__ int s_twin;
  int b = blockIdx.x, tid = threadIdx.x;
  int lane = tid & 31, wid = tid >> 5;
  ull* kb = g_keys + (size_t)b*HW;

  {
    ull m = 0ull;
    for (int i=tid; i<HW; i+=256){
      ull k = kb[i];
      if (k > m) m = k;
    }
    s_val[tid] = m;
  }
  __syncthreads();

  for (int it=0; it<NKEEP; it++){
    ull v = s_val[tid]; int idx = tid;
    #pragma unroll
    for (int off=16; off; off>>=1){
      ull ov  = __shfl_down_sync(0xFFFFFFFFu, v, off);
      int oi  = __shfl_down_sync(0xFFFFFFFFu, idx, off);
      if (ov > v){ v = ov; idx = oi; }
    }
    if (lane==0){ s_wv[wid] = v; s_wi[wid] = idx; }
    __syncthreads();
    if (tid==0){
      ull bv = s_wv[0]; int bidx = s_wi[0];
      #pragma unroll
      for (int w=1;w<8;w++)
        if (s_wv[w] > bv){ bv = s_wv[w]; bidx = s_wi[w]; }
      int wpx = (int)(0xFFFFFFFFu - (unsigned)(bv & 0xFFFFFFFFull));
      g_topk[b*NKEEP+it] = wpx;
      kb[wpx] = 0ull;
      s_twin = bidx;
    }
    __syncthreads();
    int twin = s_twin;
    if (wid==0){
      ull m = 0ull;
      int i0 = twin + lane*256, i1 = twin + (lane+32)*256;
      if (i0 < HW){ ull k = kb[i0]; if (k > m) m = k; }
      if (i1 < HW){ ull k = kb[i1]; if (k > m) m = k; }
      #pragma unroll
      for (int off=16; off; off>>=1){
        ull ov = __shfl_down_sync(0xFFFFFFFFu, m, off);
        if (ov > m) m = ov;
      }
      if (lane==0) s_val[twin] = m;
    }
    __syncthreads();
  }
}

// ---------------------------------------------------------------------------
// Gather x and pos at top-k indices. out layout: [proposals | pos | logits]
// ---------------------------------------------------------------------------
__global__ void k_gather(const float* __restrict__ x, const float* __restrict__ pos,
                         float* __restrict__ out){
  int i = blockIdx.x*256 + threadIdx.x;
  if (i >= NOUT1) return;
  int k = i % NKEEP; int t = i / NKEEP; int c = t % CIN; int b = t / CIN;
  int px = g_topk[b*NKEEP + k];
  out[i]         = x[((size_t)b*CIN + c)*HW + px];
  out[NOUT1 + i] = pos[(size_t)c*HW + px];
}

// ---------------------------------------------------------------------------
extern "C" void kernel_launch(void* const* d_in, const int* in_sizes, int n_in,
                              void* d_out, int out_size){
  (void)in_sizes; (void)n_in; (void)out_size;
  const float* x   = (const float*)d_in[0];
  const float* pos = (const float*)d_in[1];
  const float* w1  = (const float*)d_in[2];
  const float* b1  = (const float*)d_in[3];
  const float* w2  = (const float*)d_in[4];
  const float* b2  = (const float*)d_in[5];
  float* out = (float*)d_out;
  float* logits = out + 2*NOUT1;

  k_wino_w   <<<(CIN*CIN+255)/256, 256>>>(w1);
  k_wino_in  <<<dim3((NTILES+255)/256, CIN), 256>>>(x);
  k_gemm     <<<dim3(TPAD/128, CIN/128, 36), 256>>>();
  k_fused_out<<<TPAD/16, 256>>>(b1, w2, b2, logits);
  k_score    <<<(BATCH*HW+255)/256, 256>>>();
  k_topk     <<<BATCH, 256>>>();
  k_gather   <<<(NOUT1+255)/256, 256>>>(x, pos, out);
}

// round 13
// speedup vs baseline: 3.5444x; 1.0161x over previous
#include <cuda_runtime.h>
#include <math.h>

#define BATCH 8
#define CIN 256
#define HH 100
#define WW 152
#define HW 15200
#define NC 81
#define NKEEP 100
#define NOUT1 (BATCH*CIN*NKEEP)   /* 204800 */

#define NTILES 7600       /* 8 * 25 * 38 */
#define TPB    950        /* tiles per batch image */
#define TPAD   7680       /* padded tile count (60 * 128) */

typedef unsigned long long ull;

// ---------------------------------------------------------------------------
// Device scratch (allocation-free per harness rules)
// ---------------------------------------------------------------------------
__device__ int   g_cls[BATCH*HW];
__device__ float g_pv[BATCH*HW];
__device__ ull   g_keys[BATCH*HW];
__device__ int   g_topk[BATCH*NKEEP];
// Winograd buffers
__device__ float g_U[(size_t)36*CIN*CIN];         // weight transform [k][ci][co]
__device__ float g_V[(size_t)36*CIN*TPAD];        // input transform  [k][ci][t]
__device__ float g_M[(size_t)36*CIN*TPAD];        // GEMM output      [k][co][t]

// Packed f32x2 helpers (SASS FFMA2 — exact IEEE fp32)
#define FMA2(d,a,b,c) asm("fma.rn.f32x2 %0, %1, %2, %3;" : "=l"(d) : "l"(a), "l"(b), "l"(c))
#define PACK2(d,lo,hi) asm("mov.b64 %0, {%1, %2};" : "=l"(d) : "f"(lo), "f"(hi))
#define UNPACK2(lo,hi,s) asm("mov.b64 {%0, %1}, %2;" : "=f"(lo), "=f"(hi) : "l"(s))

// ---------------------------------------------------------------------------
// Winograd F(4x4,3x3) weight transform: U = G g G^T, stored [k=36][ci][co]
// ---------------------------------------------------------------------------
__global__ void k_wino_w(const float* __restrict__ w1){
  int i = blockIdx.x*256 + threadIdx.x;
  if (i >= CIN*CIN) return;
  int co = i & 255, ci = i >> 8;
  float g[3][3];
  #pragma unroll
  for (int m=0;m<3;m++)
    #pragma unroll
    for (int j=0;j<3;j++)
      g[m][j] = w1[((size_t)(co*CIN+ci)*3+m)*3+j];
  float T1[6][3];
  #pragma unroll
  for (int j=0;j<3;j++){
    float g0=g[0][j], g1=g[1][j], g2=g[2][j];
    T1[0][j] = 0.25f*g0;
    T1[1][j] = (-g0-g1-g2)*(1.f/6.f);
    T1[2][j] = (-g0+g1-g2)*(1.f/6.f);
    T1[3][j] = g0*(1.f/24.f)+g1*(1.f/12.f)+g2*(1.f/6.f);
    T1[4][j] = g0*(1.f/24.f)-g1*(1.f/12.f)+g2*(1.f/6.f);
    T1[5][j] = g2;
  }
  #pragma unroll
  for (int r=0;r<6;r++){
    float t0=T1[r][0], t1=T1[r][1], t2=T1[r][2];
    float u[6];
    u[0] = 0.25f*t0;
    u[1] = (-t0-t1-t2)*(1.f/6.f);
    u[2] = (-t0+t1-t2)*(1.f/6.f);
    u[3] = t0*(1.f/24.f)+t1*(1.f/12.f)+t2*(1.f/6.f);
    u[4] = t0*(1.f/24.f)-t1*(1.f/12.f)+t2*(1.f/6.f);
    u[5] = t2;
    #pragma unroll
    for (int c=0;c<6;c++)
      g_U[((size_t)(r*6+c)*CIN + ci)*CIN + co] = u[c];
  }
}

// ---------------------------------------------------------------------------
// Input transform: V = B^T d B per (tile, ci). Stored [k][ci][t].
// ---------------------------------------------------------------------------
__global__ void k_wino_in(const float* __restrict__ x){
  int t = blockIdx.x*256 + threadIdx.x;
  int ci = blockIdx.y;
  if (t >= NTILES) return;
  int b = t / TPB, rr = t - b*TPB;
  int ty = rr / 38, tx = rr - ty*38;
  int y0 = ty*4 - 1, xg0 = tx*4 - 1;
  const float* xp = x + ((size_t)b*CIN + ci)*HW;
  float d[6][6];
  #pragma unroll
  for (int m=0;m<6;m++){
    int gy = y0 + m;
    bool ry = ((unsigned)gy < HH);
    #pragma unroll
    for (int j=0;j<6;j++){
      int gx = xg0 + j;
      d[m][j] = (ry && (unsigned)gx < WW) ? xp[gy*WW + gx] : 0.f;
    }
  }
  float tmp[6][6];
  #pragma unroll
  for (int j=0;j<6;j++){
    float d0=d[0][j],d1=d[1][j],d2=d[2][j],d3=d[3][j],d4=d[4][j],d5=d[5][j];
    tmp[0][j] = 4.f*d0 - 5.f*d2 + d4;
    tmp[1][j] = -4.f*d1 - 4.f*d2 + d3 + d4;
    tmp[2][j] =  4.f*d1 - 4.f*d2 - d3 + d4;
    tmp[3][j] = -2.f*d1 - d2 + 2.f*d3 + d4;
    tmp[4][j] =  2.f*d1 - d2 - 2.f*d3 + d4;
    tmp[5][j] =  4.f*d1 - 5.f*d3 + d5;
  }
  #pragma unroll
  for (int i=0;i<6;i++){
    float r0=tmp[i][0],r1=tmp[i][1],r2=tmp[i][2],r3=tmp[i][3],r4=tmp[i][4],r5=tmp[i][5];
    float v[6];
    v[0] = 4.f*r0 - 5.f*r2 + r4;
    v[1] = -4.f*r1 - 4.f*r2 + r3 + r4;
    v[2] =  4.f*r1 - 4.f*r2 - r3 + r4;
    v[3] = -2.f*r1 - r2 + 2.f*r3 + r4;
    v[4] =  2.f*r1 - r2 - 2.f*r3 + r4;
    v[5] =  4.f*r1 - 5.f*r3 + r5;
    #pragma unroll
    for (int c=0;c<6;c++)
      g_V[((size_t)(i*6+c)*CIN + ci)*TPAD + t] = v[c];
  }
}

// ---------------------------------------------------------------------------
// GEMM v3 (unchanged from R10/R11 win): 128co x 128t, ci chunks of 16.
// ---------------------------------------------------------------------------
__global__ __launch_bounds__(256,2) void k_gemm(){
  __shared__ __align__(16) ull s_v[2][16][128];   // (v,v) pairs, 32KB
  __shared__ __align__(16) ull s_w[2][16][64];    // (w0,w1) pairs, 16KB
  int tid = threadIdx.x;
  int t0  = blockIdx.x*128;
  int co0 = blockIdx.y*128;
  int kk  = blockIdx.z;
  int og = tid & 15;       // co group: 8 co (4 pairs)
  int tg = tid >> 4;       // t group: 8 t
  const float* Vk = g_V + (size_t)kk*CIN*TPAD;
  const float* Uk = g_U + (size_t)kk*CIN*CIN;

  ull acc[4][8];
  #pragma unroll
  for (int p=0;p<4;p++)
    #pragma unroll
    for (int j=0;j<8;j++) PACK2(acc[p][j], 0.f, 0.f);

  int sci  = tid >> 5;
  int scol = tid & 31;

  float4 rv0 = *(const float4*)&Vk[(size_t)sci*TPAD + t0 + scol*4];
  float4 rv1 = *(const float4*)&Vk[(size_t)(sci+8)*TPAD + t0 + scol*4];
  float4 rw0 = *(const float4*)&Uk[(size_t)sci*CIN + co0 + scol*4];
  float4 rw1 = *(const float4*)&Uk[(size_t)(sci+8)*CIN + co0 + scol*4];
  {
    ull d0,d1,d2,d3;
    PACK2(d0,rv0.x,rv0.x); PACK2(d1,rv0.y,rv0.y);
    PACK2(d2,rv0.z,rv0.z); PACK2(d3,rv0.w,rv0.w);
    ull* dst = &s_v[0][sci][scol*4];
    dst[0]=d0; dst[1]=d1; dst[2]=d2; dst[3]=d3;
    PACK2(d0,rv1.x,rv1.x); PACK2(d1,rv1.y,rv1.y);
    PACK2(d2,rv1.z,rv1.z); PACK2(d3,rv1.w,rv1.w);
    dst = &s_v[0][sci+8][scol*4];
    dst[0]=d0; dst[1]=d1; dst[2]=d2; dst[3]=d3;
    ull w0,w1;
    PACK2(w0,rw0.x,rw0.y); PACK2(w1,rw0.z,rw0.w);
    s_w[0][sci][scol*2]   = w0;
    s_w[0][sci][scol*2+1] = w1;
    PACK2(w0,rw1.x,rw1.y); PACK2(w1,rw1.z,rw1.w);
    s_w[0][sci+8][scol*2]   = w0;
    s_w[0][sci+8][scol*2+1] = w1;
  }
  __syncthreads();

  #pragma unroll 1
  for (int c=0; c<16; c++){
    int buf = c & 1;
    if (c+1 < 16){
      int cin = (c+1)*16;
      rv0 = *(const float4*)&Vk[(size_t)(cin+sci)*TPAD + t0 + scol*4];
      rv1 = *(const float4*)&Vk[(size_t)(cin+sci+8)*TPAD + t0 + scol*4];
      rw0 = *(const float4*)&Uk[(size_t)(cin+sci)*CIN + co0 + scol*4];
      rw1 = *(const float4*)&Uk[(size_t)(cin+sci+8)*CIN + co0 + scol*4];
    }

    #pragma unroll 8
    for (int ci=0; ci<16; ci++){
      ulonglong2 v01 = *(const ulonglong2*)&s_v[buf][ci][tg*8];
      ulonglong2 v23 = *(const ulonglong2*)&s_v[buf][ci][tg*8+2];
      ulonglong2 v45 = *(const ulonglong2*)&s_v[buf][ci][tg*8+4];
      ulonglong2 v67 = *(const ulonglong2*)&s_v[buf][ci][tg*8+6];
      ulonglong2 wa = *(const ulonglong2*)&s_w[buf][ci][og*4];
      ulonglong2 wb = *(const ulonglong2*)&s_w[buf][ci][og*4+2];
      ull v[8] = {v01.x, v01.y, v23.x, v23.y, v45.x, v45.y, v67.x, v67.y};
      #pragma unroll
      for (int j=0;j<8;j++){
        FMA2(acc[0][j], v[j], wa.x, acc[0][j]);
        FMA2(acc[1][j], v[j], wa.y, acc[1][j]);
        FMA2(acc[2][j], v[j], wb.x, acc[2][j]);
        FMA2(acc[3][j], v[j], wb.y, acc[3][j]);
      }
    }

    if (c+1 < 16){
      int nb = buf ^ 1;
      ull d0,d1,d2,d3;
      PACK2(d0,rv0.x,rv0.x); PACK2(d1,rv0.y,rv0.y);
      PACK2(d2,rv0.z,rv0.z); PACK2(d3,rv0.w,rv0.w);
      ull* dst = &s_v[nb][sci][scol*4];
      dst[0]=d0; dst[1]=d1; dst[2]=d2; dst[3]=d3;
      PACK2(d0,rv1.x,rv1.x); PACK2(d1,rv1.y,rv1.y);
      PACK2(d2,rv1.z,rv1.z); PACK2(d3,rv1.w,rv1.w);
      dst = &s_v[nb][sci+8][scol*4];
      dst[0]=d0; dst[1]=d1; dst[2]=d2; dst[3]=d3;
      ull w0,w1;
      PACK2(w0,rw0.x,rw0.y); PACK2(w1,rw0.z,rw0.w);
      s_w[nb][sci][scol*2]   = w0;
      s_w[nb][sci][scol*2+1] = w1;
      PACK2(w0,rw1.x,rw1.y); PACK2(w1,rw1.z,rw1.w);
      s_w[nb][sci+8][scol*2]   = w0;
      s_w[nb][sci+8][scol*2+1] = w1;
    }
    __syncthreads();
  }

  float* Mk = g_M + (size_t)kk*CIN*TPAD;
  #pragma unroll
  for (int p=0;p<4;p++){
    float lo[8], hi[8];
    #pragma unroll
    for (int j=0;j<8;j++) UNPACK2(lo[j], hi[j], acc[p][j]);
    int co = co0 + og*8 + 2*p;
    float* r0 = &Mk[(size_t)co*TPAD + t0 + tg*8];
    float* r1 = &Mk[(size_t)(co+1)*TPAD + t0 + tg*8];
    *(float4*)r0     = make_float4(lo[0],lo[1],lo[2],lo[3]);
    *(float4*)(r0+4) = make_float4(lo[4],lo[5],lo[6],lo[7]);
    *(float4*)r1     = make_float4(hi[0],hi[1],hi[2],hi[3]);
    *(float4*)(r1+4) = make_float4(hi[4],hi[5],hi[6],hi[7]);
  }
}

// ---------------------------------------------------------------------------
// FUSED v2: output transform + bias/relu + 1x1 conv + softmax.
// Block = 16 tiles (256 px), 512 threads = 256 px x 2 co-halves.
// ci-chunks of 32: 512 transform tasks per chunk, then each thread
// accumulates its co-half (21/20 pairs) for its pixel. Halves combined
// through smem in the epilogue (max/argmax order-preserving; sum is
// regrouped once -> ~1ulp denominator delta).
// ---------------------------------------------------------------------------
#define NJ0 21   /* half 0: pairs j=0..20  -> co 0..41  */
#define NJ1 20   /* half 1: pairs j=21..40 -> co 42..81 (81 = pad) */

__global__ __launch_bounds__(512,1) void k_fused_out(const float* __restrict__ b1,
                                                     const float* __restrict__ w2,
                                                     const float* __restrict__ b2,
                                                     float* __restrict__ logits){
  __shared__ float s_hid[32][256];   // [ci32][tl*16 + pos], 32KB
  __shared__ ull   s_w2[32][41];     // (w[2j],w[2j+1]) per ci, 10.5KB
  int tid = threadIdx.x;
  int t0 = blockIdx.x*16;
  int co32 = tid >> 4;     // transform role: local co (0..31)
  int tl   = tid & 15;     // transform role: local tile
  int t    = t0 + tl;
  int pxl  = tid & 255;    // conv role: pixel 0..255
  int half = tid >> 8;     // conv role: co-half
  int j0   = half ? NJ0 : 0;
  int nj   = half ? NJ1 : NJ0;

  ull acc[NJ0];
  #pragma unroll
  for (int j=0;j<NJ0;j++){
    if (j < nj){
      int jj = j0 + j;
      float ba = b2[2*jj];
      float bb = (2*jj+1 < 81) ? b2[2*jj+1] : 0.f;
      PACK2(acc[j], ba, bb);
    } else PACK2(acc[j], 0.f, 0.f);
  }

  #pragma unroll 1
  for (int ch=0; ch<8; ch++){
    __syncthreads();
    // stage w2 chunk (32 ci x 41 pairs)
    #pragma unroll 1
    for (int i=tid; i<32*41; i+=512){
      int j = i % 41; int ci = i/41;
      int cia = ch*32 + ci;
      float wa = w2[(2*j)*CIN + cia];
      float wb = (2*j+1 < 81) ? w2[(2*j+1)*CIN + cia] : 0.f;
      ull d; PACK2(d, wa, wb);
      s_w2[ci][j] = d;
    }
    // transform: co = ch*32 + co32, tile t
    {
      int co = ch*32 + co32;
      const float* Mp = g_M + (size_t)co*TPAD + t;
      float bv = b1[co];
      float tr0[6], tr1[6], tr2[6], tr3[6];
      #pragma unroll
      for (int j=0;j<6;j++){
        float m0 = Mp[(size_t)(0*6+j)*CIN*TPAD];
        float m1 = Mp[(size_t)(1*6+j)*CIN*TPAD];
        float m2 = Mp[(size_t)(2*6+j)*CIN*TPAD];
        float m3 = Mp[(size_t)(3*6+j)*CIN*TPAD];
        float m4 = Mp[(size_t)(4*6+j)*CIN*TPAD];
        float m5 = Mp[(size_t)(5*6+j)*CIN*TPAD];
        tr0[j] = m0+m1+m2+m3+m4;
        tr1[j] = m1-m2+2.f*m3-2.f*m4;
        tr2[j] = m1+m2+4.f*m3+4.f*m4;
        tr3[j] = m1-m2+8.f*m3-8.f*m4+m5;
      }
      float* hrow = &s_hid[co32][tl*16];
      #pragma unroll
      for (int r=0;r<4;r++){
        const float* tr = (r==0)?tr0:((r==1)?tr1:((r==2)?tr2:tr3));
        float r0=tr[0],r1=tr[1],r2=tr[2],r3=tr[3],r4=tr[4],r5=tr[5];
        float y0 = r0+r1+r2+r3+r4;
        float y1 = r1-r2+2.f*r3-2.f*r4;
        float y2 = r1+r2+4.f*r3+4.f*r4;
        float y3 = r1-r2+8.f*r3-8.f*r4+r5;
        hrow[r*4+0] = fmaxf(y0+bv, 0.f);
        hrow[r*4+1] = fmaxf(y1+bv, 0.f);
        hrow[r*4+2] = fmaxf(y2+bv, 0.f);
        hrow[r*4+3] = fmaxf(y3+bv, 0.f);
      }
    }
    __syncthreads();
    // conv: thread owns (pxl, co-half)
    #pragma unroll 4
    for (int ci=0; ci<32; ci++){
      float v = s_hid[ci][pxl];
      ull vd; PACK2(vd, v, v);
      const ull* wp = s_w2[ci] + j0;
      #pragma unroll
      for (int j=0;j<NJ0;j++)
        if (j < nj) FMA2(acc[j], vd, wp[j], acc[j]);
    }
  }

  // epilogue: combine halves via smem (reuse s_hid storage)
  __syncthreads();
  float* redM = (float*)s_hid;          // [512]
  float* redB = redM + 512;             // [512]
  int*   redI = (int*)(redM + 1024);    // [512]
  float* redS = redM + 1536;            // [512]

  int tile = t0 + (pxl >> 4);
  int b = tile / TPB, rr = tile - b*TPB;
  int ty = rr / 38, tx = rr - ty*38;
  int pos = pxl & 15;
  int px = (ty*4 + (pos>>2))*WW + tx*4 + (pos&3);
  bool valid = (tile < NTILES);
  float* ob = logits + (size_t)b*NC*HW;

  float M = -1e30f, best = -1e30f; int bi = 0;
  #pragma unroll
  for (int j=0;j<NJ0;j++){
    if (j < nj){
      int jj = j0 + j;
      float a, c; UNPACK2(a, c, acc[j]);
      if (valid) ob[(size_t)(2*jj)*HW + px] = a;
      if (2*jj < 80 && a > best){ best = a; bi = 2*jj; }
      M = fmaxf(M, a);
      if (2*jj+1 < 81){
        if (valid) ob[(size_t)(2*jj+1)*HW + px] = c;
        if (2*jj+1 < 80 && c > best){ best = c; bi = 2*jj+1; }
        M = fmaxf(M, c);
      }
    }
  }
  redM[tid] = M; redB[tid] = best; redI[tid] = bi;
  __syncthreads();
  float Mg = fmaxf(redM[pxl], redM[pxl+256]);
  float s = 0.f;
  #pragma unroll
  for (int j=0;j<NJ0;j++){
    if (j < nj){
      int jj = j0 + j;
      float a, c; UNPACK2(a, c, acc[j]);
      s += expf(a - Mg);
      if (2*jj+1 < 81) s += expf(c - Mg);
    }
  }
  redS[tid] = s;
  __syncthreads();
  if (half==0 && valid){
    float stot = redS[pxl] + redS[pxl+256];
    float b0 = redB[pxl],  b1v = redB[pxl+256];
    int   i0 = redI[pxl],  i1  = redI[pxl+256];
    // first-wins: half0 indices < half1 indices, so prefer half0 unless strictly larger
    float bestg = b0; int big = i0;
    if (b1v > b0){ bestg = b1v; big = i1; }
    int gi = b*HW + px;
    g_pv[gi]  = expf(bestg - Mg) / stot;
    g_cls[gi] = big;
  }
}

// ---------------------------------------------------------------------------
// score = p + 1 if local max (same-class strict neighbors) — unchanged.
// ---------------------------------------------------------------------------
__global__ void k_score(){
  int i = blockIdx.x*256 + threadIdx.x;
  if (i >= BATCH*HW) return;
  int b = i / HW, px = i - b*HW;
  int y = px / WW, xx = px - y*WW;
  float p = g_pv[i]; int cls = g_cls[i];
  bool flag = (p >= 1e-6f);
  if (flag){
    #pragma unroll
    for (int dy=-1; dy<=1; dy++){
      #pragma unroll
      for (int dx=-1; dx<=1; dx++){
        if (dy==0 && dx==0) continue;
        int ny = y+dy, nx = xx+dx;
        if ((unsigned)ny < HH && (unsigned)nx < WW){
          int j = b*HW + ny*WW + nx;
          if (g_cls[j]==cls && g_pv[j] > p) flag = false;
        }
      }
    }
  }
  float score = p + (flag ? 1.f : 0.f);
  g_keys[i] = (((ull)__float_as_uint(score))<<32)
              | (ull)(0xFFFFFFFFu - (unsigned)px);
}

// ---------------------------------------------------------------------------
// Top-100 v2 (unchanged from R11 win): stripe cache + shfl argmax.
// ---------------------------------------------------------------------------
__global__ void k_topk(){
  __shared__ ull s_val[256];
  __shared__ ull s_wv[8];
  __shared__ int s_wi[8];
  __shared__ int s_twin;
  int b = blockIdx.x, tid = threadIdx.x;
  int lane = tid & 31, wid = tid >> 5;
  ull* kb = g_keys + (size_t)b*HW;

  {
    ull m = 0ull;
    for (int i=tid; i<HW; i+=256){
      ull k = kb[i];
      if (k > m) m = k;
    }
    s_val[tid] = m;
  }
  __syncthreads();

  for (int it=0; it<NKEEP; it++){
    ull v = s_val[tid]; int idx = tid;
    #pragma unroll
    for (int off=16; off; off>>=1){
      ull ov  = __shfl_down_sync(0xFFFFFFFFu, v, off);
      int oi  = __shfl_down_sync(0xFFFFFFFFu, idx, off);
      if (ov > v){ v = ov; idx = oi; }
    }
    if (lane==0){ s_wv[wid] = v; s_wi[wid] = idx; }
    __syncthreads();
    if (tid==0){
      ull bv = s_wv[0]; int bidx = s_wi[0];
      #pragma unroll
      for (int w=1;w<8;w++)
        if (s_wv[w] > bv){ bv = s_wv[w]; bidx = s_wi[w]; }
      int wpx = (int)(0xFFFFFFFFu - (unsigned)(bv & 0xFFFFFFFFull));
      g_topk[b*NKEEP+it] = wpx;
      kb[wpx] = 0ull;
      s_twin = bidx;
    }
    __syncthreads();
    int twin = s_twin;
    if (wid==0){
      ull m = 0ull;
      int i0 = twin + lane*256, i1 = twin + (lane+32)*256;
      if (i0 < HW){ ull k = kb[i0]; if (k > m) m = k; }
      if (i1 < HW){ ull k = kb[i1]; if (k > m) m = k; }
      #pragma unroll
      for (int off=16; off; off>>=1){
        ull ov = __shfl_down_sync(0xFFFFFFFFu, m, off);
        if (ov > m) m = ov;
      }
      if (lane==0) s_val[twin] = m;
    }
    __syncthreads();
  }
}

// ---------------------------------------------------------------------------
// Gather x and pos at top-k indices. out layout: [proposals | pos | logits]
// ---------------------------------------------------------------------------
__global__ void k_gather(const float* __restrict__ x, const float* __restrict__ pos,
                         float* __restrict__ out){
  int i = blockIdx.x*256 + threadIdx.x;
  if (i >= NOUT1) return;
  int k = i % NKEEP; int t = i / NKEEP; int c = t % CIN; int b = t / CIN;
  int px = g_topk[b*NKEEP + k];
  out[i]         = x[((size_t)b*CIN + c)*HW + px];
  out[NOUT1 + i] = pos[(size_t)c*HW + px];
}

// ---------------------------------------------------------------------------
extern "C" void kernel_launch(void* const* d_in, const int* in_sizes, int n_in,
                              void* d_out, int out_size){
  (void)in_sizes; (void)n_in; (void)out_size;
  const float* x   = (const float*)d_in[0];
  const float* pos = (const float*)d_in[1];
  const float* w1  = (const float*)d_in[2];
  const float* b1  = (const float*)d_in[3];
  const float* w2  = (const float*)d_in[4];
  const float* b2  = (const float*)d_in[5];
  float* out = (float*)d_out;
  float* logits = out + 2*NOUT1;

  k_wino_w   <<<(CIN*CIN+255)/256, 256>>>(w1);
  k_wino_in  <<<dim3((NTILES+255)/256, CIN), 256>>>(x);
  k_gemm     <<<dim3(TPAD/128, CIN/128, 36), 256>>>();
  k_fused_out<<<TPAD/16, 512>>>(b1, w2, b2, logits);
  k_score    <<<(BATCH*HW+255)/256, 256>>>();
  k_topk     <<<BATCH, 256>>>();
  k_gather   <<<(NOUT1+255)/256, 256>>>(x, pos, out);
}

// round 14
// speedup vs baseline: 3.7335x; 1.0533x over previous
#include <cuda_runtime.h>
#include <math.h>

#define BATCH 8
#define CIN 256
#define HH 100
#define WW 152
#define HW 15200
#define NC 81
#define NKEEP 100
#define NOUT1 (BATCH*CIN*NKEEP)   /* 204800 */

#define NTILES 7600       /* 8 * 25 * 38 */
#define TPB    950        /* tiles per batch image */
#define TPAD   7680       /* padded tile count (60 * 128) */

typedef unsigned long long ull;

// ---------------------------------------------------------------------------
// Device scratch (allocation-free per harness rules)
// ---------------------------------------------------------------------------
__device__ int   g_cls[BATCH*HW];
__device__ float g_pv[BATCH*HW];
__device__ ull   g_keys[BATCH*HW];
__device__ int   g_topk[BATCH*NKEEP];
// Winograd buffers
__device__ float g_U[(size_t)36*CIN*CIN];         // weight transform [k][ci][co]
__device__ float g_V[(size_t)36*CIN*TPAD];        // input transform  [k][ci][t]
__device__ float g_M[(size_t)36*CIN*TPAD];        // GEMM output      [k][co][t]

// Packed f32x2 helpers (SASS FFMA2 — exact IEEE fp32)
#define FMA2(d,a,b,c) asm("fma.rn.f32x2 %0, %1, %2, %3;" : "=l"(d) : "l"(a), "l"(b), "l"(c))
#define PACK2(d,lo,hi) asm("mov.b64 %0, {%1, %2};" : "=l"(d) : "f"(lo), "f"(hi))
#define UNPACK2(lo,hi,s) asm("mov.b64 {%0, %1}, %2;" : "=f"(lo), "=f"(hi) : "l"(s))

// ---------------------------------------------------------------------------
// Winograd F(4x4,3x3) weight transform: U = G g G^T, stored [k=36][ci][co]
// ---------------------------------------------------------------------------
__global__ void k_wino_w(const float* __restrict__ w1){
  int i = blockIdx.x*256 + threadIdx.x;
  if (i >= CIN*CIN) return;
  int co = i & 255, ci = i >> 8;
  float g[3][3];
  #pragma unroll
  for (int m=0;m<3;m++)
    #pragma unroll
    for (int j=0;j<3;j++)
      g[m][j] = w1[((size_t)(co*CIN+ci)*3+m)*3+j];
  float T1[6][3];
  #pragma unroll
  for (int j=0;j<3;j++){
    float g0=g[0][j], g1=g[1][j], g2=g[2][j];
    T1[0][j] = 0.25f*g0;
    T1[1][j] = (-g0-g1-g2)*(1.f/6.f);
    T1[2][j] = (-g0+g1-g2)*(1.f/6.f);
    T1[3][j] = g0*(1.f/24.f)+g1*(1.f/12.f)+g2*(1.f/6.f);
    T1[4][j] = g0*(1.f/24.f)-g1*(1.f/12.f)+g2*(1.f/6.f);
    T1[5][j] = g2;
  }
  #pragma unroll
  for (int r=0;r<6;r++){
    float t0=T1[r][0], t1=T1[r][1], t2=T1[r][2];
    float u[6];
    u[0] = 0.25f*t0;
    u[1] = (-t0-t1-t2)*(1.f/6.f);
    u[2] = (-t0+t1-t2)*(1.f/6.f);
    u[3] = t0*(1.f/24.f)+t1*(1.f/12.f)+t2*(1.f/6.f);
    u[4] = t0*(1.f/24.f)-t1*(1.f/12.f)+t2*(1.f/6.f);
    u[5] = t2;
    #pragma unroll
    for (int c=0;c<6;c++)
      g_U[((size_t)(r*6+c)*CIN + ci)*CIN + co] = u[c];
  }
}

// ---------------------------------------------------------------------------
// Input transform: V = B^T d B per (tile, ci). Stored [k][ci][t].
// ---------------------------------------------------------------------------
__global__ void k_wino_in(const float* __restrict__ x){
  int t = blockIdx.x*256 + threadIdx.x;
  int ci = blockIdx.y;
  if (t >= NTILES) return;
  int b = t / TPB, rr = t - b*TPB;
  int ty = rr / 38, tx = rr - ty*38;
  int y0 = ty*4 - 1, xg0 = tx*4 - 1;
  const float* xp = x + ((size_t)b*CIN + ci)*HW;
  float d[6][6];
  #pragma unroll
  for (int m=0;m<6;m++){
    int gy = y0 + m;
    bool ry = ((unsigned)gy < HH);
    #pragma unroll
    for (int j=0;j<6;j++){
      int gx = xg0 + j;
      d[m][j] = (ry && (unsigned)gx < WW) ? xp[gy*WW + gx] : 0.f;
    }
  }
  float tmp[6][6];
  #pragma unroll
  for (int j=0;j<6;j++){
    float d0=d[0][j],d1=d[1][j],d2=d[2][j],d3=d[3][j],d4=d[4][j],d5=d[5][j];
    tmp[0][j] = 4.f*d0 - 5.f*d2 + d4;
    tmp[1][j] = -4.f*d1 - 4.f*d2 + d3 + d4;
    tmp[2][j] =  4.f*d1 - 4.f*d2 - d3 + d4;
    tmp[3][j] = -2.f*d1 - d2 + 2.f*d3 + d4;
    tmp[4][j] =  2.f*d1 - d2 - 2.f*d3 + d4;
    tmp[5][j] =  4.f*d1 - 5.f*d3 + d5;
  }
  #pragma unroll
  for (int i=0;i<6;i++){
    float r0=tmp[i][0],r1=tmp[i][1],r2=tmp[i][2],r3=tmp[i][3],r4=tmp[i][4],r5=tmp[i][5];
    float v[6];
    v[0] = 4.f*r0 - 5.f*r2 + r4;
    v[1] = -4.f*r1 - 4.f*r2 + r3 + r4;
    v[2] =  4.f*r1 - 4.f*r2 - r3 + r4;
    v[3] = -2.f*r1 - r2 + 2.f*r3 + r4;
    v[4] =  2.f*r1 - r2 - 2.f*r3 + r4;
    v[5] =  4.f*r1 - 5.f*r3 + r5;
    #pragma unroll
    for (int c=0;c<6;c++)
      g_V[((size_t)(i*6+c)*CIN + ci)*TPAD + t] = v[c];
  }
}

// ---------------------------------------------------------------------------
// GEMM v3 (unchanged from R10/R11 win): 128co x 128t, ci chunks of 16.
// ---------------------------------------------------------------------------
__global__ __launch_bounds__(256,2) void k_gemm(){
  __shared__ __align__(16) ull s_v[2][16][128];   // (v,v) pairs, 32KB
  __shared__ __align__(16) ull s_w[2][16][64];    // (w0,w1) pairs, 16KB
  int tid = threadIdx.x;
  int t0  = blockIdx.x*128;
  int co0 = blockIdx.y*128;
  int kk  = blockIdx.z;
  int og = tid & 15;       // co group: 8 co (4 pairs)
  int tg = tid >> 4;       // t group: 8 t
  const float* Vk = g_V + (size_t)kk*CIN*TPAD;
  const float* Uk = g_U + (size_t)kk*CIN*CIN;

  ull acc[4][8];
  #pragma unroll
  for (int p=0;p<4;p++)
    #pragma unroll
    for (int j=0;j<8;j++) PACK2(acc[p][j], 0.f, 0.f);

  int sci  = tid >> 5;
  int scol = tid & 31;

  float4 rv0 = *(const float4*)&Vk[(size_t)sci*TPAD + t0 + scol*4];
  float4 rv1 = *(const float4*)&Vk[(size_t)(sci+8)*TPAD + t0 + scol*4];
  float4 rw0 = *(const float4*)&Uk[(size_t)sci*CIN + co0 + scol*4];
  float4 rw1 = *(const float4*)&Uk[(size_t)(sci+8)*CIN + co0 + scol*4];
  {
    ull d0,d1,d2,d3;
    PACK2(d0,rv0.x,rv0.x); PACK2(d1,rv0.y,rv0.y);
    PACK2(d2,rv0.z,rv0.z); PACK2(d3,rv0.w,rv0.w);
    ull* dst = &s_v[0][sci][scol*4];
    dst[0]=d0; dst[1]=d1; dst[2]=d2; dst[3]=d3;
    PACK2(d0,rv1.x,rv1.x); PACK2(d1,rv1.y,rv1.y);
    PACK2(d2,rv1.z,rv1.z); PACK2(d3,rv1.w,rv1.w);
    dst = &s_v[0][sci+8][scol*4];
    dst[0]=d0; dst[1]=d1; dst[2]=d2; dst[3]=d3;
    ull w0,w1;
    PACK2(w0,rw0.x,rw0.y); PACK2(w1,rw0.z,rw0.w);
    s_w[0][sci][scol*2]   = w0;
    s_w[0][sci][scol*2+1] = w1;
    PACK2(w0,rw1.x,rw1.y); PACK2(w1,rw1.z,rw1.w);
    s_w[0][sci+8][scol*2]   = w0;
    s_w[0][sci+8][scol*2+1] = w1;
  }
  __syncthreads();

  #pragma unroll 1
  for (int c=0; c<16; c++){
    int buf = c & 1;
    if (c+1 < 16){
      int cin = (c+1)*16;
      rv0 = *(const float4*)&Vk[(size_t)(cin+sci)*TPAD + t0 + scol*4];
      rv1 = *(const float4*)&Vk[(size_t)(cin+sci+8)*TPAD + t0 + scol*4];
      rw0 = *(const float4*)&Uk[(size_t)(cin+sci)*CIN + co0 + scol*4];
      rw1 = *(const float4*)&Uk[(size_t)(cin+sci+8)*CIN + co0 + scol*4];
    }

    #pragma unroll 8
    for (int ci=0; ci<16; ci++){
      ulonglong2 v01 = *(const ulonglong2*)&s_v[buf][ci][tg*8];
      ulonglong2 v23 = *(const ulonglong2*)&s_v[buf][ci][tg*8+2];
      ulonglong2 v45 = *(const ulonglong2*)&s_v[buf][ci][tg*8+4];
      ulonglong2 v67 = *(const ulonglong2*)&s_v[buf][ci][tg*8+6];
      ulonglong2 wa = *(const ulonglong2*)&s_w[buf][ci][og*4];
      ulonglong2 wb = *(const ulonglong2*)&s_w[buf][ci][og*4+2];
      ull v[8] = {v01.x, v01.y, v23.x, v23.y, v45.x, v45.y, v67.x, v67.y};
      #pragma unroll
      for (int j=0;j<8;j++){
        FMA2(acc[0][j], v[j], wa.x, acc[0][j]);
        FMA2(acc[1][j], v[j], wa.y, acc[1][j]);
        FMA2(acc[2][j], v[j], wb.x, acc[2][j]);
        FMA2(acc[3][j], v[j], wb.y, acc[3][j]);
      }
    }

    if (c+1 < 16){
      int nb = buf ^ 1;
      ull d0,d1,d2,d3;
      PACK2(d0,rv0.x,rv0.x); PACK2(d1,rv0.y,rv0.y);
      PACK2(d2,rv0.z,rv0.z); PACK2(d3,rv0.w,rv0.w);
      ull* dst = &s_v[nb][sci][scol*4];
      dst[0]=d0; dst[1]=d1; dst[2]=d2; dst[3]=d3;
      PACK2(d0,rv1.x,rv1.x); PACK2(d1,rv1.y,rv1.y);
      PACK2(d2,rv1.z,rv1.z); PACK2(d3,rv1.w,rv1.w);
      dst = &s_v[nb][sci+8][scol*4];
      dst[0]=d0; dst[1]=d1; dst[2]=d2; dst[3]=d3;
      ull w0,w1;
      PACK2(w0,rw0.x,rw0.y); PACK2(w1,rw0.z,rw0.w);
      s_w[nb][sci][scol*2]   = w0;
      s_w[nb][sci][scol*2+1] = w1;
      PACK2(w0,rw1.x,rw1.y); PACK2(w1,rw1.z,rw1.w);
      s_w[nb][sci+8][scol*2]   = w0;
      s_w[nb][sci+8][scol*2+1] = w1;
    }
    __syncthreads();
  }

  float* Mk = g_M + (size_t)kk*CIN*TPAD;
  #pragma unroll
  for (int p=0;p<4;p++){
    float lo[8], hi[8];
    #pragma unroll
    for (int j=0;j<8;j++) UNPACK2(lo[j], hi[j], acc[p][j]);
    int co = co0 + og*8 + 2*p;
    float* r0 = &Mk[(size_t)co*TPAD + t0 + tg*8];
    float* r1 = &Mk[(size_t)(co+1)*TPAD + t0 + tg*8];
    *(float4*)r0     = make_float4(lo[0],lo[1],lo[2],lo[3]);
    *(float4*)(r0+4) = make_float4(lo[4],lo[5],lo[6],lo[7]);
    *(float4*)r1     = make_float4(hi[0],hi[1],hi[2],hi[3]);
    *(float4*)(r1+4) = make_float4(hi[4],hi[5],hi[6],hi[7]);
  }
}

// ---------------------------------------------------------------------------
// FUSED v3: output transform + bias/relu + 1x1 conv + softmax.
// Block = 32 tiles (512 px), 512 threads = (2 co-halves) x (256 "lanes"),
// each thread owns TWO pixels (pxl, pxl+256) -> weight LDS amortized 2x:
// per ci: 21 weight-pair LDS + 2 data LDS + 42 FFMA2 (ratio 3.2 vs 1.75).
// Transform: 16 chunks of 16 ci, 512 tasks (16ci x 32 tiles) per chunk.
// Combine rules identical to v2 (first-wins argmax, single sum regroup).
// ---------------------------------------------------------------------------
#define NJ0 21   /* half 0: pairs j=0..20  -> co 0..41  */
#define NJ1 20   /* half 1: pairs j=21..40 -> co 42..81 (81 = pad) */

__global__ __launch_bounds__(512,1) void k_fused_out(const float* __restrict__ b1,
                                                     const float* __restrict__ w2,
                                                     const float* __restrict__ b2,
                                                     float* __restrict__ logits){
  __shared__ float s_hid[16][512];   // [ci16][block px], 32KB (reused in epilogue)
  __shared__ ull   s_w2[16][41];     // (w[2j],w[2j+1]) per ci, 5.25KB
  int tid = threadIdx.x;
  int t0 = blockIdx.x*32;
  int co16 = tid >> 5;     // transform role: local co (0..15)
  int tl   = tid & 31;     // transform role: local tile (0..31)
  int t    = t0 + tl;
  int pxl  = tid & 255;    // conv role: pixels pxl and pxl+256
  int half = tid >> 8;     // conv role: co-half
  int j0   = half ? NJ0 : 0;
  int nj   = half ? NJ1 : NJ0;

  ull accA[NJ0], accB[NJ0];
  #pragma unroll
  for (int j=0;j<NJ0;j++){
    if (j < nj){
      int jj = j0 + j;
      float ba = b2[2*jj];
      float bb = (2*jj+1 < 81) ? b2[2*jj+1] : 0.f;
      PACK2(accA[j], ba, bb);
      accB[j] = accA[j];
    } else { PACK2(accA[j], 0.f, 0.f); accB[j] = accA[j]; }
  }

  #pragma unroll 1
  for (int ch=0; ch<16; ch++){
    __syncthreads();
    // stage w2 chunk (16 ci x 41 pairs)
    #pragma unroll 1
    for (int i=tid; i<16*41; i+=512){
      int j = i % 41; int ci = i/41;
      int cia = ch*16 + ci;
      float wa = w2[(2*j)*CIN + cia];
      float wb = (2*j+1 < 81) ? w2[(2*j+1)*CIN + cia] : 0.f;
      ull d; PACK2(d, wa, wb);
      s_w2[ci][j] = d;
    }
    // transform: co = ch*16 + co16, tile t
    {
      int co = ch*16 + co16;
      const float* Mp = g_M + (size_t)co*TPAD + t;
      float bv = b1[co];
      float tr0[6], tr1[6], tr2[6], tr3[6];
      #pragma unroll
      for (int j=0;j<6;j++){
        float m0 = Mp[(size_t)(0*6+j)*CIN*TPAD];
        float m1 = Mp[(size_t)(1*6+j)*CIN*TPAD];
        float m2 = Mp[(size_t)(2*6+j)*CIN*TPAD];
        float m3 = Mp[(size_t)(3*6+j)*CIN*TPAD];
        float m4 = Mp[(size_t)(4*6+j)*CIN*TPAD];
        float m5 = Mp[(size_t)(5*6+j)*CIN*TPAD];
        tr0[j] = m0+m1+m2+m3+m4;
        tr1[j] = m1-m2+2.f*m3-2.f*m4;
        tr2[j] = m1+m2+4.f*m3+4.f*m4;
        tr3[j] = m1-m2+8.f*m3-8.f*m4+m5;
      }
      float* hrow = &s_hid[co16][tl*16];
      #pragma unroll
      for (int r=0;r<4;r++){
        const float* tr = (r==0)?tr0:((r==1)?tr1:((r==2)?tr2:tr3));
        float r0=tr[0],r1=tr[1],r2=tr[2],r3=tr[3],r4=tr[4],r5=tr[5];
        float y0 = r0+r1+r2+r3+r4;
        float y1 = r1-r2+2.f*r3-2.f*r4;
        float y2 = r1+r2+4.f*r3+4.f*r4;
        float y3 = r1-r2+8.f*r3-8.f*r4+r5;
        hrow[r*4+0] = fmaxf(y0+bv, 0.f);
        hrow[r*4+1] = fmaxf(y1+bv, 0.f);
        hrow[r*4+2] = fmaxf(y2+bv, 0.f);
        hrow[r*4+3] = fmaxf(y3+bv, 0.f);
      }
    }
    __syncthreads();
    // conv: thread owns (pxl & pxl+256, co-half). Weights loaded once per ci.
    #pragma unroll 2
    for (int ci=0; ci<16; ci++){
      float vA = s_hid[ci][pxl];
      float vB = s_hid[ci][pxl+256];
      ull vdA, vdB; PACK2(vdA, vA, vA); PACK2(vdB, vB, vB);
      const ull* wp = s_w2[ci] + j0;
      #pragma unroll
      for (int j=0;j<NJ0;j++){
        if (j < nj){
          ull w = wp[j];
          FMA2(accA[j], vdA, w, accA[j]);
          FMA2(accB[j], vdB, w, accB[j]);
        }
      }
    }
  }

  // ---- epilogue: per-(half,px) reduction through smem ----
  __syncthreads();
  float* base = (float*)s_hid;
  float* redM = base;                 // [2][512]
  float* redB = base + 1024;          // [2][512]
  float* redS = base + 2048;          // [2][512]
  int*   redI = (int*)(base + 3072);  // [2][512]

  // process both pixels: q = pxl (A), pxl+256 (B)
  float Ml[2], bestl[2]; int bil[2];
  #pragma unroll
  for (int s2=0;s2<2;s2++){
    int q = pxl + s2*256;
    int tile = t0 + (q >> 4);
    bool valid = (tile < NTILES);
    int b = tile / TPB, rr = tile - b*TPB;
    int ty = rr / 38, tx = rr - ty*38;
    int pos = q & 15;
    int px = (ty*4 + (pos>>2))*WW + tx*4 + (pos&3);
    float* ob = logits + (size_t)b*NC*HW;
    ull* acc = s2 ? accB : accA;

    float M = -1e30f, best = -1e30f; int bi = 0;
    #pragma unroll
    for (int j=0;j<NJ0;j++){
      if (j < nj){
        int jj = j0 + j;
        float a, c; UNPACK2(a, c, acc[j]);
        if (valid) ob[(size_t)(2*jj)*HW + px] = a;
        if (2*jj < 80 && a > best){ best = a; bi = 2*jj; }
        M = fmaxf(M, a);
        if (2*jj+1 < 81){
          if (valid) ob[(size_t)(2*jj+1)*HW + px] = c;
          if (2*jj+1 < 80 && c > best){ best = c; bi = 2*jj+1; }
          M = fmaxf(M, c);
        }
      }
    }
    Ml[s2] = M; bestl[s2] = best; bil[s2] = bi;
    redM[half*512 + q] = M;
    redB[half*512 + q] = best;
    redI[half*512 + q] = bi;
  }
  __syncthreads();
  #pragma unroll
  for (int s2=0;s2<2;s2++){
    int q = pxl + s2*256;
    float Mg = fmaxf(redM[q], redM[512 + q]);
    ull* acc = s2 ? accB : accA;
    float s = 0.f;
    #pragma unroll
    for (int j=0;j<NJ0;j++){
      if (j < nj){
        int jj = j0 + j;
        float a, c; UNPACK2(a, c, acc[j]);
        s += expf(a - Mg);
        if (2*jj+1 < 81) s += expf(c - Mg);
      }
    }
    redS[half*512 + q] = s;
  }
  __syncthreads();
  if (half==0){
    #pragma unroll
    for (int s2=0;s2<2;s2++){
      int q = pxl + s2*256;
      int tile = t0 + (q >> 4);
      if (tile >= NTILES) continue;
      int b = tile / TPB, rr = tile - b*TPB;
      int ty = rr / 38, tx = rr - ty*38;
      int pos = q & 15;
      int px = (ty*4 + (pos>>2))*WW + tx*4 + (pos&3);
      float Mg = fmaxf(redM[q], redM[512 + q]);
      float stot = redS[q] + redS[512 + q];
      float b0 = redB[q], b1v = redB[512 + q];
      int   i0 = redI[q], i1  = redI[512 + q];
      float bestg = b0; int big = i0;
      if (b1v > b0){ bestg = b1v; big = i1; }
      int gi = b*HW + px;
      g_pv[gi]  = expf(bestg - Mg) / stot;
      g_cls[gi] = big;
    }
  }
}

// ---------------------------------------------------------------------------
// score = p + 1 if local max (same-class strict neighbors) — unchanged.
// ---------------------------------------------------------------------------
__global__ void k_score(){
  int i = blockIdx.x*256 + threadIdx.x;
  if (i >= BATCH*HW) return;
  int b = i / HW, px = i - b*HW;
  int y = px / WW, xx = px - y*WW;
  float p = g_pv[i]; int cls = g_cls[i];
  bool flag = (p >= 1e-6f);
  if (flag){
    #pragma unroll
    for (int dy=-1; dy<=1; dy++){
      #pragma unroll
      for (int dx=-1; dx<=1; dx++){
        if (dy==0 && dx==0) continue;
        int ny = y+dy, nx = xx+dx;
        if ((unsigned)ny < HH && (unsigned)nx < WW){
          int j = b*HW + ny*WW + nx;
          if (g_cls[j]==cls && g_pv[j] > p) flag = false;
        }
      }
    }
  }
  float score = p + (flag ? 1.f : 0.f);
  g_keys[i] = (((ull)__float_as_uint(score))<<32)
              | (ull)(0xFFFFFFFFu - (unsigned)px);
}

// ---------------------------------------------------------------------------
// Top-100 v2 (unchanged from R11 win): stripe cache + shfl argmax.
// ---------------------------------------------------------------------------
__global__ void k_topk(){
  __shared__ ull s_val[256];
  __shared__ ull s_wv[8];
  __shared__ int s_wi[8];
  __shared__ int s_twin;
  int b = blockIdx.x, tid = threadIdx.x;
  int lane = tid & 31, wid = tid >> 5;
  ull* kb = g_keys + (size_t)b*HW;

  {
    ull m = 0ull;
    for (int i=tid; i<HW; i+=256){
      ull k = kb[i];
      if (k > m) m = k;
    }
    s_val[tid] = m;
  }
  __syncthreads();

  for (int it=0; it<NKEEP; it++){
    ull v = s_val[tid]; int idx = tid;
    #pragma unroll
    for (int off=16; off; off>>=1){
      ull ov  = __shfl_down_sync(0xFFFFFFFFu, v, off);
      int oi  = __shfl_down_sync(0xFFFFFFFFu, idx, off);
      if (ov > v){ v = ov; idx = oi; }
    }
    if (lane==0){ s_wv[wid] = v; s_wi[wid] = idx; }
    __syncthreads();
    if (tid==0){
      ull bv = s_wv[0]; int bidx = s_wi[0];
      #pragma unroll
      for (int w=1;w<8;w++)
        if (s_wv[w] > bv){ bv = s_wv[w]; bidx = s_wi[w]; }
      int wpx = (int)(0xFFFFFFFFu - (unsigned)(bv & 0xFFFFFFFFull));
      g_topk[b*NKEEP+it] = wpx;
      kb[wpx] = 0ull;
      s_twin = bidx;
    }
    __syncthreads();
    int twin = s_twin;
    if (wid==0){
      ull m = 0ull;
      int i0 = twin + lane*256, i1 = twin + (lane+32)*256;
      if (i0 < HW){ ull k = kb[i0]; if (k > m) m = k; }
      if (i1 < HW){ ull k = kb[i1]; if (k > m) m = k; }
      #pragma unroll
      for (int off=16; off; off>>=1){
        ull ov = __shfl_down_sync(0xFFFFFFFFu, m, off);
        if (ov > m) m = ov;
      }
      if (lane==0) s_val[twin] = m;
    }
    __syncthreads();
  }
}

// ---------------------------------------------------------------------------
// Gather x and pos at top-k indices. out layout: [proposals | pos | logits]
// ---------------------------------------------------------------------------
__global__ void k_gather(const float* __restrict__ x, const float* __restrict__ pos,
                         float* __restrict__ out){
  int i = blockIdx.x*256 + threadIdx.x;
  if (i >= NOUT1) return;
  int k = i % NKEEP; int t = i / NKEEP; int c = t % CIN; int b = t / CIN;
  int px = g_topk[b*NKEEP + k];
  out[i]         = x[((size_t)b*CIN + c)*HW + px];
  out[NOUT1 + i] = pos[(size_t)c*HW + px];
}

// ---------------------------------------------------------------------------
extern "C" void kernel_launch(void* const* d_in, const int* in_sizes, int n_in,
                              void* d_out, int out_size){
  (void)in_sizes; (void)n_in; (void)out_size;
  const float* x   = (const float*)d_in[0];
  const float* pos = (const float*)d_in[1];
  const float* w1  = (const float*)d_in[2];
  const float* b1  = (const float*)d_in[3];
  const float* w2  = (const float*)d_in[4];
  const float* b2  = (const float*)d_in[5];
  float* out = (float*)d_out;
  float* logits = out + 2*NOUT1;

  k_wino_w   <<<(CIN*CIN+255)/256, 256>>>(w1);
  k_wino_in  <<<dim3((NTILES+255)/256, CIN), 256>>>(x);
  k_gemm     <<<dim3(TPAD/128, CIN/128, 36), 256>>>();
  k_fused_out<<<TPAD/32, 512>>>(b1, w2, b2, logits);
  k_score    <<<(BATCH*HW+255)/256, 256>>>();
  k_topk     <<<BATCH, 256>>>();
  k_gather   <<<(NOUT1+255)/256, 256>>>(x, pos, out);
}